// round 5
// baseline (speedup 1.0000x reference)
#include <cuda_runtime.h>
#include <cuda_bf16.h>
#include <math.h>
#include <cstdint>

#define N_NODES 100000
#define N_EDGES 1600000
#define T_STEPS 8

// ---------------- device scratch (no allocations allowed) ----------------
__device__ float g_hbuf[2 * N_NODES * 64];                 // fp32 h (written t>=6 only)
__device__ __nv_bfloat16 g_h16[2 * N_NODES * 64];          // bf16 h double buffer
__device__ float g_c[N_NODES * 64];
__device__ float g_agg[N_NODES * 64];                      // fp32 agg (written t==7 only)
__device__ __nv_bfloat16 g_agg16[N_NODES * 64];
__device__ float g_gnn[N_NODES * 64];
__device__ float g_xT[T_STEPS * 20 * N_NODES];             // [t][j][n]
__device__ __align__(16) __nv_bfloat16 g_Wb[256 * 160];    // fused, row-permuted gate weights
__device__ float g_bias[256];
__device__ float g_stats[256];
__device__ float g_scale[128];
__device__ float g_shift[128];
__device__ int   g_deg[N_NODES];
__device__ int   g_offs[N_NODES + 1];
__device__ int   g_cursor[N_NODES];
__device__ int   g_ssrc[N_EDGES];
__device__ int   g_bsums[128];
__device__ int   g_boffs[128];
__device__ float g_h1[N_NODES * 64];
__device__ float g_hidden[N_NODES * 128];
__device__ int   g_is64;

// ---------------- mma/ldmatrix helpers ----------------
__device__ __forceinline__ uint32_t smem_u32(const void* p) {
    uint32_t a;
    asm("{ .reg .u64 tmp; cvta.to.shared.u64 tmp, %1; cvt.u32.u64 %0, tmp; }"
        : "=r"(a) : "l"(p));
    return a;
}
__device__ __forceinline__ void ldsm_x4(uint32_t* r, uint32_t addr) {
    asm volatile("ldmatrix.sync.aligned.m8n8.x4.shared.b16 {%0,%1,%2,%3}, [%4];"
                 : "=r"(r[0]), "=r"(r[1]), "=r"(r[2]), "=r"(r[3]) : "r"(addr));
}
__device__ __forceinline__ void mma_bf16(float* d, const uint32_t* a,
                                         uint32_t b0, uint32_t b1) {
    asm volatile(
        "mma.sync.aligned.m16n8k16.row.col.f32.bf16.bf16.f32 "
        "{%0,%1,%2,%3}, {%4,%5,%6,%7}, {%8,%9}, {%0,%1,%2,%3};"
        : "+f"(d[0]), "+f"(d[1]), "+f"(d[2]), "+f"(d[3])
        : "r"(a[0]), "r"(a[1]), "r"(a[2]), "r"(a[3]), "r"(b0), "r"(b1));
}

// ---------------- small utility kernels ----------------
__global__ void zero_state() {
    int stride = gridDim.x * blockDim.x;
    int i0 = blockIdx.x * blockDim.x + threadIdx.x;
    for (int k = i0; k < N_NODES * 64; k += stride) g_c[k] = 0.f;
    if (i0 < 256) g_stats[i0] = 0.f;
}

__global__ void detect_kernel(const unsigned int* __restrict__ w) {
    __shared__ unsigned int acc;
    if (threadIdx.x == 0) acc = 0u;
    __syncthreads();
    unsigned int v = 0u;
    for (int i = threadIdx.x; i < 2048; i += blockDim.x) v |= w[2 * i + 1];
    atomicOr(&acc, v);
    __syncthreads();
    if (threadIdx.x == 0) g_is64 = (acc == 0u) ? 1 : 0;
}

__device__ __forceinline__ int edge_val(const void* ei, long long idx) {
    if (g_is64) return (int)((const long long*)ei)[idx];
    return ((const int*)ei)[idx];
}

__global__ void hist_kernel(const void* __restrict__ ei) {
    int stride = gridDim.x * blockDim.x;
    int i0 = blockIdx.x * blockDim.x + threadIdx.x;
    for (int k = i0; k < N_NODES; k += stride) g_deg[k] = 0;
}

__global__ void hist2_kernel(const void* __restrict__ ei) {
    int stride = gridDim.x * blockDim.x;
    for (int e = blockIdx.x * blockDim.x + threadIdx.x; e < N_EDGES; e += stride) {
        int d = edge_val(ei, (long long)N_EDGES + e);
        atomicAdd(&g_deg[d], 1);
    }
}

// phase 1: per-block (1024) exclusive scan, block sums out
__global__ void scan1_kernel() {
    __shared__ int warpsums[32];
    int tid = threadIdx.x, lane = tid & 31, wid = tid >> 5;
    int i = blockIdx.x * 1024 + tid;
    int v = (i < N_NODES) ? g_deg[i] : 0;
    int x = v;
    #pragma unroll
    for (int off = 1; off < 32; off <<= 1) {
        int y = __shfl_up_sync(0xFFFFFFFFu, x, off);
        if (lane >= off) x += y;
    }
    if (lane == 31) warpsums[wid] = x;
    __syncthreads();
    if (wid == 0) {
        int wv = warpsums[lane];
        #pragma unroll
        for (int off = 1; off < 32; off <<= 1) {
            int y = __shfl_up_sync(0xFFFFFFFFu, wv, off);
            if (lane >= off) wv += y;
        }
        warpsums[lane] = wv;
    }
    __syncthreads();
    int woff = (wid == 0) ? 0 : warpsums[wid - 1];
    if (i < N_NODES) g_offs[i] = x - v + woff;
    if (tid == 1023) g_bsums[blockIdx.x] = warpsums[31];
}

// phase 2: scan of block sums (nblk <= 128), one block of 128 threads
__global__ void scan2_kernel(int nblk) {
    __shared__ int warpsums[4];
    int tid = threadIdx.x, lane = tid & 31, wid = tid >> 5;
    int v = (tid < nblk) ? g_bsums[tid] : 0;
    int x = v;
    #pragma unroll
    for (int off = 1; off < 32; off <<= 1) {
        int y = __shfl_up_sync(0xFFFFFFFFu, x, off);
        if (lane >= off) x += y;
    }
    if (lane == 31) warpsums[wid] = x;
    __syncthreads();
    if (wid == 0 && lane < 4) {
        int wv = warpsums[lane];
        #pragma unroll
        for (int off = 1; off < 4; off <<= 1) {
            int y = __shfl_up_sync(0xFu, wv, off);
            if (lane >= off) wv += y;
        }
        warpsums[lane] = wv;
    }
    __syncthreads();
    int woff = (wid == 0) ? 0 : warpsums[wid - 1];
    int excl = x - v + woff;
    if (tid < nblk) g_boffs[tid] = excl;
    if (tid == nblk - 1) g_offs[N_NODES] = excl + v;
}

// phase 3: add block offsets, init cursors
__global__ void scan3_kernel() {
    int i = blockIdx.x * blockDim.x + threadIdx.x;
    if (i >= N_NODES) return;
    int o = g_offs[i] + g_boffs[i >> 10];
    g_offs[i] = o;
    g_cursor[i] = o;
}

__global__ void scatter_kernel(const void* __restrict__ ei) {
    int stride = gridDim.x * blockDim.x;
    for (int e = blockIdx.x * blockDim.x + threadIdx.x; e < N_EDGES; e += stride) {
        int s = edge_val(ei, e);
        int d = edge_val(ei, (long long)N_EDGES + e);
        int p = atomicAdd(&g_cursor[d], 1);
        g_ssrc[p] = s;
    }
}

// x (N, 30, 8) -> g_xT[t][j][n]; only temporal slice read.
__global__ void __launch_bounds__(256) transpose_x(const float* __restrict__ x) {
    __shared__ float sm[32 * 161];
    int n0 = blockIdx.x * 32;
    #pragma unroll
    for (int w = 0; w < 20; w++) {
        int i = threadIdx.x + w * 256;       // 0..5119
        int nl = i / 160, off = i - nl * 160;
        sm[nl * 161 + off] = x[(size_t)(n0 + nl) * 240 + 80 + off];
    }
    __syncthreads();
    #pragma unroll
    for (int w = 0; w < 20; w++) {
        int idx = threadIdx.x + w * 256;
        int nl = idx & 31;
        int p = idx >> 5;                    // 0..159
        int t = p / 20, j = p - t * 20;
        g_xT[((size_t)t * 20 + j) * N_NODES + n0 + nl] = sm[nl * 161 + j * 8 + t];
    }
}

// Fold GNN projection into gate weights, permute rows to (i,f,g,o) quads, emit bf16.
__global__ void prep_weights(const float* __restrict__ W_ih, const float* __restrict__ W_hh,
                             const float* __restrict__ b_ih, const float* __restrict__ b_hh,
                             const float* __restrict__ W_rel, const float* __restrict__ b_rel,
                             const float* __restrict__ W_root) {
    int rp = blockIdx.x;
    int u = rp >> 2, q = rp & 3;
    int r = q * 64 + u;
    __shared__ float wg[64];
    int tid = threadIdx.x;  // 64 threads
    wg[tid] = W_ih[r * 84 + 20 + tid];
    __syncthreads();
    int c = tid;
    float m1 = 0.f, m2 = 0.f;
    #pragma unroll 8
    for (int j = 0; j < 64; j++) {
        float w = wg[j];
        m1 += w * W_rel[j * 64 + c];
        m2 += w * W_root[j * 64 + c];
    }
    m2 += W_hh[r * 64 + c];
    g_Wb[rp * 160 + 20 + c] = __float2bfloat16_rn(m1);
    g_Wb[rp * 160 + 84 + c] = __float2bfloat16_rn(m2);
    if (c < 20) g_Wb[rp * 160 + c] = __float2bfloat16_rn(W_ih[r * 84 + c]);
    if (c < 12) g_Wb[rp * 160 + 148 + c] = __float2bfloat16_rn(0.f);
    if (c == 0) {
        float s = b_ih[r] + b_hh[r];
        for (int j = 0; j < 64; j++) s += wg[j] * b_rel[j];
        g_bias[rp] = s;
    }
}

// ---------------- aggregation: warp per dst node, bf16 gather ----------------
__global__ void agg_kernel(const __nv_bfloat16* __restrict__ h16, int wf32) {
    int gw = (blockIdx.x * blockDim.x + threadIdx.x) >> 5;
    int lane = threadIdx.x & 31;
    if (gw >= N_NODES) return;
    int beg = g_offs[gw], end = g_offs[gw + 1];
    float2 acc = make_float2(0.f, 0.f);
    int e = beg;
    for (; e + 4 <= end; e += 4) {
        int s0 = g_ssrc[e], s1 = g_ssrc[e + 1], s2 = g_ssrc[e + 2], s3 = g_ssrc[e + 3];
        float2 v0 = __bfloat1622float2(
            *reinterpret_cast<const __nv_bfloat162*>(h16 + (size_t)s0 * 64 + lane * 2));
        float2 v1 = __bfloat1622float2(
            *reinterpret_cast<const __nv_bfloat162*>(h16 + (size_t)s1 * 64 + lane * 2));
        float2 v2 = __bfloat1622float2(
            *reinterpret_cast<const __nv_bfloat162*>(h16 + (size_t)s2 * 64 + lane * 2));
        float2 v3 = __bfloat1622float2(
            *reinterpret_cast<const __nv_bfloat162*>(h16 + (size_t)s3 * 64 + lane * 2));
        acc.x += (v0.x + v1.x) + (v2.x + v3.x);
        acc.y += (v0.y + v1.y) + (v2.y + v3.y);
    }
    for (; e < end; e++) {
        int s = g_ssrc[e];
        float2 v = __bfloat1622float2(
            *reinterpret_cast<const __nv_bfloat162*>(h16 + (size_t)s * 64 + lane * 2));
        acc.x += v.x;
        acc.y += v.y;
    }
    *reinterpret_cast<__nv_bfloat162*>(g_agg16 + (size_t)gw * 64 + lane * 2) =
        __float22bfloat162_rn(acc);
    if (wf32)
        *reinterpret_cast<float2*>(g_agg + (size_t)gw * 64 + lane * 2) = acc;
}

// ---------------- bf16 mma.sync gate GEMM + fused LSTM epilogue ----------------
// One CTA: 128 nodes x all 256 gate cols. 512 threads = 16 warps (4m x 4n),
// warp tile 32x64. A[128][168]bf16 @0, B[256][168]bf16 @43008.
#define GATE_SMEM 129024

__global__ void __launch_bounds__(512, 1)
gate_kernel(const float* __restrict__ xTt, const __nv_bfloat16* __restrict__ h16_in,
            float* __restrict__ h_out, __nv_bfloat16* __restrict__ h16_out,
            int t0, int wf32) {
    extern __shared__ char smem[];
    const int tid = threadIdx.x;
    const int wid = tid >> 5;
    const int lane = tid & 31;
    const int n0 = blockIdx.x * 128;

    // ---- stage B: 256 rows x 160 bf16, 16B chunks ----
    {
        const uint4* Wb4 = reinterpret_cast<const uint4*>(g_Wb);
        #pragma unroll
        for (int it = 0; it < 10; it++) {
            int idx = tid + it * 512;          // 0..5119 = r*20 + c
            int r = idx / 20;
            int c = idx - r * 20;
            *reinterpret_cast<uint4*>(smem + 43008 + r * 336 + c * 16) = Wb4[idx];
        }
    }
    // ---- stage A: x_t (k 0..19) ----
    #pragma unroll
    for (int it = 0; it < 5; it++) {
        int idx = tid + it * 512;              // j*128 + nl
        int j = idx >> 7;
        int nl = idx & 127;
        int n = n0 + nl;
        float v = (n < N_NODES) ? xTt[(size_t)j * N_NODES + n] : 0.f;
        *reinterpret_cast<__nv_bfloat16*>(smem + nl * 336 + j * 2) = __float2bfloat16_rn(v);
    }
    // ---- A: agg bf16 (k 20..83) + h bf16 (k 84..147), 8B chunks ----
    #pragma unroll
    for (int it = 0; it < 4; it++) {
        int idx = tid + it * 512;              // 0..2047 = nl*16 + cp
        int nl = idx >> 4;
        int cp = idx & 15;
        int n = n0 + nl;
        uint2 va = make_uint2(0u, 0u), vh = make_uint2(0u, 0u);
        if (!t0 && n < N_NODES) {
            va = *reinterpret_cast<const uint2*>(g_agg16 + (size_t)n * 64 + cp * 4);
            vh = *reinterpret_cast<const uint2*>(h16_in + (size_t)n * 64 + cp * 4);
        }
        *reinterpret_cast<uint2*>(smem + nl * 336 + 40 + cp * 8) = va;
        *reinterpret_cast<uint2*>(smem + nl * 336 + 168 + cp * 8) = vh;
    }
    // ---- A: zero pad (k 148..167) ----
    for (int idx = tid; idx < 640; idx += 512) {
        int nl = idx / 5;
        int p = idx - nl * 5;
        *reinterpret_cast<uint2*>(smem + nl * 336 + 296 + p * 8) = make_uint2(0u, 0u);
    }
    __syncthreads();

    // ---- mma mainloop ----
    const int mw = wid >> 2;                 // 0..3
    const int nw = wid & 3;                  // 0..3
    const int mr = mw * 32;
    const int nc = nw * 64;                  // absolute gate-col base
    const uint32_t sbase = smem_u32(smem);
    uint32_t aAddr = sbase + (mr + (lane & 15)) * 336 + ((lane >> 4) << 4);
    uint32_t bAddr = sbase + 43008u + (nc + (lane & 15)) * 336 + ((lane >> 4) << 4);

    float acc[2][8][4];
    #pragma unroll
    for (int mi = 0; mi < 2; mi++)
        #pragma unroll
        for (int nj = 0; nj < 8; nj++)
            #pragma unroll
            for (int e = 0; e < 4; e++) acc[mi][nj][e] = 0.f;

    #pragma unroll
    for (int ks = 0; ks < 10; ks++) {
        uint32_t a[2][4];
        ldsm_x4(a[0], aAddr + ks * 32);
        ldsm_x4(a[1], aAddr + 16 * 336 + ks * 32);
        uint32_t b[4][4];
        #pragma unroll
        for (int nj = 0; nj < 4; nj++)
            ldsm_x4(b[nj], bAddr + nj * 16 * 336 + ks * 32);
        #pragma unroll
        for (int mi = 0; mi < 2; mi++)
            #pragma unroll
            for (int nj2 = 0; nj2 < 8; nj2++) {
                int nj = nj2 >> 1, hi = nj2 & 1;
                mma_bf16(acc[mi][nj2], a[mi], b[nj][hi], b[nj][hi + 2]);
            }
    }
    __syncthreads();

    // ---- repurpose smem: Cs[128][65], Hs[128][65], bias[256] ----
    float* Cs = reinterpret_cast<float*>(smem);
    float* Hs = Cs + 128 * 65;
    float* sbias = Hs + 128 * 65;
    #pragma unroll
    for (int it = 0; it < 16; it++) {
        int idx = tid + it * 512;
        int rr = idx >> 6;
        int u = idx & 63;
        int n = n0 + rr;
        Cs[rr * 65 + u] = (n < N_NODES) ? g_c[(size_t)n * 64 + u] : 0.f;
    }
    if (tid < 256) sbias[tid] = g_bias[tid];
    __syncthreads();

    // ---- fused LSTM epilogue ----
    #pragma unroll
    for (int mi = 0; mi < 2; mi++) {
        int row = mr + mi * 16 + (lane >> 2) + ((lane & 1) << 3);
        #pragma unroll
        for (int nj2 = 0; nj2 < 8; nj2++) {
            float d0 = acc[mi][nj2][0], d1 = acc[mi][nj2][1];
            float d2 = acc[mi][nj2][2], d3 = acc[mi][nj2][3];
            float xd0 = __shfl_xor_sync(0xFFFFFFFFu, d0, 1);
            float xd1 = __shfl_xor_sync(0xFFFFFFFFu, d1, 1);
            float xd2 = __shfl_xor_sync(0xFFFFFFFFu, d2, 1);
            float xd3 = __shfl_xor_sync(0xFFFFFFFFu, d3, 1);
            float ig, fg, gg, og;
            if (lane & 1) { ig = xd2; fg = xd3; gg = d2; og = d3; }
            else          { ig = d0;  fg = d1;  gg = xd0; og = xd1; }
            int qb = nc + nj2 * 8 + ((lane & 2) << 1);
            ig += sbias[qb];
            fg += sbias[qb + 1];
            gg += sbias[qb + 2];
            og += sbias[qb + 3];
            float si = 1.f / (1.f + __expf(-ig));
            float sf = 1.f / (1.f + __expf(-fg));
            float so = 1.f / (1.f + __expf(-og));
            float tg = 2.f / (1.f + __expf(-2.f * gg)) - 1.f;
            int u = qb >> 2;
            float cold = Cs[row * 65 + u];
            float cn = sf * cold + si * tg;
            Cs[row * 65 + u] = cn;
            float tcn = 2.f / (1.f + __expf(-2.f * cn)) - 1.f;
            Hs[row * 65 + u] = so * tcn;
        }
    }
    __syncthreads();

    // ---- coalesced writeback ----
    #pragma unroll
    for (int it = 0; it < 16; it++) {
        int idx = tid + it * 512;
        int rr = idx >> 6;
        int u = idx & 63;
        int n = n0 + rr;
        if (n < N_NODES) {
            size_t o = (size_t)n * 64 + u;
            float cn = Cs[rr * 65 + u];
            float hv = Hs[rr * 65 + u];
            g_c[o] = cn;
            h16_out[o] = __float2bfloat16_rn(hv);
            if (wf32) h_out[o] = hv;
        }
    }
}

// ---------------- generic small GEMM: out = act(A @ W^T + bias) ----------------
template <int AMODE, int EPI>
__global__ void __launch_bounds__(256)
gemm64_kernel(const float* __restrict__ A0, const float* __restrict__ A1,
              const float* __restrict__ Wp0, const float* __restrict__ Wp1,
              const float* __restrict__ bias, float* __restrict__ out,
              int K, int OUT) {
    __shared__ __align__(16) float As[16][68];
    __shared__ __align__(16) float Bs[16][68];
    int tid = threadIdx.x;
    int row0 = blockIdx.x * 64;
    int col0 = blockIdx.y * 64;
    int tr = (tid >> 4) * 4;
    int tc = (tid & 15) * 4;
    float acc[4][4];
    #pragma unroll
    for (int i = 0; i < 4; i++)
        #pragma unroll
        for (int j = 0; j < 4; j++) acc[i][j] = 0.f;

    for (int kt = 0; kt < K; kt += 16) {
        #pragma unroll
        for (int it = 0; it < 4; it++) {
            int idx = tid + it * 256;
            int m = idx >> 4, kk = idx & 15;
            int n = row0 + m, gk = kt + kk;
            float v = 0.f;
            if (n < N_NODES) {
                if (AMODE == 0) {
                    v = A0[(size_t)n * K + gk];
                } else {
                    v = (gk < 64) ? A0[(size_t)n * 64 + gk] : A1[(size_t)n * 64 + gk - 64];
                    if (AMODE == 2) v = v * g_scale[gk] + g_shift[gk];
                }
            }
            As[kk][m] = v;
        }
        #pragma unroll
        for (int it = 0; it < 4; it++) {
            int idx = tid + it * 256;
            int cc = idx >> 4, kk = idx & 15;
            int oc = col0 + cc, gk = kt + kk;
            float w;
            if (Wp1) w = (gk < 64) ? Wp0[oc * 64 + gk] : Wp1[oc * 64 + gk - 64];
            else     w = Wp0[oc * K + gk];
            Bs[kk][cc] = w;
        }
        __syncthreads();
        #pragma unroll
        for (int kk = 0; kk < 16; kk++) {
            float4 a = *reinterpret_cast<const float4*>(&As[kk][tr]);
            float4 b = *reinterpret_cast<const float4*>(&Bs[kk][tc]);
            float av[4] = {a.x, a.y, a.z, a.w};
            float bv[4] = {b.x, b.y, b.z, b.w};
            #pragma unroll
            for (int i = 0; i < 4; i++)
                #pragma unroll
                for (int j = 0; j < 4; j++) acc[i][j] += av[i] * bv[j];
        }
        __syncthreads();
    }
    #pragma unroll
    for (int i = 0; i < 4; i++) {
        int n = row0 + tr + i;
        if (n >= N_NODES) continue;
        #pragma unroll
        for (int j = 0; j < 4; j++) {
            int oc = col0 + tc + j;
            float v = acc[i][j] + bias[oc];
            if (EPI == 1) v = fmaxf(v, 0.f);
            out[(size_t)n * OUT + oc] = v;
        }
    }
}

// ---------------- per-feature stats over nodes ----------------
__global__ void stats_kernel(const float* __restrict__ h, const float* __restrict__ gnn) {
    int c = threadIdx.x & 127;
    int grp = threadIdx.x >> 7;
    int r0 = blockIdx.x * 256;
    int rend = min(r0 + 256, N_NODES);
    float s = 0.f, q = 0.f;
    for (int r = r0 + grp; r < rend; r += 2) {
        float v = (c < 64) ? h[(size_t)r * 64 + c] : gnn[(size_t)r * 64 + c - 64];
        s += v;
        q += v * v;
    }
    atomicAdd(&g_stats[c], s);
    atomicAdd(&g_stats[128 + c], q);
}

__global__ void finalize_stats(const float* __restrict__ gamma, const float* __restrict__ beta) {
    int c = threadIdx.x;
    float mean = g_stats[c] / (float)N_NODES;
    float var = g_stats[128 + c] / (float)N_NODES - mean * mean;
    float rstd = rsqrtf(var + 1e-5f);
    float sc = rstd * gamma[c];
    g_scale[c] = sc;
    g_shift[c] = beta[c] - mean * sc;
}

// ---------------- final projection ----------------
__global__ void out_kernel(const float* __restrict__ hidden, const float* __restrict__ Wout,
                           const float* __restrict__ bout, float* __restrict__ out) {
    int gw = (blockIdx.x * blockDim.x + threadIdx.x) >> 5;
    int lane = threadIdx.x & 31;
    if (gw >= N_NODES) return;
    const float* hr = hidden + (size_t)gw * 128;
    float s = hr[lane] * Wout[lane] + hr[lane + 32] * Wout[lane + 32] +
              hr[lane + 64] * Wout[lane + 64] + hr[lane + 96] * Wout[lane + 96];
    #pragma unroll
    for (int off = 16; off; off >>= 1) s += __shfl_down_sync(0xFFFFFFFFu, s, off);
    if (lane == 0) out[gw] = 1.f / (1.f + __expf(-(s + bout[0])));
}

// ---------------- launch ----------------
extern "C" void kernel_launch(void* const* d_in, const int* in_sizes, int n_in,
                              void* d_out, int out_size) {
    const float* x      = (const float*)d_in[0];
    const void*  ei     = d_in[1];
    const float* W_ih   = (const float*)d_in[4];
    const float* W_hh   = (const float*)d_in[5];
    const float* b_ih   = (const float*)d_in[6];
    const float* b_hh   = (const float*)d_in[7];
    const float* W_rel  = (const float*)d_in[8];
    const float* b_rel  = (const float*)d_in[9];
    const float* W_root = (const float*)d_in[10];
    const float* gamma  = (const float*)d_in[11];
    const float* beta   = (const float*)d_in[12];
    const float* W1     = (const float*)d_in[13];
    const float* b1     = (const float*)d_in[14];
    const float* W2     = (const float*)d_in[15];
    const float* b2     = (const float*)d_in[16];
    const float* W_out  = (const float*)d_in[17];
    const float* b_out  = (const float*)d_in[18];

    float *hbuf, *agg, *gnn, *h1, *hidden, *xT;
    __nv_bfloat16* h16;
    cudaGetSymbolAddress((void**)&hbuf, g_hbuf);
    cudaGetSymbolAddress((void**)&h16, g_h16);
    cudaGetSymbolAddress((void**)&agg, g_agg);
    cudaGetSymbolAddress((void**)&gnn, g_gnn);
    cudaGetSymbolAddress((void**)&h1, g_h1);
    cudaGetSymbolAddress((void**)&hidden, g_hidden);
    cudaGetSymbolAddress((void**)&xT, g_xT);

    cudaFuncSetAttribute(gate_kernel, cudaFuncAttributeMaxDynamicSharedMemorySize,
                         GATE_SMEM);

    const int scan_blocks = (N_NODES + 1023) / 1024;   // 98

    zero_state<<<512, 256>>>();
    detect_kernel<<<1, 256>>>((const unsigned int*)ei);
    prep_weights<<<256, 64>>>(W_ih, W_hh, b_ih, b_hh, W_rel, b_rel, W_root);
    transpose_x<<<N_NODES / 32, 256>>>(x);
    hist_kernel<<<256, 256>>>(ei);
    hist2_kernel<<<512, 256>>>(ei);
    scan1_kernel<<<scan_blocks, 1024>>>();
    scan2_kernel<<<1, 128>>>(scan_blocks);
    scan3_kernel<<<(N_NODES + 255) / 256, 256>>>();
    scatter_kernel<<<512, 256>>>(ei);

    int n_tiles = (N_NODES + 127) / 128;
    for (int t = 0; t < T_STEPS; t++) {
        const __nv_bfloat16* h16_in = h16 + (size_t)(t & 1) * N_NODES * 64;
        __nv_bfloat16* h16_out = h16 + (size_t)((t + 1) & 1) * N_NODES * 64;
        const float* hf_in = hbuf + (size_t)(t & 1) * N_NODES * 64;
        float* hf_out = hbuf + (size_t)((t + 1) & 1) * N_NODES * 64;
        if (t > 0) agg_kernel<<<(N_NODES * 32 + 255) / 256, 256>>>(h16_in, t == T_STEPS - 1);
        if (t == T_STEPS - 1) {
            // gnn_out = agg @ W_rel^T + h @ W_root^T + b_rel (fp32 inputs)
            gemm64_kernel<1, 0><<<dim3((N_NODES + 63) / 64, 1), 256>>>(
                agg, hf_in, W_rel, W_root, b_rel, gnn, 128, 64);
        }
        gate_kernel<<<n_tiles, 512, GATE_SMEM>>>(
            xT + (size_t)t * 20 * N_NODES, h16_in, hf_out, h16_out,
            t == 0 ? 1 : 0, t >= T_STEPS - 2 ? 1 : 0);
    }
    const float* hfin = hbuf;  // h after 8 steps lives in buffer 0

    stats_kernel<<<(N_NODES + 255) / 256, 256>>>(hfin, gnn);
    finalize_stats<<<1, 128>>>(gamma, beta);
    gemm64_kernel<2, 1><<<dim3((N_NODES + 63) / 64, 1), 256>>>(
        hfin, gnn, W1, nullptr, b1, h1, 128, 64);
    gemm64_kernel<0, 1><<<dim3((N_NODES + 63) / 64, 2), 256>>>(
        h1, nullptr, W2, nullptr, b2, hidden, 64, 128);
    out_kernel<<<(N_NODES * 32 + 255) / 256, 256>>>(hidden, W_out, b_out, (float*)d_out);
}

// round 6
// speedup vs baseline: 1.0136x; 1.0136x over previous
#include <cuda_runtime.h>
#include <cuda_bf16.h>
#include <math.h>
#include <cstdint>

#define N_NODES 100000
#define N_EDGES 1600000
#define T_STEPS 8

// ---------------- device scratch (no allocations allowed) ----------------
__device__ float g_hbuf[2 * N_NODES * 64];                 // fp32 h (written t>=6 only)
__device__ __nv_bfloat16 g_h16[2 * N_NODES * 64];          // bf16 h double buffer
__device__ float g_c[N_NODES * 64];
__device__ float g_agg[N_NODES * 64];                      // fp32 agg (written t==7 only)
__device__ __nv_bfloat16 g_agg16[N_NODES * 64];
__device__ float g_gnn[N_NODES * 64];
__device__ float g_xT[T_STEPS * 20 * N_NODES];             // [t][j][n]
__device__ __align__(16) __nv_bfloat16 g_Wb[256 * 160];    // fused, row-permuted gate weights
__device__ float g_bias[256];
__device__ float g_stats[256];
__device__ float g_scale[128];
__device__ float g_shift[128];
__device__ int   g_deg[N_NODES];
__device__ int   g_offs[N_NODES + 1];
__device__ int   g_cursor[N_NODES];
__device__ int   g_ssrc[N_EDGES];
__device__ int   g_bsums[128];
__device__ int   g_boffs[128];
__device__ float g_h1[N_NODES * 64];
__device__ float g_hidden[N_NODES * 128];
__device__ int   g_is64;

// ---------------- mma/ldmatrix helpers ----------------
__device__ __forceinline__ uint32_t smem_u32(const void* p) {
    uint32_t a;
    asm("{ .reg .u64 tmp; cvta.to.shared.u64 tmp, %1; cvt.u32.u64 %0, tmp; }"
        : "=r"(a) : "l"(p));
    return a;
}
__device__ __forceinline__ void ldsm_x4(uint32_t* r, uint32_t addr) {
    asm volatile("ldmatrix.sync.aligned.m8n8.x4.shared.b16 {%0,%1,%2,%3}, [%4];"
                 : "=r"(r[0]), "=r"(r[1]), "=r"(r[2]), "=r"(r[3]) : "r"(addr));
}
__device__ __forceinline__ void mma_bf16(float* d, const uint32_t* a,
                                         uint32_t b0, uint32_t b1) {
    asm volatile(
        "mma.sync.aligned.m16n8k16.row.col.f32.bf16.bf16.f32 "
        "{%0,%1,%2,%3}, {%4,%5,%6,%7}, {%8,%9}, {%0,%1,%2,%3};"
        : "+f"(d[0]), "+f"(d[1]), "+f"(d[2]), "+f"(d[3])
        : "r"(a[0]), "r"(a[1]), "r"(a[2]), "r"(a[3]), "r"(b0), "r"(b1));
}

// ---------------- small utility kernels ----------------
__global__ void zero_state() {
    int stride = gridDim.x * blockDim.x;
    int i0 = blockIdx.x * blockDim.x + threadIdx.x;
    for (int k = i0; k < N_NODES * 64; k += stride) g_c[k] = 0.f;
    if (i0 < 256) g_stats[i0] = 0.f;
}

__global__ void detect_kernel(const unsigned int* __restrict__ w) {
    __shared__ unsigned int acc;
    if (threadIdx.x == 0) acc = 0u;
    __syncthreads();
    unsigned int v = 0u;
    for (int i = threadIdx.x; i < 2048; i += blockDim.x) v |= w[2 * i + 1];
    atomicOr(&acc, v);
    __syncthreads();
    if (threadIdx.x == 0) g_is64 = (acc == 0u) ? 1 : 0;
}

__device__ __forceinline__ int edge_val(const void* ei, long long idx) {
    if (g_is64) return (int)((const long long*)ei)[idx];
    return ((const int*)ei)[idx];
}

__global__ void hist_zero() {
    int stride = gridDim.x * blockDim.x;
    int i0 = blockIdx.x * blockDim.x + threadIdx.x;
    for (int k = i0; k < N_NODES; k += stride) g_deg[k] = 0;
}

__global__ void hist2_kernel(const void* __restrict__ ei) {
    int stride = gridDim.x * blockDim.x;
    for (int e = blockIdx.x * blockDim.x + threadIdx.x; e < N_EDGES; e += stride) {
        int d = edge_val(ei, (long long)N_EDGES + e);
        atomicAdd(&g_deg[d], 1);
    }
}

// phase 1: per-block (1024) exclusive scan, block sums out
__global__ void scan1_kernel() {
    __shared__ int warpsums[32];
    int tid = threadIdx.x, lane = tid & 31, wid = tid >> 5;
    int i = blockIdx.x * 1024 + tid;
    int v = (i < N_NODES) ? g_deg[i] : 0;
    int x = v;
    #pragma unroll
    for (int off = 1; off < 32; off <<= 1) {
        int y = __shfl_up_sync(0xFFFFFFFFu, x, off);
        if (lane >= off) x += y;
    }
    if (lane == 31) warpsums[wid] = x;
    __syncthreads();
    if (wid == 0) {
        int wv = warpsums[lane];
        #pragma unroll
        for (int off = 1; off < 32; off <<= 1) {
            int y = __shfl_up_sync(0xFFFFFFFFu, wv, off);
            if (lane >= off) wv += y;
        }
        warpsums[lane] = wv;
    }
    __syncthreads();
    int woff = (wid == 0) ? 0 : warpsums[wid - 1];
    if (i < N_NODES) g_offs[i] = x - v + woff;
    if (tid == 1023) g_bsums[blockIdx.x] = warpsums[31];
}

// phase 2: scan of block sums (nblk <= 128), one block of 128 threads
__global__ void scan2_kernel(int nblk) {
    __shared__ int warpsums[4];
    int tid = threadIdx.x, lane = tid & 31, wid = tid >> 5;
    int v = (tid < nblk) ? g_bsums[tid] : 0;
    int x = v;
    #pragma unroll
    for (int off = 1; off < 32; off <<= 1) {
        int y = __shfl_up_sync(0xFFFFFFFFu, x, off);
        if (lane >= off) x += y;
    }
    if (lane == 31) warpsums[wid] = x;
    __syncthreads();
    if (wid == 0 && lane < 4) {
        int wv = warpsums[lane];
        #pragma unroll
        for (int off = 1; off < 4; off <<= 1) {
            int y = __shfl_up_sync(0xFu, wv, off);
            if (lane >= off) wv += y;
        }
        warpsums[lane] = wv;
    }
    __syncthreads();
    int woff = (wid == 0) ? 0 : warpsums[wid - 1];
    int excl = x - v + woff;
    if (tid < nblk) g_boffs[tid] = excl;
    if (tid == nblk - 1) g_offs[N_NODES] = excl + v;
}

// phase 3: add block offsets, init cursors
__global__ void scan3_kernel() {
    int i = blockIdx.x * blockDim.x + threadIdx.x;
    if (i >= N_NODES) return;
    int o = g_offs[i] + g_boffs[i >> 10];
    g_offs[i] = o;
    g_cursor[i] = o;
}

__global__ void scatter_kernel(const void* __restrict__ ei) {
    int stride = gridDim.x * blockDim.x;
    for (int e = blockIdx.x * blockDim.x + threadIdx.x; e < N_EDGES; e += stride) {
        int s = edge_val(ei, e);
        int d = edge_val(ei, (long long)N_EDGES + e);
        int p = atomicAdd(&g_cursor[d], 1);
        g_ssrc[p] = s;
    }
}

// x (N, 30, 8) -> g_xT[t][j][n]; only temporal slice read.
__global__ void __launch_bounds__(256) transpose_x(const float* __restrict__ x) {
    __shared__ float sm[32 * 161];
    int n0 = blockIdx.x * 32;
    #pragma unroll
    for (int w = 0; w < 20; w++) {
        int i = threadIdx.x + w * 256;       // 0..5119
        int nl = i / 160, off = i - nl * 160;
        sm[nl * 161 + off] = x[(size_t)(n0 + nl) * 240 + 80 + off];
    }
    __syncthreads();
    #pragma unroll
    for (int w = 0; w < 20; w++) {
        int idx = threadIdx.x + w * 256;
        int nl = idx & 31;
        int p = idx >> 5;                    // 0..159
        int t = p / 20, j = p - t * 20;
        g_xT[((size_t)t * 20 + j) * N_NODES + n0 + nl] = sm[nl * 161 + j * 8 + t];
    }
}

// Fold GNN projection into gate weights, permute rows to (i,f,g,o) quads, emit bf16.
__global__ void prep_weights(const float* __restrict__ W_ih, const float* __restrict__ W_hh,
                             const float* __restrict__ b_ih, const float* __restrict__ b_hh,
                             const float* __restrict__ W_rel, const float* __restrict__ b_rel,
                             const float* __restrict__ W_root) {
    int rp = blockIdx.x;
    int u = rp >> 2, q = rp & 3;
    int r = q * 64 + u;
    __shared__ float wg[64];
    int tid = threadIdx.x;  // 64 threads
    wg[tid] = W_ih[r * 84 + 20 + tid];
    __syncthreads();
    int c = tid;
    float m1 = 0.f, m2 = 0.f;
    #pragma unroll 8
    for (int j = 0; j < 64; j++) {
        float w = wg[j];
        m1 += w * W_rel[j * 64 + c];
        m2 += w * W_root[j * 64 + c];
    }
    m2 += W_hh[r * 64 + c];
    g_Wb[rp * 160 + 20 + c] = __float2bfloat16_rn(m1);
    g_Wb[rp * 160 + 84 + c] = __float2bfloat16_rn(m2);
    if (c < 20) g_Wb[rp * 160 + c] = __float2bfloat16_rn(W_ih[r * 84 + c]);
    if (c < 12) g_Wb[rp * 160 + 148 + c] = __float2bfloat16_rn(0.f);
    if (c == 0) {
        float s = b_ih[r] + b_hh[r];
        for (int j = 0; j < 64; j++) s += wg[j] * b_rel[j];
        g_bias[rp] = s;
    }
}

// ---------------- aggregation: warp per dst node, bf16 gather ----------------
__global__ void agg_kernel(const __nv_bfloat16* __restrict__ h16, int wf32) {
    int gw = (blockIdx.x * blockDim.x + threadIdx.x) >> 5;
    int lane = threadIdx.x & 31;
    if (gw >= N_NODES) return;
    int beg = g_offs[gw], end = g_offs[gw + 1];
    float2 acc = make_float2(0.f, 0.f);
    int e = beg;
    for (; e + 4 <= end; e += 4) {
        int s0 = g_ssrc[e], s1 = g_ssrc[e + 1], s2 = g_ssrc[e + 2], s3 = g_ssrc[e + 3];
        float2 v0 = __bfloat1622float2(
            *reinterpret_cast<const __nv_bfloat162*>(h16 + (size_t)s0 * 64 + lane * 2));
        float2 v1 = __bfloat1622float2(
            *reinterpret_cast<const __nv_bfloat162*>(h16 + (size_t)s1 * 64 + lane * 2));
        float2 v2 = __bfloat1622float2(
            *reinterpret_cast<const __nv_bfloat162*>(h16 + (size_t)s2 * 64 + lane * 2));
        float2 v3 = __bfloat1622float2(
            *reinterpret_cast<const __nv_bfloat162*>(h16 + (size_t)s3 * 64 + lane * 2));
        acc.x += (v0.x + v1.x) + (v2.x + v3.x);
        acc.y += (v0.y + v1.y) + (v2.y + v3.y);
    }
    for (; e < end; e++) {
        int s = g_ssrc[e];
        float2 v = __bfloat1622float2(
            *reinterpret_cast<const __nv_bfloat162*>(h16 + (size_t)s * 64 + lane * 2));
        acc.x += v.x;
        acc.y += v.y;
    }
    *reinterpret_cast<__nv_bfloat162*>(g_agg16 + (size_t)gw * 64 + lane * 2) =
        __float22bfloat162_rn(acc);
    if (wf32)
        *reinterpret_cast<float2*>(g_agg + (size_t)gw * 64 + lane * 2) = acc;
}

// ---------------- bf16 mma.sync gate GEMM + fused LSTM epilogue ----------------
// gates[128 x 128cols] = A[128 x 160] @ W^T ; A = [x_t(20)|agg(64)|h(64)|0(12)]
// smem: A bf16 [128][168] (stride 336B), B bf16 [128][168]; 8 warps = 4m x 2n,
// warp tile 32x64, mma.m16n8k16. blockIdx.y picks 128-col half.
#define GATE_SMEM 86016   // 2 * 128 * 336

__global__ void __launch_bounds__(256, 2)
gate_kernel(const float* __restrict__ xTt, const __nv_bfloat16* __restrict__ h16_in,
            float* __restrict__ h_out, __nv_bfloat16* __restrict__ h16_out,
            int t0, int wf32) {
    extern __shared__ char smem[];
    const int tid = threadIdx.x;
    const int wid = tid >> 5;
    const int lane = tid & 31;
    const int n0 = blockIdx.x * 128;
    const int col0 = blockIdx.y * 128;   // gate-col base (0 or 128)
    const int ubase = col0 >> 2;         // unit base (0 or 32)

    // ---- stage B (this CTA's 128 weight rows, 160 k) ----
    {
        const uint4* Wb4 = reinterpret_cast<const uint4*>(g_Wb + (size_t)col0 * 160);
        #pragma unroll
        for (int it = 0; it < 10; it++) {
            int idx = tid + it * 256;        // 0..2559 = r*20 + c
            int r = idx / 20;
            int c = idx - r * 20;
            *reinterpret_cast<uint4*>(smem + 43008 + r * 336 + c * 16) = Wb4[idx];
        }
    }
    // ---- stage A: x_t (k 0..19) ----
    #pragma unroll
    for (int it = 0; it < 10; it++) {
        int idx = tid + it * 256;            // j*128 + nl
        int j = idx >> 7;
        int nl = idx & 127;
        int n = n0 + nl;
        float v = (n < N_NODES) ? xTt[(size_t)j * N_NODES + n] : 0.f;
        *reinterpret_cast<__nv_bfloat16*>(smem + nl * 336 + j * 2) = __float2bfloat16_rn(v);
    }
    // ---- A: agg bf16 (k 20..83) + h bf16 (k 84..147): raw 8B copies ----
    #pragma unroll
    for (int it = 0; it < 8; it++) {
        int idx = tid + it * 256;            // 0..2047 = nl*16 + cp
        int nl = idx >> 4;
        int cp = idx & 15;
        int n = n0 + nl;
        uint2 va = make_uint2(0u, 0u), vh = make_uint2(0u, 0u);
        if (!t0 && n < N_NODES) {
            va = *reinterpret_cast<const uint2*>(g_agg16 + (size_t)n * 64 + cp * 4);
            vh = *reinterpret_cast<const uint2*>(h16_in + (size_t)n * 64 + cp * 4);
        }
        *reinterpret_cast<uint2*>(smem + nl * 336 + 40 + cp * 8) = va;
        *reinterpret_cast<uint2*>(smem + nl * 336 + 168 + cp * 8) = vh;
    }
    // ---- A: zero pad (k 148..167) ----
    #pragma unroll
    for (int it = 0; it < 3; it++) {
        int idx = tid + it * 256;            // 0..767 needed 640
        if (idx < 640) {
            int nl = idx / 5;
            int p = idx - nl * 5;
            *reinterpret_cast<uint2*>(smem + nl * 336 + 296 + p * 8) = make_uint2(0u, 0u);
        }
    }
    __syncthreads();

    // ---- mma mainloop ----
    const int mw = wid >> 1;                 // 0..3
    const int nw = wid & 1;                  // 0..1
    const int mr = mw * 32;
    const int nc = nw * 64;
    const uint32_t sbase = smem_u32(smem);
    uint32_t aAddr = sbase + (mr + (lane & 15)) * 336 + ((lane >> 4) << 4);
    uint32_t bAddr = sbase + 43008u + (nc + (lane & 15)) * 336 + ((lane >> 4) << 4);

    float acc[2][8][4];
    #pragma unroll
    for (int mi = 0; mi < 2; mi++)
        #pragma unroll
        for (int nj = 0; nj < 8; nj++)
            #pragma unroll
            for (int e = 0; e < 4; e++) acc[mi][nj][e] = 0.f;

    #pragma unroll
    for (int ks = 0; ks < 10; ks++) {
        uint32_t a[2][4];
        ldsm_x4(a[0], aAddr + ks * 32);
        ldsm_x4(a[1], aAddr + 16 * 336 + ks * 32);
        uint32_t b[4][4];
        #pragma unroll
        for (int nj = 0; nj < 4; nj++)
            ldsm_x4(b[nj], bAddr + nj * 16 * 336 + ks * 32);
        #pragma unroll
        for (int mi = 0; mi < 2; mi++)
            #pragma unroll
            for (int nj2 = 0; nj2 < 8; nj2++) {
                int nj = nj2 >> 1, hi = nj2 & 1;
                mma_bf16(acc[mi][nj2], a[mi], b[nj][hi], b[nj][hi + 2]);
            }
    }
    __syncthreads();

    // ---- repurpose smem: Cs[128][33], Hs[128][33], bias[128] ----
    float* Cs = reinterpret_cast<float*>(smem);
    float* Hs = Cs + 128 * 33;
    float* sbias = Hs + 128 * 33;
    #pragma unroll
    for (int it = 0; it < 16; it++) {
        int idx = tid + it * 256;
        int rr = idx >> 5;
        int u = idx & 31;
        int n = n0 + rr;
        Cs[rr * 33 + u] = (n < N_NODES) ? g_c[(size_t)n * 64 + ubase + u] : 0.f;
    }
    if (tid < 128) sbias[tid] = g_bias[col0 + tid];
    __syncthreads();

    // ---- fused LSTM epilogue ----
    #pragma unroll
    for (int mi = 0; mi < 2; mi++) {
        int row = mr + mi * 16 + (lane >> 2) + ((lane & 1) << 3);
        #pragma unroll
        for (int nj2 = 0; nj2 < 8; nj2++) {
            float d0 = acc[mi][nj2][0], d1 = acc[mi][nj2][1];
            float d2 = acc[mi][nj2][2], d3 = acc[mi][nj2][3];
            float xd0 = __shfl_xor_sync(0xFFFFFFFFu, d0, 1);
            float xd1 = __shfl_xor_sync(0xFFFFFFFFu, d1, 1);
            float xd2 = __shfl_xor_sync(0xFFFFFFFFu, d2, 1);
            float xd3 = __shfl_xor_sync(0xFFFFFFFFu, d3, 1);
            float ig, fg, gg, og;
            if (lane & 1) { ig = xd2; fg = xd3; gg = d2; og = d3; }
            else          { ig = d0;  fg = d1;  gg = xd0; og = xd1; }
            int qb = nc + nj2 * 8 + ((lane & 2) << 1);   // local col quad base
            ig += sbias[qb];
            fg += sbias[qb + 1];
            gg += sbias[qb + 2];
            og += sbias[qb + 3];
            float si = 1.f / (1.f + __expf(-ig));
            float sf = 1.f / (1.f + __expf(-fg));
            float so = 1.f / (1.f + __expf(-og));
            float tg = 2.f / (1.f + __expf(-2.f * gg)) - 1.f;
            int u = qb >> 2;
            float cold = Cs[row * 33 + u];
            float cn = sf * cold + si * tg;
            Cs[row * 33 + u] = cn;
            float tcn = 2.f / (1.f + __expf(-2.f * cn)) - 1.f;
            Hs[row * 33 + u] = so * tcn;
        }
    }
    __syncthreads();

    // ---- coalesced writeback ----
    #pragma unroll
    for (int it = 0; it < 16; it++) {
        int idx = tid + it * 256;
        int rr = idx >> 5;
        int u = idx & 31;
        int n = n0 + rr;
        if (n < N_NODES) {
            size_t o = (size_t)n * 64 + ubase + u;
            float cn = Cs[rr * 33 + u];
            float hv = Hs[rr * 33 + u];
            g_c[o] = cn;
            h16_out[o] = __float2bfloat16_rn(hv);
            if (wf32) h_out[o] = hv;
        }
    }
}

// ---------------- generic small GEMM: out = act(A @ W^T + bias) ----------------
template <int AMODE, int EPI>
__global__ void __launch_bounds__(256)
gemm64_kernel(const float* __restrict__ A0, const float* __restrict__ A1,
              const float* __restrict__ Wp0, const float* __restrict__ Wp1,
              const float* __restrict__ bias, float* __restrict__ out,
              int K, int OUT) {
    __shared__ __align__(16) float As[16][68];
    __shared__ __align__(16) float Bs[16][68];
    int tid = threadIdx.x;
    int row0 = blockIdx.x * 64;
    int col0 = blockIdx.y * 64;
    int tr = (tid >> 4) * 4;
    int tc = (tid & 15) * 4;
    float acc[4][4];
    #pragma unroll
    for (int i = 0; i < 4; i++)
        #pragma unroll
        for (int j = 0; j < 4; j++) acc[i][j] = 0.f;

    for (int kt = 0; kt < K; kt += 16) {
        #pragma unroll
        for (int it = 0; it < 4; it++) {
            int idx = tid + it * 256;
            int m = idx >> 4, kk = idx & 15;
            int n = row0 + m, gk = kt + kk;
            float v = 0.f;
            if (n < N_NODES) {
                if (AMODE == 0) {
                    v = A0[(size_t)n * K + gk];
                } else {
                    v = (gk < 64) ? A0[(size_t)n * 64 + gk] : A1[(size_t)n * 64 + gk - 64];
                    if (AMODE == 2) v = v * g_scale[gk] + g_shift[gk];
                }
            }
            As[kk][m] = v;
        }
        #pragma unroll
        for (int it = 0; it < 4; it++) {
            int idx = tid + it * 256;
            int cc = idx >> 4, kk = idx & 15;
            int oc = col0 + cc, gk = kt + kk;
            float w;
            if (Wp1) w = (gk < 64) ? Wp0[oc * 64 + gk] : Wp1[oc * 64 + gk - 64];
            else     w = Wp0[oc * K + gk];
            Bs[kk][cc] = w;
        }
        __syncthreads();
        #pragma unroll
        for (int kk = 0; kk < 16; kk++) {
            float4 a = *reinterpret_cast<const float4*>(&As[kk][tr]);
            float4 b = *reinterpret_cast<const float4*>(&Bs[kk][tc]);
            float av[4] = {a.x, a.y, a.z, a.w};
            float bv[4] = {b.x, b.y, b.z, b.w};
            #pragma unroll
            for (int i = 0; i < 4; i++)
                #pragma unroll
                for (int j = 0; j < 4; j++) acc[i][j] += av[i] * bv[j];
        }
        __syncthreads();
    }
    #pragma unroll
    for (int i = 0; i < 4; i++) {
        int n = row0 + tr + i;
        if (n >= N_NODES) continue;
        #pragma unroll
        for (int j = 0; j < 4; j++) {
            int oc = col0 + tc + j;
            float v = acc[i][j] + bias[oc];
            if (EPI == 1) v = fmaxf(v, 0.f);
            out[(size_t)n * OUT + oc] = v;
        }
    }
}

// ---------------- per-feature stats over nodes ----------------
__global__ void stats_kernel(const float* __restrict__ h, const float* __restrict__ gnn) {
    int c = threadIdx.x & 127;
    int grp = threadIdx.x >> 7;
    int r0 = blockIdx.x * 256;
    int rend = min(r0 + 256, N_NODES);
    float s = 0.f, q = 0.f;
    for (int r = r0 + grp; r < rend; r += 2) {
        float v = (c < 64) ? h[(size_t)r * 64 + c] : gnn[(size_t)r * 64 + c - 64];
        s += v;
        q += v * v;
    }
    atomicAdd(&g_stats[c], s);
    atomicAdd(&g_stats[128 + c], q);
}

__global__ void finalize_stats(const float* __restrict__ gamma, const float* __restrict__ beta) {
    int c = threadIdx.x;
    float mean = g_stats[c] / (float)N_NODES;
    float var = g_stats[128 + c] / (float)N_NODES - mean * mean;
    float rstd = rsqrtf(var + 1e-5f);
    float sc = rstd * gamma[c];
    g_scale[c] = sc;
    g_shift[c] = beta[c] - mean * sc;
}

// ---------------- final projection ----------------
__global__ void out_kernel(const float* __restrict__ hidden, const float* __restrict__ Wout,
                           const float* __restrict__ bout, float* __restrict__ out) {
    int gw = (blockIdx.x * blockDim.x + threadIdx.x) >> 5;
    int lane = threadIdx.x & 31;
    if (gw >= N_NODES) return;
    const float* hr = hidden + (size_t)gw * 128;
    float s = hr[lane] * Wout[lane] + hr[lane + 32] * Wout[lane + 32] +
              hr[lane + 64] * Wout[lane + 64] + hr[lane + 96] * Wout[lane + 96];
    #pragma unroll
    for (int off = 16; off; off >>= 1) s += __shfl_down_sync(0xFFFFFFFFu, s, off);
    if (lane == 0) out[gw] = 1.f / (1.f + __expf(-(s + bout[0])));
}

// ---------------- launch ----------------
extern "C" void kernel_launch(void* const* d_in, const int* in_sizes, int n_in,
                              void* d_out, int out_size) {
    const float* x      = (const float*)d_in[0];
    const void*  ei     = d_in[1];
    const float* W_ih   = (const float*)d_in[4];
    const float* W_hh   = (const float*)d_in[5];
    const float* b_ih   = (const float*)d_in[6];
    const float* b_hh   = (const float*)d_in[7];
    const float* W_rel  = (const float*)d_in[8];
    const float* b_rel  = (const float*)d_in[9];
    const float* W_root = (const float*)d_in[10];
    const float* gamma  = (const float*)d_in[11];
    const float* beta   = (const float*)d_in[12];
    const float* W1     = (const float*)d_in[13];
    const float* b1     = (const float*)d_in[14];
    const float* W2     = (const float*)d_in[15];
    const float* b2     = (const float*)d_in[16];
    const float* W_out  = (const float*)d_in[17];
    const float* b_out  = (const float*)d_in[18];

    float *hbuf, *agg, *gnn, *h1, *hidden, *xT;
    __nv_bfloat16* h16;
    cudaGetSymbolAddress((void**)&hbuf, g_hbuf);
    cudaGetSymbolAddress((void**)&h16, g_h16);
    cudaGetSymbolAddress((void**)&agg, g_agg);
    cudaGetSymbolAddress((void**)&gnn, g_gnn);
    cudaGetSymbolAddress((void**)&h1, g_h1);
    cudaGetSymbolAddress((void**)&hidden, g_hidden);
    cudaGetSymbolAddress((void**)&xT, g_xT);

    cudaFuncSetAttribute(gate_kernel, cudaFuncAttributeMaxDynamicSharedMemorySize,
                         GATE_SMEM);

    const int scan_blocks = (N_NODES + 1023) / 1024;   // 98

    zero_state<<<512, 256>>>();
    detect_kernel<<<1, 256>>>((const unsigned int*)ei);
    prep_weights<<<256, 64>>>(W_ih, W_hh, b_ih, b_hh, W_rel, b_rel, W_root);
    transpose_x<<<N_NODES / 32, 256>>>(x);
    hist_zero<<<256, 256>>>();
    hist2_kernel<<<512, 256>>>(ei);
    scan1_kernel<<<scan_blocks, 1024>>>();
    scan2_kernel<<<1, 128>>>(scan_blocks);
    scan3_kernel<<<(N_NODES + 255) / 256, 256>>>();
    scatter_kernel<<<512, 256>>>(ei);

    dim3 ggrid((N_NODES + 127) / 128, 2);
    for (int t = 0; t < T_STEPS; t++) {
        const __nv_bfloat16* h16_in = h16 + (size_t)(t & 1) * N_NODES * 64;
        __nv_bfloat16* h16_out = h16 + (size_t)((t + 1) & 1) * N_NODES * 64;
        const float* hf_in = hbuf + (size_t)(t & 1) * N_NODES * 64;
        float* hf_out = hbuf + (size_t)((t + 1) & 1) * N_NODES * 64;
        if (t > 0) agg_kernel<<<(N_NODES * 32 + 255) / 256, 256>>>(h16_in, t == T_STEPS - 1);
        if (t == T_STEPS - 1) {
            // gnn_out = agg @ W_rel^T + h @ W_root^T + b_rel (fp32 inputs)
            gemm64_kernel<1, 0><<<dim3((N_NODES + 63) / 64, 1), 256>>>(
                agg, hf_in, W_rel, W_root, b_rel, gnn, 128, 64);
        }
        gate_kernel<<<ggrid, 256, GATE_SMEM>>>(
            xT + (size_t)t * 20 * N_NODES, h16_in, hf_out, h16_out,
            t == 0 ? 1 : 0, t >= T_STEPS - 2 ? 1 : 0);
    }
    const float* hfin = hbuf;  // h after 8 steps lives in buffer 0

    stats_kernel<<<(N_NODES + 255) / 256, 256>>>(hfin, gnn);
    finalize_stats<<<1, 128>>>(gamma, beta);
    gemm64_kernel<2, 1><<<dim3((N_NODES + 63) / 64, 1), 256>>>(
        hfin, gnn, W1, nullptr, b1, h1, 128, 64);
    gemm64_kernel<0, 1><<<dim3((N_NODES + 63) / 64, 2), 256>>>(
        h1, nullptr, W2, nullptr, b2, hidden, 64, 128);
    out_kernel<<<(N_NODES * 32 + 255) / 256, 256>>>(hidden, W_out, b_out, (float*)d_out);
}

// round 7
// speedup vs baseline: 1.1763x; 1.1605x over previous
#include <cuda_runtime.h>
#include <cuda_bf16.h>
#include <math.h>
#include <cstdint>

#define N_NODES 100000
#define N_EDGES 1600000
#define T_STEPS 8

// ---------------- device scratch (no allocations allowed) ----------------
__device__ float g_hbuf[N_NODES * 64];                     // fp32 final h (t=7 only)
__device__ __nv_bfloat16 g_h16[2 * N_NODES * 64];          // bf16 h double buffer
__device__ float g_c[N_NODES * 64];
__device__ __nv_bfloat16 g_agg16[N_NODES * 64];
__device__ float g_gnn[N_NODES * 64];
__device__ float g_xT[T_STEPS * 20 * N_NODES];             // [t][j][n]
__device__ __align__(16) __nv_bfloat16 g_Wb[256 * 160];    // fused gate weights
__device__ __align__(16) __nv_bfloat16 g_W1b[64 * 128];
__device__ __align__(16) __nv_bfloat16 g_W2b[128 * 64];
__device__ __align__(16) __nv_bfloat16 g_Whb[64 * 128];    // [W_rel | W_root]
__device__ float g_bias[256];
__device__ float g_stats[256];
__device__ float g_scale[128];
__device__ float g_shift[128];
__device__ int   g_deg[N_NODES];
__device__ int   g_offs[N_NODES + 1];
__device__ int   g_cursor[N_NODES];
__device__ int   g_ssrc[N_EDGES];
__device__ int   g_bsums[128];
__device__ int   g_boffs[128];
__device__ int   g_is64;

// ---------------- mma/ldmatrix helpers ----------------
__device__ __forceinline__ uint32_t smem_u32(const void* p) {
    uint32_t a;
    asm("{ .reg .u64 tmp; cvta.to.shared.u64 tmp, %1; cvt.u32.u64 %0, tmp; }"
        : "=r"(a) : "l"(p));
    return a;
}
__device__ __forceinline__ void ldsm_x4(uint32_t* r, uint32_t addr) {
    asm volatile("ldmatrix.sync.aligned.m8n8.x4.shared.b16 {%0,%1,%2,%3}, [%4];"
                 : "=r"(r[0]), "=r"(r[1]), "=r"(r[2]), "=r"(r[3]) : "r"(addr));
}
__device__ __forceinline__ void mma_bf16(float* d, const uint32_t* a,
                                         uint32_t b0, uint32_t b1) {
    asm volatile(
        "mma.sync.aligned.m16n8k16.row.col.f32.bf16.bf16.f32 "
        "{%0,%1,%2,%3}, {%4,%5,%6,%7}, {%8,%9}, {%0,%1,%2,%3};"
        : "+f"(d[0]), "+f"(d[1]), "+f"(d[2]), "+f"(d[3])
        : "r"(a[0]), "r"(a[1]), "r"(a[2]), "r"(a[3]), "r"(b0), "r"(b1));
}

// ---------------- small utility kernels ----------------
__global__ void zero_state() {
    int stride = gridDim.x * blockDim.x;
    int i0 = blockIdx.x * blockDim.x + threadIdx.x;
    for (int k = i0; k < N_NODES * 64; k += stride) g_c[k] = 0.f;
    if (i0 < 256) g_stats[i0] = 0.f;
}

__global__ void detect_kernel(const unsigned int* __restrict__ w) {
    __shared__ unsigned int acc;
    if (threadIdx.x == 0) acc = 0u;
    __syncthreads();
    unsigned int v = 0u;
    for (int i = threadIdx.x; i < 2048; i += blockDim.x) v |= w[2 * i + 1];
    atomicOr(&acc, v);
    __syncthreads();
    if (threadIdx.x == 0) g_is64 = (acc == 0u) ? 1 : 0;
}

__device__ __forceinline__ int edge_val(const void* ei, long long idx) {
    if (g_is64) return (int)((const long long*)ei)[idx];
    return ((const int*)ei)[idx];
}

__global__ void hist_zero() {
    int stride = gridDim.x * blockDim.x;
    int i0 = blockIdx.x * blockDim.x + threadIdx.x;
    for (int k = i0; k < N_NODES; k += stride) g_deg[k] = 0;
}

__global__ void hist2_kernel(const void* __restrict__ ei) {
    int stride = gridDim.x * blockDim.x;
    for (int e = blockIdx.x * blockDim.x + threadIdx.x; e < N_EDGES; e += stride) {
        int d = edge_val(ei, (long long)N_EDGES + e);
        atomicAdd(&g_deg[d], 1);
    }
}

__global__ void scan1_kernel() {
    __shared__ int warpsums[32];
    int tid = threadIdx.x, lane = tid & 31, wid = tid >> 5;
    int i = blockIdx.x * 1024 + tid;
    int v = (i < N_NODES) ? g_deg[i] : 0;
    int x = v;
    #pragma unroll
    for (int off = 1; off < 32; off <<= 1) {
        int y = __shfl_up_sync(0xFFFFFFFFu, x, off);
        if (lane >= off) x += y;
    }
    if (lane == 31) warpsums[wid] = x;
    __syncthreads();
    if (wid == 0) {
        int wv = warpsums[lane];
        #pragma unroll
        for (int off = 1; off < 32; off <<= 1) {
            int y = __shfl_up_sync(0xFFFFFFFFu, wv, off);
            if (lane >= off) wv += y;
        }
        warpsums[lane] = wv;
    }
    __syncthreads();
    int woff = (wid == 0) ? 0 : warpsums[wid - 1];
    if (i < N_NODES) g_offs[i] = x - v + woff;
    if (tid == 1023) g_bsums[blockIdx.x] = warpsums[31];
}

__global__ void scan2_kernel(int nblk) {
    __shared__ int warpsums[4];
    int tid = threadIdx.x, lane = tid & 31, wid = tid >> 5;
    int v = (tid < nblk) ? g_bsums[tid] : 0;
    int x = v;
    #pragma unroll
    for (int off = 1; off < 32; off <<= 1) {
        int y = __shfl_up_sync(0xFFFFFFFFu, x, off);
        if (lane >= off) x += y;
    }
    if (lane == 31) warpsums[wid] = x;
    __syncthreads();
    if (wid == 0 && lane < 4) {
        int wv = warpsums[lane];
        #pragma unroll
        for (int off = 1; off < 4; off <<= 1) {
            int y = __shfl_up_sync(0xFu, wv, off);
            if (lane >= off) wv += y;
        }
        warpsums[lane] = wv;
    }
    __syncthreads();
    int woff = (wid == 0) ? 0 : warpsums[wid - 1];
    int excl = x - v + woff;
    if (tid < nblk) g_boffs[tid] = excl;
    if (tid == nblk - 1) g_offs[N_NODES] = excl + v;
}

__global__ void scan3_kernel() {
    int i = blockIdx.x * blockDim.x + threadIdx.x;
    if (i >= N_NODES) return;
    int o = g_offs[i] + g_boffs[i >> 10];
    g_offs[i] = o;
    g_cursor[i] = o;
}

__global__ void scatter_kernel(const void* __restrict__ ei) {
    int stride = gridDim.x * blockDim.x;
    for (int e = blockIdx.x * blockDim.x + threadIdx.x; e < N_EDGES; e += stride) {
        int s = edge_val(ei, e);
        int d = edge_val(ei, (long long)N_EDGES + e);
        int p = atomicAdd(&g_cursor[d], 1);
        g_ssrc[p] = s;
    }
}

// x (N, 30, 8) -> g_xT[t][j][n]; only temporal slice read.
__global__ void __launch_bounds__(256) transpose_x(const float* __restrict__ x) {
    __shared__ float sm[32 * 161];
    int n0 = blockIdx.x * 32;
    #pragma unroll
    for (int w = 0; w < 20; w++) {
        int i = threadIdx.x + w * 256;
        int nl = i / 160, off = i - nl * 160;
        sm[nl * 161 + off] = x[(size_t)(n0 + nl) * 240 + 80 + off];
    }
    __syncthreads();
    #pragma unroll
    for (int w = 0; w < 20; w++) {
        int idx = threadIdx.x + w * 256;
        int nl = idx & 31;
        int p = idx >> 5;
        int t = p / 20, j = p - t * 20;
        g_xT[((size_t)t * 20 + j) * N_NODES + n0 + nl] = sm[nl * 161 + j * 8 + t];
    }
}

// Fold GNN projection into gate weights, permute rows to (i,f,g,o) quads, emit bf16.
__global__ void prep_weights(const float* __restrict__ W_ih, const float* __restrict__ W_hh,
                             const float* __restrict__ b_ih, const float* __restrict__ b_hh,
                             const float* __restrict__ W_rel, const float* __restrict__ b_rel,
                             const float* __restrict__ W_root) {
    int rp = blockIdx.x;
    int u = rp >> 2, q = rp & 3;
    int r = q * 64 + u;
    __shared__ float wg[64];
    int tid = threadIdx.x;  // 64 threads
    wg[tid] = W_ih[r * 84 + 20 + tid];
    __syncthreads();
    int c = tid;
    float m1 = 0.f, m2 = 0.f;
    #pragma unroll 8
    for (int j = 0; j < 64; j++) {
        float w = wg[j];
        m1 += w * W_rel[j * 64 + c];
        m2 += w * W_root[j * 64 + c];
    }
    m2 += W_hh[r * 64 + c];
    g_Wb[rp * 160 + 20 + c] = __float2bfloat16_rn(m1);
    g_Wb[rp * 160 + 84 + c] = __float2bfloat16_rn(m2);
    if (c < 20) g_Wb[rp * 160 + c] = __float2bfloat16_rn(W_ih[r * 84 + c]);
    if (c < 12) g_Wb[rp * 160 + 148 + c] = __float2bfloat16_rn(0.f);
    if (c == 0) {
        float s = b_ih[r] + b_hh[r];
        for (int j = 0; j < 64; j++) s += wg[j] * b_rel[j];
        g_bias[rp] = s;
    }
}

// bf16 copies of head weights.
__global__ void prep_head(const float* __restrict__ W1, const float* __restrict__ W2,
                          const float* __restrict__ W_rel, const float* __restrict__ W_root) {
    int i = blockIdx.x * 256 + threadIdx.x;
    if (i < 8192) {
        g_W1b[i] = __float2bfloat16_rn(W1[i]);
    } else if (i < 16384) {
        g_W2b[i - 8192] = __float2bfloat16_rn(W2[i - 8192]);
    } else if (i < 24576) {
        int j = i - 16384;
        int o = j >> 7, k = j & 127;
        float v = (k < 64) ? W_rel[o * 64 + k] : W_root[o * 64 + k - 64];
        g_Whb[j] = __float2bfloat16_rn(v);
    }
}

// ---------------- aggregation: warp per dst node, bf16 gather ----------------
__global__ void agg_kernel(const __nv_bfloat16* __restrict__ h16) {
    int gw = (blockIdx.x * blockDim.x + threadIdx.x) >> 5;
    int lane = threadIdx.x & 31;
    if (gw >= N_NODES) return;
    int beg = g_offs[gw], end = g_offs[gw + 1];
    float2 acc = make_float2(0.f, 0.f);
    int e = beg;
    for (; e + 4 <= end; e += 4) {
        int s0 = g_ssrc[e], s1 = g_ssrc[e + 1], s2 = g_ssrc[e + 2], s3 = g_ssrc[e + 3];
        float2 v0 = __bfloat1622float2(
            *reinterpret_cast<const __nv_bfloat162*>(h16 + (size_t)s0 * 64 + lane * 2));
        float2 v1 = __bfloat1622float2(
            *reinterpret_cast<const __nv_bfloat162*>(h16 + (size_t)s1 * 64 + lane * 2));
        float2 v2 = __bfloat1622float2(
            *reinterpret_cast<const __nv_bfloat162*>(h16 + (size_t)s2 * 64 + lane * 2));
        float2 v3 = __bfloat1622float2(
            *reinterpret_cast<const __nv_bfloat162*>(h16 + (size_t)s3 * 64 + lane * 2));
        acc.x += (v0.x + v1.x) + (v2.x + v3.x);
        acc.y += (v0.y + v1.y) + (v2.y + v3.y);
    }
    for (; e < end; e++) {
        int s = g_ssrc[e];
        float2 v = __bfloat1622float2(
            *reinterpret_cast<const __nv_bfloat162*>(h16 + (size_t)s * 64 + lane * 2));
        acc.x += v.x;
        acc.y += v.y;
    }
    *reinterpret_cast<__nv_bfloat162*>(g_agg16 + (size_t)gw * 64 + lane * 2) =
        __float22bfloat162_rn(acc);
}

// ---------------- bf16 mma.sync gate GEMM + fused LSTM epilogue ----------------
#define GATE_SMEM 86016   // 2 * 128 * 336

__global__ void __launch_bounds__(256, 2)
gate_kernel(const float* __restrict__ xTt, const __nv_bfloat16* __restrict__ h16_in,
            float* __restrict__ h_out, __nv_bfloat16* __restrict__ h16_out,
            int t0, int wf32) {
    extern __shared__ char smem[];
    const int tid = threadIdx.x;
    const int wid = tid >> 5;
    const int lane = tid & 31;
    const int n0 = blockIdx.x * 128;
    const int col0 = blockIdx.y * 128;
    const int ubase = col0 >> 2;

    {
        const uint4* Wb4 = reinterpret_cast<const uint4*>(g_Wb + (size_t)col0 * 160);
        #pragma unroll
        for (int it = 0; it < 10; it++) {
            int idx = tid + it * 256;
            int r = idx / 20;
            int c = idx - r * 20;
            *reinterpret_cast<uint4*>(smem + 43008 + r * 336 + c * 16) = Wb4[idx];
        }
    }
    #pragma unroll
    for (int it = 0; it < 10; it++) {
        int idx = tid + it * 256;
        int j = idx >> 7;
        int nl = idx & 127;
        int n = n0 + nl;
        float v = (n < N_NODES) ? xTt[(size_t)j * N_NODES + n] : 0.f;
        *reinterpret_cast<__nv_bfloat16*>(smem + nl * 336 + j * 2) = __float2bfloat16_rn(v);
    }
    #pragma unroll
    for (int it = 0; it < 8; it++) {
        int idx = tid + it * 256;
        int nl = idx >> 4;
        int cp = idx & 15;
        int n = n0 + nl;
        uint2 va = make_uint2(0u, 0u), vh = make_uint2(0u, 0u);
        if (!t0 && n < N_NODES) {
            va = *reinterpret_cast<const uint2*>(g_agg16 + (size_t)n * 64 + cp * 4);
            vh = *reinterpret_cast<const uint2*>(h16_in + (size_t)n * 64 + cp * 4);
        }
        *reinterpret_cast<uint2*>(smem + nl * 336 + 40 + cp * 8) = va;
        *reinterpret_cast<uint2*>(smem + nl * 336 + 168 + cp * 8) = vh;
    }
    #pragma unroll
    for (int it = 0; it < 3; it++) {
        int idx = tid + it * 256;
        if (idx < 640) {
            int nl = idx / 5;
            int p = idx - nl * 5;
            *reinterpret_cast<uint2*>(smem + nl * 336 + 296 + p * 8) = make_uint2(0u, 0u);
        }
    }
    __syncthreads();

    const int mw = wid >> 1;
    const int nw = wid & 1;
    const int mr = mw * 32;
    const int nc = nw * 64;
    const uint32_t sbase = smem_u32(smem);
    uint32_t aAddr = sbase + (mr + (lane & 15)) * 336 + ((lane >> 4) << 4);
    uint32_t bAddr = sbase + 43008u + (nc + (lane & 15)) * 336 + ((lane >> 4) << 4);

    float acc[2][8][4];
    #pragma unroll
    for (int mi = 0; mi < 2; mi++)
        #pragma unroll
        for (int nj = 0; nj < 8; nj++)
            #pragma unroll
            for (int e = 0; e < 4; e++) acc[mi][nj][e] = 0.f;

    #pragma unroll
    for (int ks = 0; ks < 10; ks++) {
        uint32_t a[2][4];
        ldsm_x4(a[0], aAddr + ks * 32);
        ldsm_x4(a[1], aAddr + 16 * 336 + ks * 32);
        uint32_t b[4][4];
        #pragma unroll
        for (int nj = 0; nj < 4; nj++)
            ldsm_x4(b[nj], bAddr + nj * 16 * 336 + ks * 32);
        #pragma unroll
        for (int mi = 0; mi < 2; mi++)
            #pragma unroll
            for (int nj2 = 0; nj2 < 8; nj2++) {
                int nj = nj2 >> 1, hi = nj2 & 1;
                mma_bf16(acc[mi][nj2], a[mi], b[nj][hi], b[nj][hi + 2]);
            }
    }
    __syncthreads();

    float* Cs = reinterpret_cast<float*>(smem);
    float* Hs = Cs + 128 * 33;
    float* sbias = Hs + 128 * 33;
    #pragma unroll
    for (int it = 0; it < 16; it++) {
        int idx = tid + it * 256;
        int rr = idx >> 5;
        int u = idx & 31;
        int n = n0 + rr;
        Cs[rr * 33 + u] = (n < N_NODES) ? g_c[(size_t)n * 64 + ubase + u] : 0.f;
    }
    if (tid < 128) sbias[tid] = g_bias[col0 + tid];
    __syncthreads();

    #pragma unroll
    for (int mi = 0; mi < 2; mi++) {
        int row = mr + mi * 16 + (lane >> 2) + ((lane & 1) << 3);
        #pragma unroll
        for (int nj2 = 0; nj2 < 8; nj2++) {
            float d0 = acc[mi][nj2][0], d1 = acc[mi][nj2][1];
            float d2 = acc[mi][nj2][2], d3 = acc[mi][nj2][3];
            float xd0 = __shfl_xor_sync(0xFFFFFFFFu, d0, 1);
            float xd1 = __shfl_xor_sync(0xFFFFFFFFu, d1, 1);
            float xd2 = __shfl_xor_sync(0xFFFFFFFFu, d2, 1);
            float xd3 = __shfl_xor_sync(0xFFFFFFFFu, d3, 1);
            float ig, fg, gg, og;
            if (lane & 1) { ig = xd2; fg = xd3; gg = d2; og = d3; }
            else          { ig = d0;  fg = d1;  gg = xd0; og = xd1; }
            int qb = nc + nj2 * 8 + ((lane & 2) << 1);
            ig += sbias[qb];
            fg += sbias[qb + 1];
            gg += sbias[qb + 2];
            og += sbias[qb + 3];
            float si = 1.f / (1.f + __expf(-ig));
            float sf = 1.f / (1.f + __expf(-fg));
            float so = 1.f / (1.f + __expf(-og));
            float tg = 2.f / (1.f + __expf(-2.f * gg)) - 1.f;
            int u = qb >> 2;
            float cold = Cs[row * 33 + u];
            float cn = sf * cold + si * tg;
            Cs[row * 33 + u] = cn;
            float tcn = 2.f / (1.f + __expf(-2.f * cn)) - 1.f;
            Hs[row * 33 + u] = so * tcn;
        }
    }
    __syncthreads();

    #pragma unroll
    for (int it = 0; it < 16; it++) {
        int idx = tid + it * 256;
        int rr = idx >> 5;
        int u = idx & 31;
        int n = n0 + rr;
        if (n < N_NODES) {
            size_t o = (size_t)n * 64 + ubase + u;
            float cn = Cs[rr * 33 + u];
            float hv = Hs[rr * 33 + u];
            g_c[o] = cn;
            h16_out[o] = __float2bfloat16_rn(hv);
            if (wf32) h_out[o] = hv;
        }
    }
}

// ---------------- head1: gnn = [agg|h] @ [W_rel|W_root]^T + b_rel (mma) ------
// A [128 x 136] bf16 stride 272B @0 ; B [64 x 136] @34816 ; sb @52224
#define H1_SMEM 52480

__global__ void __launch_bounds__(256)
head1_kernel(const __nv_bfloat16* __restrict__ h16in, const float* __restrict__ b_rel) {
    extern __shared__ char smem[];
    const int tid = threadIdx.x;
    const int wid = tid >> 5;
    const int lane = tid & 31;
    const int n0 = blockIdx.x * 128;
    float* sb = reinterpret_cast<float*>(smem + 52224);

    {
        const uint4* Wh4 = reinterpret_cast<const uint4*>(g_Whb);
        #pragma unroll
        for (int it = 0; it < 4; it++) {
            int idx = tid + it * 256;          // 0..1023
            int r = idx >> 4, c16 = idx & 15;
            *reinterpret_cast<uint4*>(smem + 34816 + r * 272 + c16 * 16) = Wh4[idx];
        }
    }
    #pragma unroll
    for (int it = 0; it < 8; it++) {
        int idx = tid + it * 256;              // 0..2047
        int nl = idx >> 4, q = idx & 15;
        int n = n0 + nl;
        uint4 v = make_uint4(0u, 0u, 0u, 0u);
        if (n < N_NODES) {
            if (q < 8) v = reinterpret_cast<const uint4*>(g_agg16 + (size_t)n * 64)[q];
            else       v = reinterpret_cast<const uint4*>(h16in + (size_t)n * 64)[q - 8];
        }
        *reinterpret_cast<uint4*>(smem + nl * 272 + q * 16) = v;
    }
    if (tid < 128)
        *reinterpret_cast<uint4*>(smem + tid * 272 + 256) = make_uint4(0u, 0u, 0u, 0u);
    if (tid < 64) sb[tid] = b_rel[tid];
    __syncthreads();

    const int mw = wid >> 1;                   // 0..3
    const int nw = wid & 1;                    // 0..1
    const int mr = mw * 32;
    const int nc = nw * 32;
    const uint32_t sbase = smem_u32(smem);
    uint32_t aAddr = sbase + (mr + (lane & 15)) * 272 + ((lane >> 4) << 4);
    uint32_t bAddr = sbase + 34816u + (nc + (lane & 15)) * 272 + ((lane >> 4) << 4);

    float acc[2][4][4];
    #pragma unroll
    for (int mi = 0; mi < 2; mi++)
        #pragma unroll
        for (int nj = 0; nj < 4; nj++)
            #pragma unroll
            for (int e = 0; e < 4; e++) acc[mi][nj][e] = 0.f;

    #pragma unroll
    for (int ks = 0; ks < 8; ks++) {
        uint32_t a[2][4];
        ldsm_x4(a[0], aAddr + ks * 32);
        ldsm_x4(a[1], aAddr + 16 * 272 + ks * 32);
        uint32_t b[2][4];
        ldsm_x4(b[0], bAddr + ks * 32);
        ldsm_x4(b[1], bAddr + 16 * 272 + ks * 32);
        #pragma unroll
        for (int mi = 0; mi < 2; mi++)
            #pragma unroll
            for (int nj2 = 0; nj2 < 4; nj2++) {
                int nj = nj2 >> 1, hi = nj2 & 1;
                mma_bf16(acc[mi][nj2], a[mi], b[nj][hi], b[nj][hi + 2]);
            }
    }
    __syncthreads();

    float* Gs = reinterpret_cast<float*>(smem);   // [128][68]
    #pragma unroll
    for (int mi = 0; mi < 2; mi++) {
        int row = mr + mi * 16 + (lane >> 2);
        #pragma unroll
        for (int nj2 = 0; nj2 < 4; nj2++) {
            int c = nc + nj2 * 8 + (lane & 3) * 2;
            *reinterpret_cast<float2*>(&Gs[row * 68 + c]) =
                make_float2(acc[mi][nj2][0] + sb[c], acc[mi][nj2][1] + sb[c + 1]);
            *reinterpret_cast<float2*>(&Gs[(row + 8) * 68 + c]) =
                make_float2(acc[mi][nj2][2] + sb[c], acc[mi][nj2][3] + sb[c + 1]);
        }
    }
    __syncthreads();

    #pragma unroll
    for (int it = 0; it < 32; it++) {
        int idx = tid + it * 256;
        int rr = idx >> 6, u = idx & 63;
        int n = n0 + rr;
        if (n < N_NODES) g_gnn[(size_t)n * 64 + u] = Gs[rr * 68 + u];
    }
}

// ---------------- head2: fused layernorm + MLP + out-projection (mma) --------
// A1[128x136]@0  B1=W1[64x136]@34816  A2[128x72]@52224  B2=W2[128x72]@70656
// sb1@89088 sb2@89344 sWout@89856 sdot@90368 ; total 90880
#define H2_SMEM 90880

__global__ void __launch_bounds__(256)
head2_kernel(const float* __restrict__ hfin, const float* __restrict__ b1,
             const float* __restrict__ b2, const float* __restrict__ Wout,
             const float* __restrict__ bout, float* __restrict__ out) {
    extern __shared__ char smem[];
    const int tid = threadIdx.x;
    const int wid = tid >> 5;
    const int lane = tid & 31;
    const int n0 = blockIdx.x * 128;
    float* sb1 = reinterpret_cast<float*>(smem + 89088);
    float* sb2 = reinterpret_cast<float*>(smem + 89344);
    float* sWout = reinterpret_cast<float*>(smem + 89856);
    float* sdot = reinterpret_cast<float*>(smem + 90368);

    // ---- stage A1 = layernorm([h|gnn]) in bf16 ----
    #pragma unroll
    for (int it = 0; it < 32; it++) {
        int idx = tid + it * 256;              // 0..8191
        int nl = idx >> 6, cp = idx & 63;
        int c = cp * 2;
        int n = n0 + nl;
        float2 v = make_float2(0.f, 0.f);
        if (n < N_NODES) {
            v = (cp < 32)
                ? reinterpret_cast<const float2*>(hfin)[(size_t)n * 32 + cp]
                : reinterpret_cast<const float2*>(g_gnn)[(size_t)n * 32 + cp - 32];
        }
        float2 nv = make_float2(v.x * g_scale[c] + g_shift[c],
                                v.y * g_scale[c + 1] + g_shift[c + 1]);
        *reinterpret_cast<__nv_bfloat162*>(smem + nl * 272 + c * 2) =
            __float22bfloat162_rn(nv);
    }
    if (tid < 128)
        *reinterpret_cast<uint4*>(smem + tid * 272 + 256) = make_uint4(0u, 0u, 0u, 0u);
    // ---- stage B1, B2 ----
    {
        const uint4* W14 = reinterpret_cast<const uint4*>(g_W1b);
        #pragma unroll
        for (int it = 0; it < 4; it++) {
            int idx = tid + it * 256;          // 0..1023
            int r = idx >> 4, c16 = idx & 15;
            *reinterpret_cast<uint4*>(smem + 34816 + r * 272 + c16 * 16) = W14[idx];
        }
        const uint4* W24 = reinterpret_cast<const uint4*>(g_W2b);
        #pragma unroll
        for (int it = 0; it < 4; it++) {
            int idx = tid + it * 256;          // 0..1023
            int r = idx >> 3, c8 = idx & 7;
            *reinterpret_cast<uint4*>(smem + 70656 + r * 144 + c8 * 16) = W24[idx];
        }
    }
    if (tid < 64) sb1[tid] = b1[tid];
    if (tid < 128) {
        sb2[tid] = b2[tid];
        sWout[tid] = Wout[tid];
        sdot[tid] = 0.f;
    }
    __syncthreads();

    const int mw = wid >> 1;
    const int nw = wid & 1;
    const int mr = mw * 32;
    const uint32_t sbase = smem_u32(smem);

    // ---- mma1: h1 = relu(A1 @ W1^T + b1) -> A2 bf16 ----
    {
        const int nc = nw * 32;
        uint32_t aAddr = sbase + (mr + (lane & 15)) * 272 + ((lane >> 4) << 4);
        uint32_t bAddr = sbase + 34816u + (nc + (lane & 15)) * 272 + ((lane >> 4) << 4);
        float acc1[2][4][4];
        #pragma unroll
        for (int mi = 0; mi < 2; mi++)
            #pragma unroll
            for (int nj = 0; nj < 4; nj++)
                #pragma unroll
                for (int e = 0; e < 4; e++) acc1[mi][nj][e] = 0.f;
        #pragma unroll
        for (int ks = 0; ks < 8; ks++) {
            uint32_t a[2][4];
            ldsm_x4(a[0], aAddr + ks * 32);
            ldsm_x4(a[1], aAddr + 16 * 272 + ks * 32);
            uint32_t b[2][4];
            ldsm_x4(b[0], bAddr + ks * 32);
            ldsm_x4(b[1], bAddr + 16 * 272 + ks * 32);
            #pragma unroll
            for (int mi = 0; mi < 2; mi++)
                #pragma unroll
                for (int nj2 = 0; nj2 < 4; nj2++) {
                    int nj = nj2 >> 1, hi = nj2 & 1;
                    mma_bf16(acc1[mi][nj2], a[mi], b[nj][hi], b[nj][hi + 2]);
                }
        }
        #pragma unroll
        for (int mi = 0; mi < 2; mi++) {
            int row = mr + mi * 16 + (lane >> 2);
            #pragma unroll
            for (int nj2 = 0; nj2 < 4; nj2++) {
                int c = nc + nj2 * 8 + (lane & 3) * 2;
                float v0 = fmaxf(acc1[mi][nj2][0] + sb1[c], 0.f);
                float v1 = fmaxf(acc1[mi][nj2][1] + sb1[c + 1], 0.f);
                float v2 = fmaxf(acc1[mi][nj2][2] + sb1[c], 0.f);
                float v3 = fmaxf(acc1[mi][nj2][3] + sb1[c + 1], 0.f);
                *reinterpret_cast<__nv_bfloat162*>(smem + 52224 + row * 144 + c * 2) =
                    __float22bfloat162_rn(make_float2(v0, v1));
                *reinterpret_cast<__nv_bfloat162*>(smem + 52224 + (row + 8) * 144 + c * 2) =
                    __float22bfloat162_rn(make_float2(v2, v3));
            }
        }
    }
    __syncthreads();

    // ---- mma2: hidden = relu(A2 @ W2^T + b2); dot with Wout ----
    {
        const int nc = nw * 64;
        uint32_t aAddr = sbase + 52224u + (mr + (lane & 15)) * 144 + ((lane >> 4) << 4);
        uint32_t bAddr = sbase + 70656u + (nc + (lane & 15)) * 144 + ((lane >> 4) << 4);
        float acc2[2][8][4];
        #pragma unroll
        for (int mi = 0; mi < 2; mi++)
            #pragma unroll
            for (int nj = 0; nj < 8; nj++)
                #pragma unroll
                for (int e = 0; e < 4; e++) acc2[mi][nj][e] = 0.f;
        #pragma unroll
        for (int ks = 0; ks < 4; ks++) {
            uint32_t a[2][4];
            ldsm_x4(a[0], aAddr + ks * 32);
            ldsm_x4(a[1], aAddr + 16 * 144 + ks * 32);
            uint32_t b[4][4];
            #pragma unroll
            for (int nj = 0; nj < 4; nj++)
                ldsm_x4(b[nj], bAddr + nj * 16 * 144 + ks * 32);
            #pragma unroll
            for (int mi = 0; mi < 2; mi++)
                #pragma unroll
                for (int nj2 = 0; nj2 < 8; nj2++) {
                    int nj = nj2 >> 1, hi = nj2 & 1;
                    mma_bf16(acc2[mi][nj2], a[mi], b[nj][hi], b[nj][hi + 2]);
                }
        }
        // per-row partial dot with Wout
        #pragma unroll
        for (int mi = 0; mi < 2; mi++) {
            float p0 = 0.f, p1 = 0.f;
            #pragma unroll
            for (int nj2 = 0; nj2 < 8; nj2++) {
                int c = nc + nj2 * 8 + (lane & 3) * 2;
                float w0 = sWout[c], w1 = sWout[c + 1];
                p0 += fmaxf(acc2[mi][nj2][0] + sb2[c], 0.f) * w0
                    + fmaxf(acc2[mi][nj2][1] + sb2[c + 1], 0.f) * w1;
                p1 += fmaxf(acc2[mi][nj2][2] + sb2[c], 0.f) * w0
                    + fmaxf(acc2[mi][nj2][3] + sb2[c + 1], 0.f) * w1;
            }
            p0 += __shfl_xor_sync(0xFFFFFFFFu, p0, 1);
            p0 += __shfl_xor_sync(0xFFFFFFFFu, p0, 2);
            p1 += __shfl_xor_sync(0xFFFFFFFFu, p1, 1);
            p1 += __shfl_xor_sync(0xFFFFFFFFu, p1, 2);
            if ((lane & 3) == 0) {
                int row = mr + mi * 16 + (lane >> 2);
                atomicAdd(&sdot[row], p0);
                atomicAdd(&sdot[row + 8], p1);
            }
        }
    }
    __syncthreads();

    if (tid < 128) {
        int n = n0 + tid;
        if (n < N_NODES) {
            float s = sdot[tid] + bout[0];
            out[n] = 1.f / (1.f + __expf(-s));
        }
    }
}

// ---------------- per-feature stats over nodes ----------------
__global__ void stats_kernel(const float* __restrict__ h, const float* __restrict__ gnn) {
    int c = threadIdx.x & 127;
    int grp = threadIdx.x >> 7;
    int r0 = blockIdx.x * 256;
    int rend = min(r0 + 256, N_NODES);
    float s = 0.f, q = 0.f;
    for (int r = r0 + grp; r < rend; r += 2) {
        float v = (c < 64) ? h[(size_t)r * 64 + c] : gnn[(size_t)r * 64 + c - 64];
        s += v;
        q += v * v;
    }
    atomicAdd(&g_stats[c], s);
    atomicAdd(&g_stats[128 + c], q);
}

__global__ void finalize_stats(const float* __restrict__ gamma, const float* __restrict__ beta) {
    int c = threadIdx.x;
    float mean = g_stats[c] / (float)N_NODES;
    float var = g_stats[128 + c] / (float)N_NODES - mean * mean;
    float rstd = rsqrtf(var + 1e-5f);
    float sc = rstd * gamma[c];
    g_scale[c] = sc;
    g_shift[c] = beta[c] - mean * sc;
}

// ---------------- launch ----------------
extern "C" void kernel_launch(void* const* d_in, const int* in_sizes, int n_in,
                              void* d_out, int out_size) {
    const float* x      = (const float*)d_in[0];
    const void*  ei     = d_in[1];
    const float* W_ih   = (const float*)d_in[4];
    const float* W_hh   = (const float*)d_in[5];
    const float* b_ih   = (const float*)d_in[6];
    const float* b_hh   = (const float*)d_in[7];
    const float* W_rel  = (const float*)d_in[8];
    const float* b_rel  = (const float*)d_in[9];
    const float* W_root = (const float*)d_in[10];
    const float* gamma  = (const float*)d_in[11];
    const float* beta   = (const float*)d_in[12];
    const float* W1     = (const float*)d_in[13];
    const float* b1     = (const float*)d_in[14];
    const float* W2     = (const float*)d_in[15];
    const float* b2     = (const float*)d_in[16];
    const float* W_out  = (const float*)d_in[17];
    const float* b_out  = (const float*)d_in[18];

    float *hbuf, *gnn, *xT;
    __nv_bfloat16* h16;
    cudaGetSymbolAddress((void**)&hbuf, g_hbuf);
    cudaGetSymbolAddress((void**)&h16, g_h16);
    cudaGetSymbolAddress((void**)&gnn, g_gnn);
    cudaGetSymbolAddress((void**)&xT, g_xT);

    cudaFuncSetAttribute(gate_kernel, cudaFuncAttributeMaxDynamicSharedMemorySize, GATE_SMEM);
    cudaFuncSetAttribute(head1_kernel, cudaFuncAttributeMaxDynamicSharedMemorySize, H1_SMEM);
    cudaFuncSetAttribute(head2_kernel, cudaFuncAttributeMaxDynamicSharedMemorySize, H2_SMEM);

    const int scan_blocks = (N_NODES + 1023) / 1024;   // 98

    zero_state<<<512, 256>>>();
    detect_kernel<<<1, 256>>>((const unsigned int*)ei);
    prep_weights<<<256, 64>>>(W_ih, W_hh, b_ih, b_hh, W_rel, b_rel, W_root);
    prep_head<<<96, 256>>>(W1, W2, W_rel, W_root);
    transpose_x<<<N_NODES / 32, 256>>>(x);
    hist_zero<<<256, 256>>>();
    hist2_kernel<<<512, 256>>>(ei);
    scan1_kernel<<<scan_blocks, 1024>>>();
    scan2_kernel<<<1, 128>>>(scan_blocks);
    scan3_kernel<<<(N_NODES + 255) / 256, 256>>>();
    scatter_kernel<<<512, 256>>>(ei);

    dim3 ggrid((N_NODES + 127) / 128, 2);
    for (int t = 0; t < T_STEPS; t++) {
        const __nv_bfloat16* h16_in = h16 + (size_t)(t & 1) * N_NODES * 64;
        __nv_bfloat16* h16_out = h16 + (size_t)((t + 1) & 1) * N_NODES * 64;
        if (t > 0) agg_kernel<<<(N_NODES * 32 + 255) / 256, 256>>>(h16_in);
        gate_kernel<<<ggrid, 256, GATE_SMEM>>>(
            xT + (size_t)t * 20 * N_NODES, h16_in, hbuf, h16_out,
            t == 0 ? 1 : 0, t == T_STEPS - 1 ? 1 : 0);
    }
    // h16 buffer 1 = h at start of step 7 (used by gnn); hbuf = final h fp32.
    int n_tiles = (N_NODES + 127) / 128;   // 782
    head1_kernel<<<n_tiles, 256, H1_SMEM>>>(h16 + (size_t)N_NODES * 64, b_rel);
    stats_kernel<<<(N_NODES + 255) / 256, 256>>>(hbuf, gnn);
    finalize_stats<<<1, 128>>>(gamma, beta);
    head2_kernel<<<n_tiles, 256, H2_SMEM>>>(hbuf, b1, b2, W_out, b_out, (float*)d_out);
}

// round 8
// speedup vs baseline: 1.8819x; 1.5999x over previous
#include <cuda_runtime.h>
#include <cuda_bf16.h>
#include <math.h>
#include <cstdint>

#define N_NODES 100000
#define N_EDGES 1600000
#define T_STEPS 8

// ---------------- device scratch (no allocations allowed) ----------------
__device__ float g_hbuf[N_NODES * 64];                     // fp32 final h (t=7 only)
__device__ __nv_bfloat16 g_h16[2 * N_NODES * 64];          // bf16 h double buffer
__device__ float g_c[N_NODES * 64];
__device__ __nv_bfloat16 g_agg16[N_NODES * 64];
__device__ float g_gnn[N_NODES * 64];
__device__ float g_xT[T_STEPS * 20 * N_NODES];             // [t][j][n]
__device__ __align__(16) __nv_bfloat16 g_Wb[256 * 160];    // fused gate weights
__device__ __align__(16) __nv_bfloat16 g_W1b[64 * 128];
__device__ __align__(16) __nv_bfloat16 g_W2b[128 * 64];
__device__ __align__(16) __nv_bfloat16 g_Whb[64 * 128];    // [W_rel | W_root]
__device__ float g_bias[256];
__device__ float g_stats[256];
__device__ float g_scale[128];
__device__ float g_shift[128];
__device__ int   g_deg4[4 * N_NODES];
__device__ int   g_cur4[4 * N_NODES];
__device__ int   g_offs[N_NODES + 1];
__device__ int   g_ssrc[N_EDGES];
__device__ int   g_bsums[128];
__device__ int   g_boffs[128];
__device__ int   g_is64;

// ---------------- mma/ldmatrix helpers ----------------
__device__ __forceinline__ uint32_t smem_u32(const void* p) {
    uint32_t a;
    asm("{ .reg .u64 tmp; cvta.to.shared.u64 tmp, %1; cvt.u32.u64 %0, tmp; }"
        : "=r"(a) : "l"(p));
    return a;
}
__device__ __forceinline__ void ldsm_x4(uint32_t* r, uint32_t addr) {
    asm volatile("ldmatrix.sync.aligned.m8n8.x4.shared.b16 {%0,%1,%2,%3}, [%4];"
                 : "=r"(r[0]), "=r"(r[1]), "=r"(r[2]), "=r"(r[3]) : "r"(addr));
}
__device__ __forceinline__ void mma_bf16(float* d, const uint32_t* a,
                                         uint32_t b0, uint32_t b1) {
    asm volatile(
        "mma.sync.aligned.m16n8k16.row.col.f32.bf16.bf16.f32 "
        "{%0,%1,%2,%3}, {%4,%5,%6,%7}, {%8,%9}, {%0,%1,%2,%3};"
        : "+f"(d[0]), "+f"(d[1]), "+f"(d[2]), "+f"(d[3])
        : "r"(a[0]), "r"(a[1]), "r"(a[2]), "r"(a[3]), "r"(b0), "r"(b1));
}
__device__ __forceinline__ float fast_tanh(float x) {
    float y;
    asm("tanh.approx.f32 %0, %1;" : "=f"(y) : "f"(x));
    return y;
}
__device__ __forceinline__ float fast_sigmoid(float x) {
    return 0.5f * fast_tanh(0.5f * x) + 0.5f;
}

// ---------------- small utility kernels ----------------
__global__ void zero_state() {
    int stride = gridDim.x * blockDim.x;
    int i0 = blockIdx.x * blockDim.x + threadIdx.x;
    for (int k = i0; k < N_NODES * 64; k += stride) g_c[k] = 0.f;
    if (i0 < 256) g_stats[i0] = 0.f;
}

__global__ void detect_kernel(const unsigned int* __restrict__ w) {
    __shared__ unsigned int acc;
    if (threadIdx.x == 0) acc = 0u;
    __syncthreads();
    unsigned int v = 0u;
    for (int i = threadIdx.x; i < 2048; i += blockDim.x) v |= w[2 * i + 1];
    atomicOr(&acc, v);
    __syncthreads();
    if (threadIdx.x == 0) g_is64 = (acc == 0u) ? 1 : 0;
}

__device__ __forceinline__ int edge_val(const void* ei, long long idx) {
    if (g_is64) return (int)((const long long*)ei)[idx];
    return ((const int*)ei)[idx];
}

__global__ void hist_zero() {
    int stride = gridDim.x * blockDim.x;
    int i0 = blockIdx.x * blockDim.x + threadIdx.x;
    for (int k = i0; k < 4 * N_NODES; k += stride) g_deg4[k] = 0;
}

__global__ void hist2_kernel(const void* __restrict__ ei) {
    int stride = gridDim.x * blockDim.x;
    for (int e = blockIdx.x * blockDim.x + threadIdx.x; e < N_EDGES; e += stride) {
        int d = edge_val(ei, (long long)N_EDGES + e);
        atomicAdd(&g_deg4[(e & 3) * N_NODES + d], 1);
    }
}

__global__ void scan1_kernel() {
    __shared__ int warpsums[32];
    int tid = threadIdx.x, lane = tid & 31, wid = tid >> 5;
    int i = blockIdx.x * 1024 + tid;
    int v = 0;
    if (i < N_NODES)
        v = g_deg4[i] + g_deg4[N_NODES + i] + g_deg4[2 * N_NODES + i]
          + g_deg4[3 * N_NODES + i];
    int x = v;
    #pragma unroll
    for (int off = 1; off < 32; off <<= 1) {
        int y = __shfl_up_sync(0xFFFFFFFFu, x, off);
        if (lane >= off) x += y;
    }
    if (lane == 31) warpsums[wid] = x;
    __syncthreads();
    if (wid == 0) {
        int wv = warpsums[lane];
        #pragma unroll
        for (int off = 1; off < 32; off <<= 1) {
            int y = __shfl_up_sync(0xFFFFFFFFu, wv, off);
            if (lane >= off) wv += y;
        }
        warpsums[lane] = wv;
    }
    __syncthreads();
    int woff = (wid == 0) ? 0 : warpsums[wid - 1];
    if (i < N_NODES) g_offs[i] = x - v + woff;
    if (tid == 1023) g_bsums[blockIdx.x] = warpsums[31];
}

__global__ void scan2_kernel(int nblk) {
    __shared__ int warpsums[4];
    int tid = threadIdx.x, lane = tid & 31, wid = tid >> 5;
    int v = (tid < nblk) ? g_bsums[tid] : 0;
    int x = v;
    #pragma unroll
    for (int off = 1; off < 32; off <<= 1) {
        int y = __shfl_up_sync(0xFFFFFFFFu, x, off);
        if (lane >= off) x += y;
    }
    if (lane == 31) warpsums[wid] = x;
    __syncthreads();
    if (wid == 0 && lane < 4) {
        int wv = warpsums[lane];
        #pragma unroll
        for (int off = 1; off < 4; off <<= 1) {
            int y = __shfl_up_sync(0xFu, wv, off);
            if (lane >= off) wv += y;
        }
        warpsums[lane] = wv;
    }
    __syncthreads();
    int woff = (wid == 0) ? 0 : warpsums[wid - 1];
    int excl = x - v + woff;
    if (tid < nblk) g_boffs[tid] = excl;
    if (tid == nblk - 1) g_offs[N_NODES] = excl + v;
}

__global__ void scan3_kernel() {
    int i = blockIdx.x * blockDim.x + threadIdx.x;
    if (i >= N_NODES) return;
    int o = g_offs[i] + g_boffs[i >> 10];
    g_offs[i] = o;
    int d0 = g_deg4[i];
    int d1 = g_deg4[N_NODES + i];
    int d2 = g_deg4[2 * N_NODES + i];
    g_cur4[i] = o;
    g_cur4[N_NODES + i] = o + d0;
    g_cur4[2 * N_NODES + i] = o + d0 + d1;
    g_cur4[3 * N_NODES + i] = o + d0 + d1 + d2;
}

__global__ void scatter_kernel(const void* __restrict__ ei) {
    int stride = gridDim.x * blockDim.x;
    for (int e = blockIdx.x * blockDim.x + threadIdx.x; e < N_EDGES; e += stride) {
        int s = edge_val(ei, e);
        int d = edge_val(ei, (long long)N_EDGES + e);
        int p = atomicAdd(&g_cur4[(e & 3) * N_NODES + d], 1);
        g_ssrc[p] = s;
    }
}

// x (N, 30, 8) -> g_xT[t][j][n]; only temporal slice read.
__global__ void __launch_bounds__(256) transpose_x(const float* __restrict__ x) {
    __shared__ float sm[32 * 161];
    int n0 = blockIdx.x * 32;
    #pragma unroll
    for (int w = 0; w < 20; w++) {
        int i = threadIdx.x + w * 256;
        int nl = i / 160, off = i - nl * 160;
        sm[nl * 161 + off] = x[(size_t)(n0 + nl) * 240 + 80 + off];
    }
    __syncthreads();
    #pragma unroll
    for (int w = 0; w < 20; w++) {
        int idx = threadIdx.x + w * 256;
        int nl = idx & 31;
        int p = idx >> 5;
        int t = p / 20, j = p - t * 20;
        g_xT[((size_t)t * 20 + j) * N_NODES + n0 + nl] = sm[nl * 161 + j * 8 + t];
    }
}

// Fold GNN projection into gate weights, permute rows to (i,f,g,o) quads, emit bf16.
__global__ void prep_weights(const float* __restrict__ W_ih, const float* __restrict__ W_hh,
                             const float* __restrict__ b_ih, const float* __restrict__ b_hh,
                             const float* __restrict__ W_rel, const float* __restrict__ b_rel,
                             const float* __restrict__ W_root) {
    int rp = blockIdx.x;
    int u = rp >> 2, q = rp & 3;
    int r = q * 64 + u;
    __shared__ float wg[64];
    int tid = threadIdx.x;  // 64 threads
    wg[tid] = W_ih[r * 84 + 20 + tid];
    __syncthreads();
    int c = tid;
    float m1 = 0.f, m2 = 0.f;
    #pragma unroll 8
    for (int j = 0; j < 64; j++) {
        float w = wg[j];
        m1 += w * W_rel[j * 64 + c];
        m2 += w * W_root[j * 64 + c];
    }
    m2 += W_hh[r * 64 + c];
    g_Wb[rp * 160 + 20 + c] = __float2bfloat16_rn(m1);
    g_Wb[rp * 160 + 84 + c] = __float2bfloat16_rn(m2);
    if (c < 20) g_Wb[rp * 160 + c] = __float2bfloat16_rn(W_ih[r * 84 + c]);
    if (c < 12) g_Wb[rp * 160 + 148 + c] = __float2bfloat16_rn(0.f);
    if (c == 0) {
        float s = b_ih[r] + b_hh[r];
        for (int j = 0; j < 64; j++) s += wg[j] * b_rel[j];
        g_bias[rp] = s;
    }
}

// bf16 copies of head weights.
__global__ void prep_head(const float* __restrict__ W1, const float* __restrict__ W2,
                          const float* __restrict__ W_rel, const float* __restrict__ W_root) {
    int i = blockIdx.x * 256 + threadIdx.x;
    if (i < 8192) {
        g_W1b[i] = __float2bfloat16_rn(W1[i]);
    } else if (i < 16384) {
        g_W2b[i - 8192] = __float2bfloat16_rn(W2[i - 8192]);
    } else if (i < 24576) {
        int j = i - 16384;
        int o = j >> 7, k = j & 127;
        float v = (k < 64) ? W_rel[o * 64 + k] : W_root[o * 64 + k - 64];
        g_Whb[j] = __float2bfloat16_rn(v);
    }
}

// ---------------- aggregation: warp per dst node, bf16 gather ----------------
__global__ void agg_kernel(const __nv_bfloat16* __restrict__ h16) {
    int gw = (blockIdx.x * blockDim.x + threadIdx.x) >> 5;
    int lane = threadIdx.x & 31;
    if (gw >= N_NODES) return;
    int beg = g_offs[gw], end = g_offs[gw + 1];
    float2 acc = make_float2(0.f, 0.f);
    int e = beg;
    for (; e + 4 <= end; e += 4) {
        int s0 = g_ssrc[e], s1 = g_ssrc[e + 1], s2 = g_ssrc[e + 2], s3 = g_ssrc[e + 3];
        float2 v0 = __bfloat1622float2(
            *reinterpret_cast<const __nv_bfloat162*>(h16 + (size_t)s0 * 64 + lane * 2));
        float2 v1 = __bfloat1622float2(
            *reinterpret_cast<const __nv_bfloat162*>(h16 + (size_t)s1 * 64 + lane * 2));
        float2 v2 = __bfloat1622float2(
            *reinterpret_cast<const __nv_bfloat162*>(h16 + (size_t)s2 * 64 + lane * 2));
        float2 v3 = __bfloat1622float2(
            *reinterpret_cast<const __nv_bfloat162*>(h16 + (size_t)s3 * 64 + lane * 2));
        acc.x += (v0.x + v1.x) + (v2.x + v3.x);
        acc.y += (v0.y + v1.y) + (v2.y + v3.y);
    }
    for (; e < end; e++) {
        int s = g_ssrc[e];
        float2 v = __bfloat1622float2(
            *reinterpret_cast<const __nv_bfloat162*>(h16 + (size_t)s * 64 + lane * 2));
        acc.x += v.x;
        acc.y += v.y;
    }
    *reinterpret_cast<__nv_bfloat162*>(g_agg16 + (size_t)gw * 64 + lane * 2) =
        __float22bfloat162_rn(acc);
}

// ---------------- bf16 mma.sync gate GEMM + fused LSTM epilogue ----------------
#define GATE_SMEM 86016   // 2 * 128 * 336

__global__ void __launch_bounds__(256, 2)
gate_kernel(const float* __restrict__ xTt, const __nv_bfloat16* __restrict__ h16_in,
            float* __restrict__ h_out, __nv_bfloat16* __restrict__ h16_out,
            int t0, int wf32) {
    extern __shared__ char smem[];
    const int tid = threadIdx.x;
    const int wid = tid >> 5;
    const int lane = tid & 31;
    const int n0 = blockIdx.x * 128;
    const int col0 = blockIdx.y * 128;
    const int ubase = col0 >> 2;

    {
        const uint4* Wb4 = reinterpret_cast<const uint4*>(g_Wb + (size_t)col0 * 160);
        #pragma unroll
        for (int it = 0; it < 10; it++) {
            int idx = tid + it * 256;
            int r = idx / 20;
            int c = idx - r * 20;
            *reinterpret_cast<uint4*>(smem + 43008 + r * 336 + c * 16) = Wb4[idx];
        }
    }
    #pragma unroll
    for (int it = 0; it < 10; it++) {
        int idx = tid + it * 256;
        int j = idx >> 7;
        int nl = idx & 127;
        int n = n0 + nl;
        float v = (n < N_NODES) ? xTt[(size_t)j * N_NODES + n] : 0.f;
        *reinterpret_cast<__nv_bfloat16*>(smem + nl * 336 + j * 2) = __float2bfloat16_rn(v);
    }
    #pragma unroll
    for (int it = 0; it < 8; it++) {
        int idx = tid + it * 256;
        int nl = idx >> 4;
        int cp = idx & 15;
        int n = n0 + nl;
        uint2 va = make_uint2(0u, 0u), vh = make_uint2(0u, 0u);
        if (!t0 && n < N_NODES) {
            va = *reinterpret_cast<const uint2*>(g_agg16 + (size_t)n * 64 + cp * 4);
            vh = *reinterpret_cast<const uint2*>(h16_in + (size_t)n * 64 + cp * 4);
        }
        *reinterpret_cast<uint2*>(smem + nl * 336 + 40 + cp * 8) = va;
        *reinterpret_cast<uint2*>(smem + nl * 336 + 168 + cp * 8) = vh;
    }
    #pragma unroll
    for (int it = 0; it < 3; it++) {
        int idx = tid + it * 256;
        if (idx < 640) {
            int nl = idx / 5;
            int p = idx - nl * 5;
            *reinterpret_cast<uint2*>(smem + nl * 336 + 296 + p * 8) = make_uint2(0u, 0u);
        }
    }
    __syncthreads();

    const int mw = wid >> 1;
    const int nw = wid & 1;
    const int mr = mw * 32;
    const int nc = nw * 64;
    const uint32_t sbase = smem_u32(smem);
    uint32_t aAddr = sbase + (mr + (lane & 15)) * 336 + ((lane >> 4) << 4);
    uint32_t bAddr = sbase + 43008u + (nc + (lane & 15)) * 336 + ((lane >> 4) << 4);

    float acc[2][8][4];
    #pragma unroll
    for (int mi = 0; mi < 2; mi++)
        #pragma unroll
        for (int nj = 0; nj < 8; nj++)
            #pragma unroll
            for (int e = 0; e < 4; e++) acc[mi][nj][e] = 0.f;

    #pragma unroll
    for (int ks = 0; ks < 10; ks++) {
        uint32_t a[2][4];
        ldsm_x4(a[0], aAddr + ks * 32);
        ldsm_x4(a[1], aAddr + 16 * 336 + ks * 32);
        uint32_t b[4][4];
        #pragma unroll
        for (int nj = 0; nj < 4; nj++)
            ldsm_x4(b[nj], bAddr + nj * 16 * 336 + ks * 32);
        #pragma unroll
        for (int mi = 0; mi < 2; mi++)
            #pragma unroll
            for (int nj2 = 0; nj2 < 8; nj2++) {
                int nj = nj2 >> 1, hi = nj2 & 1;
                mma_bf16(acc[mi][nj2], a[mi], b[nj][hi], b[nj][hi + 2]);
            }
    }
    __syncthreads();

    float* Cs = reinterpret_cast<float*>(smem);
    float* Hs = Cs + 128 * 33;
    float* sbias = Hs + 128 * 33;
    #pragma unroll
    for (int it = 0; it < 16; it++) {
        int idx = tid + it * 256;
        int rr = idx >> 5;
        int u = idx & 31;
        int n = n0 + rr;
        Cs[rr * 33 + u] = (n < N_NODES) ? g_c[(size_t)n * 64 + ubase + u] : 0.f;
    }
    if (tid < 128) sbias[tid] = g_bias[col0 + tid];
    __syncthreads();

    #pragma unroll
    for (int mi = 0; mi < 2; mi++) {
        int row = mr + mi * 16 + (lane >> 2) + ((lane & 1) << 3);
        #pragma unroll
        for (int nj2 = 0; nj2 < 8; nj2++) {
            float d0 = acc[mi][nj2][0], d1 = acc[mi][nj2][1];
            float d2 = acc[mi][nj2][2], d3 = acc[mi][nj2][3];
            float xd0 = __shfl_xor_sync(0xFFFFFFFFu, d0, 1);
            float xd1 = __shfl_xor_sync(0xFFFFFFFFu, d1, 1);
            float xd2 = __shfl_xor_sync(0xFFFFFFFFu, d2, 1);
            float xd3 = __shfl_xor_sync(0xFFFFFFFFu, d3, 1);
            float ig, fg, gg, og;
            if (lane & 1) { ig = xd2; fg = xd3; gg = d2; og = d3; }
            else          { ig = d0;  fg = d1;  gg = xd0; og = xd1; }
            int qb = nc + nj2 * 8 + ((lane & 2) << 1);
            ig += sbias[qb];
            fg += sbias[qb + 1];
            gg += sbias[qb + 2];
            og += sbias[qb + 3];
            float si = fast_sigmoid(ig);
            float sf = fast_sigmoid(fg);
            float so = fast_sigmoid(og);
            float tg = fast_tanh(gg);
            int u = qb >> 2;
            float cold = Cs[row * 33 + u];
            float cn = sf * cold + si * tg;
            Cs[row * 33 + u] = cn;
            float tcn = fast_tanh(cn);
            Hs[row * 33 + u] = so * tcn;
        }
    }
    __syncthreads();

    #pragma unroll
    for (int it = 0; it < 16; it++) {
        int idx = tid + it * 256;
        int rr = idx >> 5;
        int u = idx & 31;
        int n = n0 + rr;
        if (n < N_NODES) {
            size_t o = (size_t)n * 64 + ubase + u;
            float cn = Cs[rr * 33 + u];
            float hv = Hs[rr * 33 + u];
            g_c[o] = cn;
            h16_out[o] = __float2bfloat16_rn(hv);
            if (wf32) h_out[o] = hv;
        }
    }
}

// ---------------- head1: gnn = [agg|h] @ [W_rel|W_root]^T + b_rel (mma) ------
#define H1_SMEM 52480

__global__ void __launch_bounds__(256)
head1_kernel(const __nv_bfloat16* __restrict__ h16in, const float* __restrict__ b_rel) {
    extern __shared__ char smem[];
    const int tid = threadIdx.x;
    const int wid = tid >> 5;
    const int lane = tid & 31;
    const int n0 = blockIdx.x * 128;
    float* sb = reinterpret_cast<float*>(smem + 52224);

    {
        const uint4* Wh4 = reinterpret_cast<const uint4*>(g_Whb);
        #pragma unroll
        for (int it = 0; it < 4; it++) {
            int idx = tid + it * 256;
            int r = idx >> 4, c16 = idx & 15;
            *reinterpret_cast<uint4*>(smem + 34816 + r * 272 + c16 * 16) = Wh4[idx];
        }
    }
    #pragma unroll
    for (int it = 0; it < 8; it++) {
        int idx = tid + it * 256;
        int nl = idx >> 4, q = idx & 15;
        int n = n0 + nl;
        uint4 v = make_uint4(0u, 0u, 0u, 0u);
        if (n < N_NODES) {
            if (q < 8) v = reinterpret_cast<const uint4*>(g_agg16 + (size_t)n * 64)[q];
            else       v = reinterpret_cast<const uint4*>(h16in + (size_t)n * 64)[q - 8];
        }
        *reinterpret_cast<uint4*>(smem + nl * 272 + q * 16) = v;
    }
    if (tid < 128)
        *reinterpret_cast<uint4*>(smem + tid * 272 + 256) = make_uint4(0u, 0u, 0u, 0u);
    if (tid < 64) sb[tid] = b_rel[tid];
    __syncthreads();

    const int mw = wid >> 1;
    const int nw = wid & 1;
    const int mr = mw * 32;
    const int nc = nw * 32;
    const uint32_t sbase = smem_u32(smem);
    uint32_t aAddr = sbase + (mr + (lane & 15)) * 272 + ((lane >> 4) << 4);
    uint32_t bAddr = sbase + 34816u + (nc + (lane & 15)) * 272 + ((lane >> 4) << 4);

    float acc[2][4][4];
    #pragma unroll
    for (int mi = 0; mi < 2; mi++)
        #pragma unroll
        for (int nj = 0; nj < 4; nj++)
            #pragma unroll
            for (int e = 0; e < 4; e++) acc[mi][nj][e] = 0.f;

    #pragma unroll
    for (int ks = 0; ks < 8; ks++) {
        uint32_t a[2][4];
        ldsm_x4(a[0], aAddr + ks * 32);
        ldsm_x4(a[1], aAddr + 16 * 272 + ks * 32);
        uint32_t b[2][4];
        ldsm_x4(b[0], bAddr + ks * 32);
        ldsm_x4(b[1], bAddr + 16 * 272 + ks * 32);
        #pragma unroll
        for (int mi = 0; mi < 2; mi++)
            #pragma unroll
            for (int nj2 = 0; nj2 < 4; nj2++) {
                int nj = nj2 >> 1, hi = nj2 & 1;
                mma_bf16(acc[mi][nj2], a[mi], b[nj][hi], b[nj][hi + 2]);
            }
    }
    __syncthreads();

    float* Gs = reinterpret_cast<float*>(smem);
    #pragma unroll
    for (int mi = 0; mi < 2; mi++) {
        int row = mr + mi * 16 + (lane >> 2);
        #pragma unroll
        for (int nj2 = 0; nj2 < 4; nj2++) {
            int c = nc + nj2 * 8 + (lane & 3) * 2;
            *reinterpret_cast<float2*>(&Gs[row * 68 + c]) =
                make_float2(acc[mi][nj2][0] + sb[c], acc[mi][nj2][1] + sb[c + 1]);
            *reinterpret_cast<float2*>(&Gs[(row + 8) * 68 + c]) =
                make_float2(acc[mi][nj2][2] + sb[c], acc[mi][nj2][3] + sb[c + 1]);
        }
    }
    __syncthreads();

    #pragma unroll
    for (int it = 0; it < 32; it++) {
        int idx = tid + it * 256;
        int rr = idx >> 6, u = idx & 63;
        int n = n0 + rr;
        if (n < N_NODES) g_gnn[(size_t)n * 64 + u] = Gs[rr * 68 + u];
    }
}

// ---------------- head2: fused layernorm + MLP + out-projection (mma) --------
#define H2_SMEM 90880

__global__ void __launch_bounds__(256)
head2_kernel(const float* __restrict__ hfin, const float* __restrict__ b1,
             const float* __restrict__ b2, const float* __restrict__ Wout,
             const float* __restrict__ bout, float* __restrict__ out) {
    extern __shared__ char smem[];
    const int tid = threadIdx.x;
    const int wid = tid >> 5;
    const int lane = tid & 31;
    const int n0 = blockIdx.x * 128;
    float* sb1 = reinterpret_cast<float*>(smem + 89088);
    float* sb2 = reinterpret_cast<float*>(smem + 89344);
    float* sWout = reinterpret_cast<float*>(smem + 89856);
    float* sdot = reinterpret_cast<float*>(smem + 90368);

    #pragma unroll
    for (int it = 0; it < 32; it++) {
        int idx = tid + it * 256;
        int nl = idx >> 6, cp = idx & 63;
        int c = cp * 2;
        int n = n0 + nl;
        float2 v = make_float2(0.f, 0.f);
        if (n < N_NODES) {
            v = (cp < 32)
                ? reinterpret_cast<const float2*>(hfin)[(size_t)n * 32 + cp]
                : reinterpret_cast<const float2*>(g_gnn)[(size_t)n * 32 + cp - 32];
        }
        float2 nv = make_float2(v.x * g_scale[c] + g_shift[c],
                                v.y * g_scale[c + 1] + g_shift[c + 1]);
        *reinterpret_cast<__nv_bfloat162*>(smem + nl * 272 + c * 2) =
            __float22bfloat162_rn(nv);
    }
    if (tid < 128)
        *reinterpret_cast<uint4*>(smem + tid * 272 + 256) = make_uint4(0u, 0u, 0u, 0u);
    {
        const uint4* W14 = reinterpret_cast<const uint4*>(g_W1b);
        #pragma unroll
        for (int it = 0; it < 4; it++) {
            int idx = tid + it * 256;
            int r = idx >> 4, c16 = idx & 15;
            *reinterpret_cast<uint4*>(smem + 34816 + r * 272 + c16 * 16) = W14[idx];
        }
        const uint4* W24 = reinterpret_cast<const uint4*>(g_W2b);
        #pragma unroll
        for (int it = 0; it < 4; it++) {
            int idx = tid + it * 256;
            int r = idx >> 3, c8 = idx & 7;
            *reinterpret_cast<uint4*>(smem + 70656 + r * 144 + c8 * 16) = W24[idx];
        }
    }
    if (tid < 64) sb1[tid] = b1[tid];
    if (tid < 128) {
        sb2[tid] = b2[tid];
        sWout[tid] = Wout[tid];
        sdot[tid] = 0.f;
    }
    __syncthreads();

    const int mw = wid >> 1;
    const int nw = wid & 1;
    const int mr = mw * 32;
    const uint32_t sbase = smem_u32(smem);

    {
        const int nc = nw * 32;
        uint32_t aAddr = sbase + (mr + (lane & 15)) * 272 + ((lane >> 4) << 4);
        uint32_t bAddr = sbase + 34816u + (nc + (lane & 15)) * 272 + ((lane >> 4) << 4);
        float acc1[2][4][4];
        #pragma unroll
        for (int mi = 0; mi < 2; mi++)
            #pragma unroll
            for (int nj = 0; nj < 4; nj++)
                #pragma unroll
                for (int e = 0; e < 4; e++) acc1[mi][nj][e] = 0.f;
        #pragma unroll
        for (int ks = 0; ks < 8; ks++) {
            uint32_t a[2][4];
            ldsm_x4(a[0], aAddr + ks * 32);
            ldsm_x4(a[1], aAddr + 16 * 272 + ks * 32);
            uint32_t b[2][4];
            ldsm_x4(b[0], bAddr + ks * 32);
            ldsm_x4(b[1], bAddr + 16 * 272 + ks * 32);
            #pragma unroll
            for (int mi = 0; mi < 2; mi++)
                #pragma unroll
                for (int nj2 = 0; nj2 < 4; nj2++) {
                    int nj = nj2 >> 1, hi = nj2 & 1;
                    mma_bf16(acc1[mi][nj2], a[mi], b[nj][hi], b[nj][hi + 2]);
                }
        }
        #pragma unroll
        for (int mi = 0; mi < 2; mi++) {
            int row = mr + mi * 16 + (lane >> 2);
            #pragma unroll
            for (int nj2 = 0; nj2 < 4; nj2++) {
                int c = nc + nj2 * 8 + (lane & 3) * 2;
                float v0 = fmaxf(acc1[mi][nj2][0] + sb1[c], 0.f);
                float v1 = fmaxf(acc1[mi][nj2][1] + sb1[c + 1], 0.f);
                float v2 = fmaxf(acc1[mi][nj2][2] + sb1[c], 0.f);
                float v3 = fmaxf(acc1[mi][nj2][3] + sb1[c + 1], 0.f);
                *reinterpret_cast<__nv_bfloat162*>(smem + 52224 + row * 144 + c * 2) =
                    __float22bfloat162_rn(make_float2(v0, v1));
                *reinterpret_cast<__nv_bfloat162*>(smem + 52224 + (row + 8) * 144 + c * 2) =
                    __float22bfloat162_rn(make_float2(v2, v3));
            }
        }
    }
    __syncthreads();

    {
        const int nc = nw * 64;
        uint32_t aAddr = sbase + 52224u + (mr + (lane & 15)) * 144 + ((lane >> 4) << 4);
        uint32_t bAddr = sbase + 70656u + (nc + (lane & 15)) * 144 + ((lane >> 4) << 4);
        float acc2[2][8][4];
        #pragma unroll
        for (int mi = 0; mi < 2; mi++)
            #pragma unroll
            for (int nj = 0; nj < 8; nj++)
                #pragma unroll
                for (int e = 0; e < 4; e++) acc2[mi][nj][e] = 0.f;
        #pragma unroll
        for (int ks = 0; ks < 4; ks++) {
            uint32_t a[2][4];
            ldsm_x4(a[0], aAddr + ks * 32);
            ldsm_x4(a[1], aAddr + 16 * 144 + ks * 32);
            uint32_t b[4][4];
            #pragma unroll
            for (int nj = 0; nj < 4; nj++)
                ldsm_x4(b[nj], bAddr + nj * 16 * 144 + ks * 32);
            #pragma unroll
            for (int mi = 0; mi < 2; mi++)
                #pragma unroll
                for (int nj2 = 0; nj2 < 8; nj2++) {
                    int nj = nj2 >> 1, hi = nj2 & 1;
                    mma_bf16(acc2[mi][nj2], a[mi], b[nj][hi], b[nj][hi + 2]);
                }
        }
        #pragma unroll
        for (int mi = 0; mi < 2; mi++) {
            float p0 = 0.f, p1 = 0.f;
            #pragma unroll
            for (int nj2 = 0; nj2 < 8; nj2++) {
                int c = nc + nj2 * 8 + (lane & 3) * 2;
                float w0 = sWout[c], w1 = sWout[c + 1];
                p0 += fmaxf(acc2[mi][nj2][0] + sb2[c], 0.f) * w0
                    + fmaxf(acc2[mi][nj2][1] + sb2[c + 1], 0.f) * w1;
                p1 += fmaxf(acc2[mi][nj2][2] + sb2[c], 0.f) * w0
                    + fmaxf(acc2[mi][nj2][3] + sb2[c + 1], 0.f) * w1;
            }
            p0 += __shfl_xor_sync(0xFFFFFFFFu, p0, 1);
            p0 += __shfl_xor_sync(0xFFFFFFFFu, p0, 2);
            p1 += __shfl_xor_sync(0xFFFFFFFFu, p1, 1);
            p1 += __shfl_xor_sync(0xFFFFFFFFu, p1, 2);
            if ((lane & 3) == 0) {
                int row = mr + mi * 16 + (lane >> 2);
                atomicAdd(&sdot[row], p0);
                atomicAdd(&sdot[row + 8], p1);
            }
        }
    }
    __syncthreads();

    if (tid < 128) {
        int n = n0 + tid;
        if (n < N_NODES) {
            float s = sdot[tid] + bout[0];
            out[n] = 1.f / (1.f + __expf(-s));
        }
    }
}

// ---------------- per-feature stats over nodes ----------------
__global__ void stats_kernel(const float* __restrict__ h, const float* __restrict__ gnn) {
    int c = threadIdx.x & 127;
    int grp = threadIdx.x >> 7;
    int r0 = blockIdx.x * 256;
    int rend = min(r0 + 256, N_NODES);
    float s = 0.f, q = 0.f;
    for (int r = r0 + grp; r < rend; r += 2) {
        float v = (c < 64) ? h[(size_t)r * 64 + c] : gnn[(size_t)r * 64 + c - 64];
        s += v;
        q += v * v;
    }
    atomicAdd(&g_stats[c], s);
    atomicAdd(&g_stats[128 + c], q);
}

__global__ void finalize_stats(const float* __restrict__ gamma, const float* __restrict__ beta) {
    int c = threadIdx.x;
    float mean = g_stats[c] / (float)N_NODES;
    float var = g_stats[128 + c] / (float)N_NODES - mean * mean;
    float rstd = rsqrtf(var + 1e-5f);
    float sc = rstd * gamma[c];
    g_scale[c] = sc;
    g_shift[c] = beta[c] - mean * sc;
}

// ---------------- launch ----------------
extern "C" void kernel_launch(void* const* d_in, const int* in_sizes, int n_in,
                              void* d_out, int out_size) {
    const float* x      = (const float*)d_in[0];
    const void*  ei     = d_in[1];
    const float* W_ih   = (const float*)d_in[4];
    const float* W_hh   = (const float*)d_in[5];
    const float* b_ih   = (const float*)d_in[6];
    const float* b_hh   = (const float*)d_in[7];
    const float* W_rel  = (const float*)d_in[8];
    const float* b_rel  = (const float*)d_in[9];
    const float* W_root = (const float*)d_in[10];
    const float* gamma  = (const float*)d_in[11];
    const float* beta   = (const float*)d_in[12];
    const float* W1     = (const float*)d_in[13];
    const float* b1     = (const float*)d_in[14];
    const float* W2     = (const float*)d_in[15];
    const float* b2     = (const float*)d_in[16];
    const float* W_out  = (const float*)d_in[17];
    const float* b_out  = (const float*)d_in[18];

    float *hbuf, *gnn, *xT;
    __nv_bfloat16* h16;
    cudaGetSymbolAddress((void**)&hbuf, g_hbuf);
    cudaGetSymbolAddress((void**)&h16, g_h16);
    cudaGetSymbolAddress((void**)&gnn, g_gnn);
    cudaGetSymbolAddress((void**)&xT, g_xT);

    cudaFuncSetAttribute(gate_kernel, cudaFuncAttributeMaxDynamicSharedMemorySize, GATE_SMEM);
    cudaFuncSetAttribute(head1_kernel, cudaFuncAttributeMaxDynamicSharedMemorySize, H1_SMEM);
    cudaFuncSetAttribute(head2_kernel, cudaFuncAttributeMaxDynamicSharedMemorySize, H2_SMEM);

    const int scan_blocks = (N_NODES + 1023) / 1024;   // 98
    dim3 ggrid((N_NODES + 127) / 128, 2);

    // t=0 gate only needs zero_state + prep_weights + transpose_x.
    // (gate_kernel is launch #4 so the fixed ncu window profiles it.)
    zero_state<<<512, 256>>>();
    prep_weights<<<256, 64>>>(W_ih, W_hh, b_ih, b_hh, W_rel, b_rel, W_root);
    transpose_x<<<N_NODES / 32, 256>>>(x);
    gate_kernel<<<ggrid, 256, GATE_SMEM>>>(xT, h16, hbuf, h16 + (size_t)N_NODES * 64, 1, 0);

    detect_kernel<<<1, 256>>>((const unsigned int*)ei);
    prep_head<<<96, 256>>>(W1, W2, W_rel, W_root);
    hist_zero<<<256, 256>>>();
    hist2_kernel<<<512, 256>>>(ei);
    scan1_kernel<<<scan_blocks, 1024>>>();
    scan2_kernel<<<1, 128>>>(scan_blocks);
    scan3_kernel<<<(N_NODES + 255) / 256, 256>>>();
    scatter_kernel<<<512, 256>>>(ei);

    for (int t = 1; t < T_STEPS; t++) {
        const __nv_bfloat16* h16_in = h16 + (size_t)(t & 1) * N_NODES * 64;
        __nv_bfloat16* h16_out = h16 + (size_t)((t + 1) & 1) * N_NODES * 64;
        agg_kernel<<<(N_NODES * 32 + 255) / 256, 256>>>(h16_in);
        gate_kernel<<<ggrid, 256, GATE_SMEM>>>(
            xT + (size_t)t * 20 * N_NODES, h16_in, hbuf, h16_out,
            0, t == T_STEPS - 1 ? 1 : 0);
    }
    // h16 buffer 1 = h at start of step 7 (used by gnn); hbuf = final h fp32.
    int n_tiles = (N_NODES + 127) / 128;   // 782
    head1_kernel<<<n_tiles, 256, H1_SMEM>>>(h16 + (size_t)N_NODES * 64, b_rel);
    stats_kernel<<<(N_NODES + 255) / 256, 256>>>(hbuf, gnn);
    finalize_stats<<<1, 128>>>(gamma, beta);
    head2_kernel<<<n_tiles, 256, H2_SMEM>>>(hbuf, b1, b2, W_out, b_out, (float*)d_out);
}

// round 9
// speedup vs baseline: 1.9449x; 1.0335x over previous
#include <cuda_runtime.h>
#include <cuda_bf16.h>
#include <math.h>
#include <cstdint>

#define N_NODES 100000
#define N_EDGES 1600000
#define T_STEPS 8

// ---------------- device scratch (no allocations allowed) ----------------
__device__ float g_hbuf[N_NODES * 64];                     // fp32 final h (t=7 only)
__device__ __nv_bfloat16 g_h16[2 * N_NODES * 64];          // bf16 h double buffer
__device__ float g_c[N_NODES * 64];
__device__ __nv_bfloat16 g_agg16[N_NODES * 64];
__device__ float g_gnn[N_NODES * 64];
__device__ __align__(16) __nv_bfloat16 g_xT16[T_STEPS * N_NODES * 20];  // [t][n][20]
__device__ __align__(16) __nv_bfloat16 g_Wb[256 * 160];    // fused gate weights
__device__ __align__(16) __nv_bfloat16 g_W1b[64 * 128];
__device__ __align__(16) __nv_bfloat16 g_W2b[128 * 64];
__device__ __align__(16) __nv_bfloat16 g_Whb[64 * 128];    // [W_rel | W_root]
__device__ float g_bias[256];
__device__ float g_stats[256];
__device__ float g_scale[128];
__device__ float g_shift[128];
__device__ int   g_deg4[4 * N_NODES];
__device__ int   g_cur4[4 * N_NODES];
__device__ int   g_offs[N_NODES + 1];
__device__ int   g_ssrc[N_EDGES];
__device__ int   g_bsums[128];
__device__ int   g_boffs[128];
__device__ int   g_is64;

// ---------------- mma/ldmatrix helpers ----------------
__device__ __forceinline__ uint32_t smem_u32(const void* p) {
    uint32_t a;
    asm("{ .reg .u64 tmp; cvta.to.shared.u64 tmp, %1; cvt.u32.u64 %0, tmp; }"
        : "=r"(a) : "l"(p));
    return a;
}
__device__ __forceinline__ void ldsm_x4(uint32_t* r, uint32_t addr) {
    asm volatile("ldmatrix.sync.aligned.m8n8.x4.shared.b16 {%0,%1,%2,%3}, [%4];"
                 : "=r"(r[0]), "=r"(r[1]), "=r"(r[2]), "=r"(r[3]) : "r"(addr));
}
__device__ __forceinline__ void mma_bf16(float* d, const uint32_t* a,
                                         uint32_t b0, uint32_t b1) {
    asm volatile(
        "mma.sync.aligned.m16n8k16.row.col.f32.bf16.bf16.f32 "
        "{%0,%1,%2,%3}, {%4,%5,%6,%7}, {%8,%9}, {%0,%1,%2,%3};"
        : "+f"(d[0]), "+f"(d[1]), "+f"(d[2]), "+f"(d[3])
        : "r"(a[0]), "r"(a[1]), "r"(a[2]), "r"(a[3]), "r"(b0), "r"(b1));
}
__device__ __forceinline__ float fast_tanh(float x) {
    float y;
    asm("tanh.approx.f32 %0, %1;" : "=f"(y) : "f"(x));
    return y;
}
__device__ __forceinline__ float fast_sigmoid(float x) {
    return 0.5f * fast_tanh(0.5f * x) + 0.5f;
}

// ---------------- small utility kernels ----------------
__global__ void zero_state() {
    int stride = gridDim.x * blockDim.x;
    int i0 = blockIdx.x * blockDim.x + threadIdx.x;
    for (int k = i0; k < N_NODES * 64; k += stride) g_c[k] = 0.f;
    if (i0 < 256) g_stats[i0] = 0.f;
}

__global__ void detect_kernel(const unsigned int* __restrict__ w) {
    __shared__ unsigned int acc;
    if (threadIdx.x == 0) acc = 0u;
    __syncthreads();
    unsigned int v = 0u;
    for (int i = threadIdx.x; i < 2048; i += blockDim.x) v |= w[2 * i + 1];
    atomicOr(&acc, v);
    __syncthreads();
    if (threadIdx.x == 0) g_is64 = (acc == 0u) ? 1 : 0;
}

__device__ __forceinline__ int edge_val(const void* ei, long long idx) {
    if (g_is64) return (int)((const long long*)ei)[idx];
    return ((const int*)ei)[idx];
}

__global__ void hist_zero() {
    int stride = gridDim.x * blockDim.x;
    int i0 = blockIdx.x * blockDim.x + threadIdx.x;
    for (int k = i0; k < 4 * N_NODES; k += stride) g_deg4[k] = 0;
}

__global__ void hist2_kernel(const void* __restrict__ ei) {
    int stride = gridDim.x * blockDim.x;
    for (int e = blockIdx.x * blockDim.x + threadIdx.x; e < N_EDGES; e += stride) {
        int d = edge_val(ei, (long long)N_EDGES + e);
        atomicAdd(&g_deg4[(e & 3) * N_NODES + d], 1);
    }
}

__global__ void scan1_kernel() {
    __shared__ int warpsums[32];
    int tid = threadIdx.x, lane = tid & 31, wid = tid >> 5;
    int i = blockIdx.x * 1024 + tid;
    int v = 0;
    if (i < N_NODES)
        v = g_deg4[i] + g_deg4[N_NODES + i] + g_deg4[2 * N_NODES + i]
          + g_deg4[3 * N_NODES + i];
    int x = v;
    #pragma unroll
    for (int off = 1; off < 32; off <<= 1) {
        int y = __shfl_up_sync(0xFFFFFFFFu, x, off);
        if (lane >= off) x += y;
    }
    if (lane == 31) warpsums[wid] = x;
    __syncthreads();
    if (wid == 0) {
        int wv = warpsums[lane];
        #pragma unroll
        for (int off = 1; off < 32; off <<= 1) {
            int y = __shfl_up_sync(0xFFFFFFFFu, wv, off);
            if (lane >= off) wv += y;
        }
        warpsums[lane] = wv;
    }
    __syncthreads();
    int woff = (wid == 0) ? 0 : warpsums[wid - 1];
    if (i < N_NODES) g_offs[i] = x - v + woff;
    if (tid == 1023) g_bsums[blockIdx.x] = warpsums[31];
}

__global__ void scan2_kernel(int nblk) {
    __shared__ int warpsums[4];
    int tid = threadIdx.x, lane = tid & 31, wid = tid >> 5;
    int v = (tid < nblk) ? g_bsums[tid] : 0;
    int x = v;
    #pragma unroll
    for (int off = 1; off < 32; off <<= 1) {
        int y = __shfl_up_sync(0xFFFFFFFFu, x, off);
        if (lane >= off) x += y;
    }
    if (lane == 31) warpsums[wid] = x;
    __syncthreads();
    if (wid == 0 && lane < 4) {
        int wv = warpsums[lane];
        #pragma unroll
        for (int off = 1; off < 4; off <<= 1) {
            int y = __shfl_up_sync(0xFu, wv, off);
            if (lane >= off) wv += y;
        }
        warpsums[lane] = wv;
    }
    __syncthreads();
    int woff = (wid == 0) ? 0 : warpsums[wid - 1];
    int excl = x - v + woff;
    if (tid < nblk) g_boffs[tid] = excl;
    if (tid == nblk - 1) g_offs[N_NODES] = excl + v;
}

__global__ void scan3_kernel() {
    int i = blockIdx.x * blockDim.x + threadIdx.x;
    if (i >= N_NODES) return;
    int o = g_offs[i] + g_boffs[i >> 10];
    g_offs[i] = o;
    int d0 = g_deg4[i];
    int d1 = g_deg4[N_NODES + i];
    int d2 = g_deg4[2 * N_NODES + i];
    g_cur4[i] = o;
    g_cur4[N_NODES + i] = o + d0;
    g_cur4[2 * N_NODES + i] = o + d0 + d1;
    g_cur4[3 * N_NODES + i] = o + d0 + d1 + d2;
}

__global__ void scatter_kernel(const void* __restrict__ ei) {
    int stride = gridDim.x * blockDim.x;
    for (int e = blockIdx.x * blockDim.x + threadIdx.x; e < N_EDGES; e += stride) {
        int s = edge_val(ei, e);
        int d = edge_val(ei, (long long)N_EDGES + e);
        int p = atomicAdd(&g_cur4[(e & 3) * N_NODES + d], 1);
        g_ssrc[p] = s;
    }
}

// x (N, 30, 8) -> g_xT16[t][n][20] bf16, node-major, coalesced out.
__global__ void __launch_bounds__(256) transpose_x(const float* __restrict__ x) {
    __shared__ float sm[32 * 161];
    __shared__ __nv_bfloat16 so[8 * 32 * 20];   // [t][nl][j]
    int n0 = blockIdx.x * 32;
    #pragma unroll
    for (int w = 0; w < 20; w++) {
        int i = threadIdx.x + w * 256;
        int nl = i / 160, off = i - nl * 160;
        sm[nl * 161 + off] = x[(size_t)(n0 + nl) * 240 + 80 + off];
    }
    __syncthreads();
    #pragma unroll
    for (int w = 0; w < 20; w++) {
        int idx = threadIdx.x + w * 256;
        int nl = idx & 31;
        int p = idx >> 5;
        int t = p / 20, j = p - t * 20;
        so[(t * 32 + nl) * 20 + j] = __float2bfloat16_rn(sm[nl * 161 + j * 8 + t]);
    }
    __syncthreads();
    const uint32_t* sou = reinterpret_cast<const uint32_t*>(so);
    uint32_t* dst = reinterpret_cast<uint32_t*>(g_xT16);
    #pragma unroll
    for (int w = 0; w < 10; w++) {
        int idx = threadIdx.x + w * 256;           // 0..2559
        int t = idx / 320;
        int rem = idx - t * 320;
        dst[((size_t)t * N_NODES + n0) * 10 + rem] = sou[idx];
    }
}

// Fold GNN projection into gate weights, permute rows to (i,f,g,o) quads, emit bf16.
__global__ void prep_weights(const float* __restrict__ W_ih, const float* __restrict__ W_hh,
                             const float* __restrict__ b_ih, const float* __restrict__ b_hh,
                             const float* __restrict__ W_rel, const float* __restrict__ b_rel,
                             const float* __restrict__ W_root) {
    int rp = blockIdx.x;
    int u = rp >> 2, q = rp & 3;
    int r = q * 64 + u;
    __shared__ float wg[64];
    int tid = threadIdx.x;  // 64 threads
    wg[tid] = W_ih[r * 84 + 20 + tid];
    __syncthreads();
    int c = tid;
    float m1 = 0.f, m2 = 0.f;
    #pragma unroll 8
    for (int j = 0; j < 64; j++) {
        float w = wg[j];
        m1 += w * W_rel[j * 64 + c];
        m2 += w * W_root[j * 64 + c];
    }
    m2 += W_hh[r * 64 + c];
    g_Wb[rp * 160 + 20 + c] = __float2bfloat16_rn(m1);
    g_Wb[rp * 160 + 84 + c] = __float2bfloat16_rn(m2);
    if (c < 20) g_Wb[rp * 160 + c] = __float2bfloat16_rn(W_ih[r * 84 + c]);
    if (c < 12) g_Wb[rp * 160 + 148 + c] = __float2bfloat16_rn(0.f);
    if (c == 0) {
        float s = b_ih[r] + b_hh[r];
        for (int j = 0; j < 64; j++) s += wg[j] * b_rel[j];
        g_bias[rp] = s;
    }
}

// bf16 copies of head weights.
__global__ void prep_head(const float* __restrict__ W1, const float* __restrict__ W2,
                          const float* __restrict__ W_rel, const float* __restrict__ W_root) {
    int i = blockIdx.x * 256 + threadIdx.x;
    if (i < 8192) {
        g_W1b[i] = __float2bfloat16_rn(W1[i]);
    } else if (i < 16384) {
        g_W2b[i - 8192] = __float2bfloat16_rn(W2[i - 8192]);
    } else if (i < 24576) {
        int j = i - 16384;
        int o = j >> 7, k = j & 127;
        float v = (k < 64) ? W_rel[o * 64 + k] : W_root[o * 64 + k - 64];
        g_Whb[j] = __float2bfloat16_rn(v);
    }
}

// ---------------- aggregation: warp per dst node, bf16 gather ----------------
__global__ void agg_kernel(const __nv_bfloat16* __restrict__ h16) {
    int gw = (blockIdx.x * blockDim.x + threadIdx.x) >> 5;
    int lane = threadIdx.x & 31;
    if (gw >= N_NODES) return;
    int beg = g_offs[gw], end = g_offs[gw + 1];
    float2 acc = make_float2(0.f, 0.f);
    int e = beg;
    for (; e + 4 <= end; e += 4) {
        int s0 = g_ssrc[e], s1 = g_ssrc[e + 1], s2 = g_ssrc[e + 2], s3 = g_ssrc[e + 3];
        float2 v0 = __bfloat1622float2(
            *reinterpret_cast<const __nv_bfloat162*>(h16 + (size_t)s0 * 64 + lane * 2));
        float2 v1 = __bfloat1622float2(
            *reinterpret_cast<const __nv_bfloat162*>(h16 + (size_t)s1 * 64 + lane * 2));
        float2 v2 = __bfloat1622float2(
            *reinterpret_cast<const __nv_bfloat162*>(h16 + (size_t)s2 * 64 + lane * 2));
        float2 v3 = __bfloat1622float2(
            *reinterpret_cast<const __nv_bfloat162*>(h16 + (size_t)s3 * 64 + lane * 2));
        acc.x += (v0.x + v1.x) + (v2.x + v3.x);
        acc.y += (v0.y + v1.y) + (v2.y + v3.y);
    }
    for (; e < end; e++) {
        int s = g_ssrc[e];
        float2 v = __bfloat1622float2(
            *reinterpret_cast<const __nv_bfloat162*>(h16 + (size_t)s * 64 + lane * 2));
        acc.x += v.x;
        acc.y += v.y;
    }
    *reinterpret_cast<__nv_bfloat162*>(g_agg16 + (size_t)gw * 64 + lane * 2) =
        __float22bfloat162_rn(acc);
}

// ---------------- bf16 mma.sync gate GEMM + fused LSTM epilogue ----------------
// Tile: 128 nodes x 64 gate cols (grid y = 4). 8 warps = 4m x 2n, warp 32x32.
// smem: A[128][336B] @0 (43008), B[64][336B] @43008 (21504). Total 64512.
// 3 CTAs/SM (smem 193.5KB, regs <= 85).
#define GATE_SMEM 64512

__global__ void __launch_bounds__(256, 3)
gate_kernel(const __nv_bfloat16* __restrict__ xTt16,
            const __nv_bfloat16* __restrict__ h16_in,
            float* __restrict__ h_out, __nv_bfloat16* __restrict__ h16_out,
            int t0, int wf32) {
    extern __shared__ char smem[];
    const int tid = threadIdx.x;
    const int wid = tid >> 5;
    const int lane = tid & 31;
    const int n0 = blockIdx.x * 128;
    const int col0 = blockIdx.y * 64;    // gate-col base (0/64/128/192)
    const int ubase = col0 >> 2;         // unit base (16 units per CTA)

    // ---- stage B: 64 weight rows x 160 bf16 ----
    {
        const uint4* Wb4 = reinterpret_cast<const uint4*>(g_Wb + (size_t)col0 * 160);
        #pragma unroll
        for (int it = 0; it < 5; it++) {
            int idx = tid + it * 256;        // 0..1279 = r*20 + c
            int r = idx / 20;
            int c = idx - r * 20;
            *reinterpret_cast<uint4*>(smem + 43008 + r * 336 + c * 16) = Wb4[idx];
        }
    }
    // ---- stage A: x bf16 (k 0..19), raw 4B copies ----
    {
        const uint32_t* xr = reinterpret_cast<const uint32_t*>(xTt16);
        #pragma unroll
        for (int it = 0; it < 5; it++) {
            int idx = tid + it * 256;        // 0..1279 = nl*10 + p
            int nl = idx / 10;
            int p = idx - nl * 10;
            int n = n0 + nl;
            uint32_t v = (n < N_NODES) ? xr[(size_t)n * 10 + p] : 0u;
            *reinterpret_cast<uint32_t*>(smem + nl * 336 + p * 4) = v;
        }
    }
    // ---- A: agg bf16 (k 20..83) + h bf16 (k 84..147): raw 8B copies ----
    #pragma unroll
    for (int it = 0; it < 8; it++) {
        int idx = tid + it * 256;            // 0..2047 = nl*16 + cp
        int nl = idx >> 4;
        int cp = idx & 15;
        int n = n0 + nl;
        uint2 va = make_uint2(0u, 0u), vh = make_uint2(0u, 0u);
        if (!t0 && n < N_NODES) {
            va = *reinterpret_cast<const uint2*>(g_agg16 + (size_t)n * 64 + cp * 4);
            vh = *reinterpret_cast<const uint2*>(h16_in + (size_t)n * 64 + cp * 4);
        }
        *reinterpret_cast<uint2*>(smem + nl * 336 + 40 + cp * 8) = va;
        *reinterpret_cast<uint2*>(smem + nl * 336 + 168 + cp * 8) = vh;
    }
    // ---- A: zero pad (k 148..167) ----
    #pragma unroll
    for (int it = 0; it < 3; it++) {
        int idx = tid + it * 256;            // need 640
        if (idx < 640) {
            int nl = idx / 5;
            int p = idx - nl * 5;
            *reinterpret_cast<uint2*>(smem + nl * 336 + 296 + p * 8) = make_uint2(0u, 0u);
        }
    }
    __syncthreads();

    // ---- mma mainloop: warp tile 32 rows x 32 cols ----
    const int mw = wid >> 1;                 // 0..3
    const int nw = wid & 1;                  // 0..1
    const int mr = mw * 32;
    const int ncw = nw * 32;                 // col within CTA tile (0 or 32)
    const uint32_t sbase = smem_u32(smem);
    uint32_t aAddr = sbase + (mr + (lane & 15)) * 336 + ((lane >> 4) << 4);
    uint32_t bAddr = sbase + 43008u + (ncw + (lane & 15)) * 336 + ((lane >> 4) << 4);

    float acc[2][4][4];
    #pragma unroll
    for (int mi = 0; mi < 2; mi++)
        #pragma unroll
        for (int nj = 0; nj < 4; nj++)
            #pragma unroll
            for (int e = 0; e < 4; e++) acc[mi][nj][e] = 0.f;

    #pragma unroll
    for (int ks = 0; ks < 10; ks++) {
        uint32_t a[2][4];
        ldsm_x4(a[0], aAddr + ks * 32);
        ldsm_x4(a[1], aAddr + 16 * 336 + ks * 32);
        uint32_t b[2][4];
        ldsm_x4(b[0], bAddr + ks * 32);
        ldsm_x4(b[1], bAddr + 16 * 336 + ks * 32);
        #pragma unroll
        for (int mi = 0; mi < 2; mi++)
            #pragma unroll
            for (int nj2 = 0; nj2 < 4; nj2++) {
                int nj = nj2 >> 1, hi = nj2 & 1;
                mma_bf16(acc[mi][nj2], a[mi], b[nj][hi], b[nj][hi + 2]);
            }
    }
    __syncthreads();

    // ---- repurpose smem: Cs[128][17], Hs[128][17], sbias[64] ----
    float* Cs = reinterpret_cast<float*>(smem);
    float* Hs = Cs + 128 * 17;
    float* sbias = Hs + 128 * 17;
    #pragma unroll
    for (int it = 0; it < 8; it++) {
        int idx = tid + it * 256;            // 0..2047 = rr*16 + u
        int rr = idx >> 4;
        int u = idx & 15;
        int n = n0 + rr;
        Cs[rr * 17 + u] = (n < N_NODES) ? g_c[(size_t)n * 64 + ubase + u] : 0.f;
    }
    if (tid < 64) sbias[tid] = g_bias[col0 + tid];
    __syncthreads();

    // ---- fused LSTM epilogue ----
    #pragma unroll
    for (int mi = 0; mi < 2; mi++) {
        int row = mr + mi * 16 + (lane >> 2) + ((lane & 1) << 3);
        #pragma unroll
        for (int nj2 = 0; nj2 < 4; nj2++) {
            float d0 = acc[mi][nj2][0], d1 = acc[mi][nj2][1];
            float d2 = acc[mi][nj2][2], d3 = acc[mi][nj2][3];
            float xd0 = __shfl_xor_sync(0xFFFFFFFFu, d0, 1);
            float xd1 = __shfl_xor_sync(0xFFFFFFFFu, d1, 1);
            float xd2 = __shfl_xor_sync(0xFFFFFFFFu, d2, 1);
            float xd3 = __shfl_xor_sync(0xFFFFFFFFu, d3, 1);
            float ig, fg, gg, og;
            if (lane & 1) { ig = xd2; fg = xd3; gg = d2; og = d3; }
            else          { ig = d0;  fg = d1;  gg = xd0; og = xd1; }
            int qb = ncw + nj2 * 8 + ((lane & 2) << 1);   // local col quad base
            ig += sbias[qb];
            fg += sbias[qb + 1];
            gg += sbias[qb + 2];
            og += sbias[qb + 3];
            float si = fast_sigmoid(ig);
            float sf = fast_sigmoid(fg);
            float so = fast_sigmoid(og);
            float tg = fast_tanh(gg);
            int u = qb >> 2;                 // 0..15
            float cold = Cs[row * 17 + u];
            float cn = sf * cold + si * tg;
            Cs[row * 17 + u] = cn;
            float tcn = fast_tanh(cn);
            Hs[row * 17 + u] = so * tcn;
        }
    }
    __syncthreads();

    // ---- coalesced writeback (32B per node per CTA) ----
    #pragma unroll
    for (int it = 0; it < 8; it++) {
        int idx = tid + it * 256;
        int rr = idx >> 4;
        int u = idx & 15;
        int n = n0 + rr;
        if (n < N_NODES) {
            size_t o = (size_t)n * 64 + ubase + u;
            float cn = Cs[rr * 17 + u];
            float hv = Hs[rr * 17 + u];
            g_c[o] = cn;
            h16_out[o] = __float2bfloat16_rn(hv);
            if (wf32) h_out[o] = hv;
        }
    }
}

// ---------------- head1: gnn = [agg|h] @ [W_rel|W_root]^T + b_rel (mma) ------
#define H1_SMEM 52480

__global__ void __launch_bounds__(256)
head1_kernel(const __nv_bfloat16* __restrict__ h16in, const float* __restrict__ b_rel) {
    extern __shared__ char smem[];
    const int tid = threadIdx.x;
    const int wid = tid >> 5;
    const int lane = tid & 31;
    const int n0 = blockIdx.x * 128;
    float* sb = reinterpret_cast<float*>(smem + 52224);

    {
        const uint4* Wh4 = reinterpret_cast<const uint4*>(g_Whb);
        #pragma unroll
        for (int it = 0; it < 4; it++) {
            int idx = tid + it * 256;
            int r = idx >> 4, c16 = idx & 15;
            *reinterpret_cast<uint4*>(smem + 34816 + r * 272 + c16 * 16) = Wh4[idx];
        }
    }
    #pragma unroll
    for (int it = 0; it < 8; it++) {
        int idx = tid + it * 256;
        int nl = idx >> 4, q = idx & 15;
        int n = n0 + nl;
        uint4 v = make_uint4(0u, 0u, 0u, 0u);
        if (n < N_NODES) {
            if (q < 8) v = reinterpret_cast<const uint4*>(g_agg16 + (size_t)n * 64)[q];
            else       v = reinterpret_cast<const uint4*>(h16in + (size_t)n * 64)[q - 8];
        }
        *reinterpret_cast<uint4*>(smem + nl * 272 + q * 16) = v;
    }
    if (tid < 128)
        *reinterpret_cast<uint4*>(smem + tid * 272 + 256) = make_uint4(0u, 0u, 0u, 0u);
    if (tid < 64) sb[tid] = b_rel[tid];
    __syncthreads();

    const int mw = wid >> 1;
    const int nw = wid & 1;
    const int mr = mw * 32;
    const int nc = nw * 32;
    const uint32_t sbase = smem_u32(smem);
    uint32_t aAddr = sbase + (mr + (lane & 15)) * 272 + ((lane >> 4) << 4);
    uint32_t bAddr = sbase + 34816u + (nc + (lane & 15)) * 272 + ((lane >> 4) << 4);

    float acc[2][4][4];
    #pragma unroll
    for (int mi = 0; mi < 2; mi++)
        #pragma unroll
        for (int nj = 0; nj < 4; nj++)
            #pragma unroll
            for (int e = 0; e < 4; e++) acc[mi][nj][e] = 0.f;

    #pragma unroll
    for (int ks = 0; ks < 8; ks++) {
        uint32_t a[2][4];
        ldsm_x4(a[0], aAddr + ks * 32);
        ldsm_x4(a[1], aAddr + 16 * 272 + ks * 32);
        uint32_t b[2][4];
        ldsm_x4(b[0], bAddr + ks * 32);
        ldsm_x4(b[1], bAddr + 16 * 272 + ks * 32);
        #pragma unroll
        for (int mi = 0; mi < 2; mi++)
            #pragma unroll
            for (int nj2 = 0; nj2 < 4; nj2++) {
                int nj = nj2 >> 1, hi = nj2 & 1;
                mma_bf16(acc[mi][nj2], a[mi], b[nj][hi], b[nj][hi + 2]);
            }
    }
    __syncthreads();

    float* Gs = reinterpret_cast<float*>(smem);
    #pragma unroll
    for (int mi = 0; mi < 2; mi++) {
        int row = mr + mi * 16 + (lane >> 2);
        #pragma unroll
        for (int nj2 = 0; nj2 < 4; nj2++) {
            int c = nc + nj2 * 8 + (lane & 3) * 2;
            *reinterpret_cast<float2*>(&Gs[row * 68 + c]) =
                make_float2(acc[mi][nj2][0] + sb[c], acc[mi][nj2][1] + sb[c + 1]);
            *reinterpret_cast<float2*>(&Gs[(row + 8) * 68 + c]) =
                make_float2(acc[mi][nj2][2] + sb[c], acc[mi][nj2][3] + sb[c + 1]);
        }
    }
    __syncthreads();

    #pragma unroll
    for (int it = 0; it < 32; it++) {
        int idx = tid + it * 256;
        int rr = idx >> 6, u = idx & 63;
        int n = n0 + rr;
        if (n < N_NODES) g_gnn[(size_t)n * 64 + u] = Gs[rr * 68 + u];
    }
}

// ---------------- head2: fused layernorm + MLP + out-projection (mma) --------
#define H2_SMEM 90880

__global__ void __launch_bounds__(256)
head2_kernel(const float* __restrict__ hfin, const float* __restrict__ b1,
             const float* __restrict__ b2, const float* __restrict__ Wout,
             const float* __restrict__ bout, float* __restrict__ out) {
    extern __shared__ char smem[];
    const int tid = threadIdx.x;
    const int wid = tid >> 5;
    const int lane = tid & 31;
    const int n0 = blockIdx.x * 128;
    float* sb1 = reinterpret_cast<float*>(smem + 89088);
    float* sb2 = reinterpret_cast<float*>(smem + 89344);
    float* sWout = reinterpret_cast<float*>(smem + 89856);
    float* sdot = reinterpret_cast<float*>(smem + 90368);

    #pragma unroll
    for (int it = 0; it < 32; it++) {
        int idx = tid + it * 256;
        int nl = idx >> 6, cp = idx & 63;
        int c = cp * 2;
        int n = n0 + nl;
        float2 v = make_float2(0.f, 0.f);
        if (n < N_NODES) {
            v = (cp < 32)
                ? reinterpret_cast<const float2*>(hfin)[(size_t)n * 32 + cp]
                : reinterpret_cast<const float2*>(g_gnn)[(size_t)n * 32 + cp - 32];
        }
        float2 nv = make_float2(v.x * g_scale[c] + g_shift[c],
                                v.y * g_scale[c + 1] + g_shift[c + 1]);
        *reinterpret_cast<__nv_bfloat162*>(smem + nl * 272 + c * 2) =
            __float22bfloat162_rn(nv);
    }
    if (tid < 128)
        *reinterpret_cast<uint4*>(smem + tid * 272 + 256) = make_uint4(0u, 0u, 0u, 0u);
    {
        const uint4* W14 = reinterpret_cast<const uint4*>(g_W1b);
        #pragma unroll
        for (int it = 0; it < 4; it++) {
            int idx = tid + it * 256;
            int r = idx >> 4, c16 = idx & 15;
            *reinterpret_cast<uint4*>(smem + 34816 + r * 272 + c16 * 16) = W14[idx];
        }
        const uint4* W24 = reinterpret_cast<const uint4*>(g_W2b);
        #pragma unroll
        for (int it = 0; it < 4; it++) {
            int idx = tid + it * 256;
            int r = idx >> 3, c8 = idx & 7;
            *reinterpret_cast<uint4*>(smem + 70656 + r * 144 + c8 * 16) = W24[idx];
        }
    }
    if (tid < 64) sb1[tid] = b1[tid];
    if (tid < 128) {
        sb2[tid] = b2[tid];
        sWout[tid] = Wout[tid];
        sdot[tid] = 0.f;
    }
    __syncthreads();

    const int mw = wid >> 1;
    const int nw = wid & 1;
    const int mr = mw * 32;
    const uint32_t sbase = smem_u32(smem);

    {
        const int nc = nw * 32;
        uint32_t aAddr = sbase + (mr + (lane & 15)) * 272 + ((lane >> 4) << 4);
        uint32_t bAddr = sbase + 34816u + (nc + (lane & 15)) * 272 + ((lane >> 4) << 4);
        float acc1[2][4][4];
        #pragma unroll
        for (int mi = 0; mi < 2; mi++)
            #pragma unroll
            for (int nj = 0; nj < 4; nj++)
                #pragma unroll
                for (int e = 0; e < 4; e++) acc1[mi][nj][e] = 0.f;
        #pragma unroll
        for (int ks = 0; ks < 8; ks++) {
            uint32_t a[2][4];
            ldsm_x4(a[0], aAddr + ks * 32);
            ldsm_x4(a[1], aAddr + 16 * 272 + ks * 32);
            uint32_t b[2][4];
            ldsm_x4(b[0], bAddr + ks * 32);
            ldsm_x4(b[1], bAddr + 16 * 272 + ks * 32);
            #pragma unroll
            for (int mi = 0; mi < 2; mi++)
                #pragma unroll
                for (int nj2 = 0; nj2 < 4; nj2++) {
                    int nj = nj2 >> 1, hi = nj2 & 1;
                    mma_bf16(acc1[mi][nj2], a[mi], b[nj][hi], b[nj][hi + 2]);
                }
        }
        #pragma unroll
        for (int mi = 0; mi < 2; mi++) {
            int row = mr + mi * 16 + (lane >> 2);
            #pragma unroll
            for (int nj2 = 0; nj2 < 4; nj2++) {
                int c = nc + nj2 * 8 + (lane & 3) * 2;
                float v0 = fmaxf(acc1[mi][nj2][0] + sb1[c], 0.f);
                float v1 = fmaxf(acc1[mi][nj2][1] + sb1[c + 1], 0.f);
                float v2 = fmaxf(acc1[mi][nj2][2] + sb1[c], 0.f);
                float v3 = fmaxf(acc1[mi][nj2][3] + sb1[c + 1], 0.f);
                *reinterpret_cast<__nv_bfloat162*>(smem + 52224 + row * 144 + c * 2) =
                    __float22bfloat162_rn(make_float2(v0, v1));
                *reinterpret_cast<__nv_bfloat162*>(smem + 52224 + (row + 8) * 144 + c * 2) =
                    __float22bfloat162_rn(make_float2(v2, v3));
            }
        }
    }
    __syncthreads();

    {
        const int nc = nw * 64;
        uint32_t aAddr = sbase + 52224u + (mr + (lane & 15)) * 144 + ((lane >> 4) << 4);
        uint32_t bAddr = sbase + 70656u + (nc + (lane & 15)) * 144 + ((lane >> 4) << 4);
        float acc2[2][8][4];
        #pragma unroll
        for (int mi = 0; mi < 2; mi++)
            #pragma unroll
            for (int nj = 0; nj < 8; nj++)
                #pragma unroll
                for (int e = 0; e < 4; e++) acc2[mi][nj][e] = 0.f;
        #pragma unroll
        for (int ks = 0; ks < 4; ks++) {
            uint32_t a[2][4];
            ldsm_x4(a[0], aAddr + ks * 32);
            ldsm_x4(a[1], aAddr + 16 * 144 + ks * 32);
            uint32_t b[4][4];
            #pragma unroll
            for (int nj = 0; nj < 4; nj++)
                ldsm_x4(b[nj], bAddr + nj * 16 * 144 + ks * 32);
            #pragma unroll
            for (int mi = 0; mi < 2; mi++)
                #pragma unroll
                for (int nj2 = 0; nj2 < 8; nj2++) {
                    int nj = nj2 >> 1, hi = nj2 & 1;
                    mma_bf16(acc2[mi][nj2], a[mi], b[nj][hi], b[nj][hi + 2]);
                }
        }
        #pragma unroll
        for (int mi = 0; mi < 2; mi++) {
            float p0 = 0.f, p1 = 0.f;
            #pragma unroll
            for (int nj2 = 0; nj2 < 8; nj2++) {
                int c = nc + nj2 * 8 + (lane & 3) * 2;
                float w0 = sWout[c], w1 = sWout[c + 1];
                p0 += fmaxf(acc2[mi][nj2][0] + sb2[c], 0.f) * w0
                    + fmaxf(acc2[mi][nj2][1] + sb2[c + 1], 0.f) * w1;
                p1 += fmaxf(acc2[mi][nj2][2] + sb2[c], 0.f) * w0
                    + fmaxf(acc2[mi][nj2][3] + sb2[c + 1], 0.f) * w1;
            }
            p0 += __shfl_xor_sync(0xFFFFFFFFu, p0, 1);
            p0 += __shfl_xor_sync(0xFFFFFFFFu, p0, 2);
            p1 += __shfl_xor_sync(0xFFFFFFFFu, p1, 1);
            p1 += __shfl_xor_sync(0xFFFFFFFFu, p1, 2);
            if ((lane & 3) == 0) {
                int row = mr + mi * 16 + (lane >> 2);
                atomicAdd(&sdot[row], p0);
                atomicAdd(&sdot[row + 8], p1);
            }
        }
    }
    __syncthreads();

    if (tid < 128) {
        int n = n0 + tid;
        if (n < N_NODES) {
            float s = sdot[tid] + bout[0];
            out[n] = 1.f / (1.f + __expf(-s));
        }
    }
}

// ---------------- per-feature stats over nodes ----------------
__global__ void stats_kernel(const float* __restrict__ h, const float* __restrict__ gnn) {
    int c = threadIdx.x & 127;
    int grp = threadIdx.x >> 7;
    int r0 = blockIdx.x * 256;
    int rend = min(r0 + 256, N_NODES);
    float s = 0.f, q = 0.f;
    for (int r = r0 + grp; r < rend; r += 2) {
        float v = (c < 64) ? h[(size_t)r * 64 + c] : gnn[(size_t)r * 64 + c - 64];
        s += v;
        q += v * v;
    }
    atomicAdd(&g_stats[c], s);
    atomicAdd(&g_stats[128 + c], q);
}

__global__ void finalize_stats(const float* __restrict__ gamma, const float* __restrict__ beta) {
    int c = threadIdx.x;
    float mean = g_stats[c] / (float)N_NODES;
    float var = g_stats[128 + c] / (float)N_NODES - mean * mean;
    float rstd = rsqrtf(var + 1e-5f);
    float sc = rstd * gamma[c];
    g_scale[c] = sc;
    g_shift[c] = beta[c] - mean * sc;
}

// ---------------- launch ----------------
extern "C" void kernel_launch(void* const* d_in, const int* in_sizes, int n_in,
                              void* d_out, int out_size) {
    const float* x      = (const float*)d_in[0];
    const void*  ei     = d_in[1];
    const float* W_ih   = (const float*)d_in[4];
    const float* W_hh   = (const float*)d_in[5];
    const float* b_ih   = (const float*)d_in[6];
    const float* b_hh   = (const float*)d_in[7];
    const float* W_rel  = (const float*)d_in[8];
    const float* b_rel  = (const float*)d_in[9];
    const float* W_root = (const float*)d_in[10];
    const float* gamma  = (const float*)d_in[11];
    const float* beta   = (const float*)d_in[12];
    const float* W1     = (const float*)d_in[13];
    const float* b1     = (const float*)d_in[14];
    const float* W2     = (const float*)d_in[15];
    const float* b2     = (const float*)d_in[16];
    const float* W_out  = (const float*)d_in[17];
    const float* b_out  = (const float*)d_in[18];

    float *hbuf, *gnn;
    __nv_bfloat16 *h16, *xT16;
    cudaGetSymbolAddress((void**)&hbuf, g_hbuf);
    cudaGetSymbolAddress((void**)&h16, g_h16);
    cudaGetSymbolAddress((void**)&gnn, g_gnn);
    cudaGetSymbolAddress((void**)&xT16, g_xT16);

    cudaFuncSetAttribute(gate_kernel, cudaFuncAttributeMaxDynamicSharedMemorySize, GATE_SMEM);
    cudaFuncSetAttribute(head1_kernel, cudaFuncAttributeMaxDynamicSharedMemorySize, H1_SMEM);
    cudaFuncSetAttribute(head2_kernel, cudaFuncAttributeMaxDynamicSharedMemorySize, H2_SMEM);

    const int scan_blocks = (N_NODES + 1023) / 1024;   // 98
    dim3 ggrid((N_NODES + 127) / 128, 4);

    // t=0 gate only needs zero_state + prep_weights + transpose_x.
    // (gate_kernel is launch #4 so the fixed ncu window profiles it.)
    zero_state<<<512, 256>>>();
    prep_weights<<<256, 64>>>(W_ih, W_hh, b_ih, b_hh, W_rel, b_rel, W_root);
    transpose_x<<<N_NODES / 32, 256>>>(x);
    gate_kernel<<<ggrid, 256, GATE_SMEM>>>(xT16, h16, hbuf, h16 + (size_t)N_NODES * 64, 1, 0);

    detect_kernel<<<1, 256>>>((const unsigned int*)ei);
    prep_head<<<96, 256>>>(W1, W2, W_rel, W_root);
    hist_zero<<<256, 256>>>();
    hist2_kernel<<<512, 256>>>(ei);
    scan1_kernel<<<scan_blocks, 1024>>>();
    scan2_kernel<<<1, 128>>>(scan_blocks);
    scan3_kernel<<<(N_NODES + 255) / 256, 256>>>();
    scatter_kernel<<<512, 256>>>(ei);

    for (int t = 1; t < T_STEPS; t++) {
        const __nv_bfloat16* h16_in = h16 + (size_t)(t & 1) * N_NODES * 64;
        __nv_bfloat16* h16_out = h16 + (size_t)((t + 1) & 1) * N_NODES * 64;
        agg_kernel<<<(N_NODES * 32 + 255) / 256, 256>>>(h16_in);
        gate_kernel<<<ggrid, 256, GATE_SMEM>>>(
            xT16 + (size_t)t * N_NODES * 20, h16_in, hbuf, h16_out,
            0, t == T_STEPS - 1 ? 1 : 0);
    }
    // h16 buffer 1 = h at start of step 7 (used by gnn); hbuf = final h fp32.
    int n_tiles = (N_NODES + 127) / 128;   // 782
    head1_kernel<<<n_tiles, 256, H1_SMEM>>>(h16 + (size_t)N_NODES * 64, b_rel);
    stats_kernel<<<(N_NODES + 255) / 256, 256>>>(hbuf, gnn);
    finalize_stats<<<1, 128>>>(gamma, beta);
    head2_kernel<<<n_tiles, 256, H2_SMEM>>>(hbuf, b1, b2, W_out, b_out, (float*)d_out);
}

// round 10
// speedup vs baseline: 1.9985x; 1.0276x over previous
#include <cuda_runtime.h>
#include <cuda_bf16.h>
#include <math.h>
#include <cstdint>

#define N_NODES 100000
#define N_EDGES 1600000
#define T_STEPS 8

// ---------------- device scratch (no allocations allowed) ----------------
__device__ float g_hbuf[N_NODES * 64];                     // fp32 final h (t=7 only)
__device__ __nv_bfloat16 g_h16[2 * N_NODES * 64];          // bf16 h double buffer
__device__ float g_c[N_NODES * 64];
__device__ __nv_bfloat16 g_agg16[N_NODES * 64];
__device__ float g_gnn[N_NODES * 64];
__device__ __align__(16) __nv_bfloat16 g_xT16[T_STEPS * N_NODES * 20];  // [t][n][20]
__device__ __align__(16) __nv_bfloat16 g_Wb[256 * 160];    // fused gate weights (interleaved rows)
__device__ __align__(16) __nv_bfloat16 g_W1b[64 * 128];
__device__ __align__(16) __nv_bfloat16 g_W2b[128 * 64];
__device__ __align__(16) __nv_bfloat16 g_Whb[64 * 128];    // [W_rel | W_root]
__device__ __align__(16) float g_bias[256];                // per-unit quads (i,f,g,o)
__device__ float g_stats[256];
__device__ float g_scale[128];
__device__ float g_shift[128];
__device__ int   g_deg4[4 * N_NODES];
__device__ int   g_cur4[4 * N_NODES];
__device__ int   g_offs[N_NODES + 1];
__device__ int   g_ssrc[N_EDGES];
__device__ int   g_bsums[128];
__device__ int   g_boffs[128];
__device__ int   g_is64;

// ---------------- mma/ldmatrix/cp.async helpers ----------------
__device__ __forceinline__ uint32_t smem_u32(const void* p) {
    uint32_t a;
    asm("{ .reg .u64 tmp; cvta.to.shared.u64 tmp, %1; cvt.u32.u64 %0, tmp; }"
        : "=r"(a) : "l"(p));
    return a;
}
__device__ __forceinline__ void ldsm_x4(uint32_t* r, uint32_t addr) {
    asm volatile("ldmatrix.sync.aligned.m8n8.x4.shared.b16 {%0,%1,%2,%3}, [%4];"
                 : "=r"(r[0]), "=r"(r[1]), "=r"(r[2]), "=r"(r[3]) : "r"(addr));
}
__device__ __forceinline__ void mma_bf16(float* d, const uint32_t* a,
                                         uint32_t b0, uint32_t b1) {
    asm volatile(
        "mma.sync.aligned.m16n8k16.row.col.f32.bf16.bf16.f32 "
        "{%0,%1,%2,%3}, {%4,%5,%6,%7}, {%8,%9}, {%0,%1,%2,%3};"
        : "+f"(d[0]), "+f"(d[1]), "+f"(d[2]), "+f"(d[3])
        : "r"(a[0]), "r"(a[1]), "r"(a[2]), "r"(a[3]), "r"(b0), "r"(b1));
}
__device__ __forceinline__ float fast_tanh(float x) {
    float y;
    asm("tanh.approx.f32 %0, %1;" : "=f"(y) : "f"(x));
    return y;
}
__device__ __forceinline__ float fast_sigmoid(float x) {
    return 0.5f * fast_tanh(0.5f * x) + 0.5f;
}
#define CP_ASYNC_16(dst, src) \
    asm volatile("cp.async.ca.shared.global [%0], [%1], 16;" :: "r"(dst), "l"(src))
#define CP_ASYNC_8S(dst, src, ssz) \
    asm volatile("cp.async.ca.shared.global [%0], [%1], 8, %2;" :: "r"(dst), "l"(src), "r"(ssz))
#define CP_ASYNC_4S(dst, src, ssz) \
    asm volatile("cp.async.ca.shared.global [%0], [%1], 4, %2;" :: "r"(dst), "l"(src), "r"(ssz))
#define CP_ASYNC_COMMIT() asm volatile("cp.async.commit_group;" ::: "memory")
#define CP_ASYNC_WAIT0()  asm volatile("cp.async.wait_group 0;" ::: "memory")

// ---------------- small utility kernels ----------------
__global__ void zero_state() {
    int stride = gridDim.x * blockDim.x;
    int i0 = blockIdx.x * blockDim.x + threadIdx.x;
    for (int k = i0; k < N_NODES * 64; k += stride) g_c[k] = 0.f;
    for (int k = i0; k < 4 * N_NODES; k += stride) g_deg4[k] = 0;
    if (i0 < 256) g_stats[i0] = 0.f;
}

__global__ void detect_kernel(const unsigned int* __restrict__ w) {
    __shared__ unsigned int acc;
    if (threadIdx.x == 0) acc = 0u;
    __syncthreads();
    unsigned int v = 0u;
    for (int i = threadIdx.x; i < 2048; i += blockDim.x) v |= w[2 * i + 1];
    atomicOr(&acc, v);
    __syncthreads();
    if (threadIdx.x == 0) g_is64 = (acc == 0u) ? 1 : 0;
}

__device__ __forceinline__ int edge_val(const void* ei, long long idx) {
    if (g_is64) return (int)((const long long*)ei)[idx];
    return ((const int*)ei)[idx];
}

__global__ void hist2_kernel(const void* __restrict__ ei) {
    int stride = gridDim.x * blockDim.x;
    for (int e = blockIdx.x * blockDim.x + threadIdx.x; e < N_EDGES; e += stride) {
        int d = edge_val(ei, (long long)N_EDGES + e);
        atomicAdd(&g_deg4[(e & 3) * N_NODES + d], 1);
    }
}

__global__ void scan1_kernel() {
    __shared__ int warpsums[32];
    int tid = threadIdx.x, lane = tid & 31, wid = tid >> 5;
    int i = blockIdx.x * 1024 + tid;
    int v = 0;
    if (i < N_NODES)
        v = g_deg4[i] + g_deg4[N_NODES + i] + g_deg4[2 * N_NODES + i]
          + g_deg4[3 * N_NODES + i];
    int x = v;
    #pragma unroll
    for (int off = 1; off < 32; off <<= 1) {
        int y = __shfl_up_sync(0xFFFFFFFFu, x, off);
        if (lane >= off) x += y;
    }
    if (lane == 31) warpsums[wid] = x;
    __syncthreads();
    if (wid == 0) {
        int wv = warpsums[lane];
        #pragma unroll
        for (int off = 1; off < 32; off <<= 1) {
            int y = __shfl_up_sync(0xFFFFFFFFu, wv, off);
            if (lane >= off) wv += y;
        }
        warpsums[lane] = wv;
    }
    __syncthreads();
    int woff = (wid == 0) ? 0 : warpsums[wid - 1];
    if (i < N_NODES) g_offs[i] = x - v + woff;
    if (tid == 1023) g_bsums[blockIdx.x] = warpsums[31];
}

__global__ void scan2_kernel(int nblk) {
    __shared__ int warpsums[4];
    int tid = threadIdx.x, lane = tid & 31, wid = tid >> 5;
    int v = (tid < nblk) ? g_bsums[tid] : 0;
    int x = v;
    #pragma unroll
    for (int off = 1; off < 32; off <<= 1) {
        int y = __shfl_up_sync(0xFFFFFFFFu, x, off);
        if (lane >= off) x += y;
    }
    if (lane == 31) warpsums[wid] = x;
    __syncthreads();
    if (wid == 0 && lane < 4) {
        int wv = warpsums[lane];
        #pragma unroll
        for (int off = 1; off < 4; off <<= 1) {
            int y = __shfl_up_sync(0xFu, wv, off);
            if (lane >= off) wv += y;
        }
        warpsums[lane] = wv;
    }
    __syncthreads();
    int woff = (wid == 0) ? 0 : warpsums[wid - 1];
    int excl = x - v + woff;
    if (tid < nblk) g_boffs[tid] = excl;
    if (tid == nblk - 1) g_offs[N_NODES] = excl + v;
}

__global__ void scan3_kernel() {
    int i = blockIdx.x * blockDim.x + threadIdx.x;
    if (i >= N_NODES) return;
    int o = g_offs[i] + g_boffs[i >> 10];
    g_offs[i] = o;
    int d0 = g_deg4[i];
    int d1 = g_deg4[N_NODES + i];
    int d2 = g_deg4[2 * N_NODES + i];
    g_cur4[i] = o;
    g_cur4[N_NODES + i] = o + d0;
    g_cur4[2 * N_NODES + i] = o + d0 + d1;
    g_cur4[3 * N_NODES + i] = o + d0 + d1 + d2;
}

__global__ void scatter_kernel(const void* __restrict__ ei) {
    int stride = gridDim.x * blockDim.x;
    for (int e = blockIdx.x * blockDim.x + threadIdx.x; e < N_EDGES; e += stride) {
        int s = edge_val(ei, e);
        int d = edge_val(ei, (long long)N_EDGES + e);
        int p = atomicAdd(&g_cur4[(e & 3) * N_NODES + d], 1);
        g_ssrc[p] = s;
    }
}

// x (N, 30, 8) -> g_xT16[t][n][20] bf16, node-major, coalesced out.
__global__ void __launch_bounds__(256) transpose_x(const float* __restrict__ x) {
    __shared__ float sm[32 * 161];
    __shared__ __nv_bfloat16 so[8 * 32 * 20];   // [t][nl][j]
    int n0 = blockIdx.x * 32;
    #pragma unroll
    for (int w = 0; w < 20; w++) {
        int i = threadIdx.x + w * 256;
        int nl = i / 160, off = i - nl * 160;
        sm[nl * 161 + off] = x[(size_t)(n0 + nl) * 240 + 80 + off];
    }
    __syncthreads();
    #pragma unroll
    for (int w = 0; w < 20; w++) {
        int idx = threadIdx.x + w * 256;
        int nl = idx & 31;
        int p = idx >> 5;
        int t = p / 20, j = p - t * 20;
        so[(t * 32 + nl) * 20 + j] = __float2bfloat16_rn(sm[nl * 161 + j * 8 + t]);
    }
    __syncthreads();
    const uint32_t* sou = reinterpret_cast<const uint32_t*>(so);
    uint32_t* dst = reinterpret_cast<uint32_t*>(g_xT16);
    #pragma unroll
    for (int w = 0; w < 10; w++) {
        int idx = threadIdx.x + w * 256;           // 0..2559
        int t = idx / 320;
        int rem = idx - t * 320;
        dst[((size_t)t * N_NODES + n0) * 10 + rem] = sou[idx];
    }
}

// Fold GNN projection into gate weights; interleaved row layout:
// block16 = rp>>4, within = rp&15; within<8: (i,f) vl=within>>1 q=within&1;
// else (g,o). unit u = block16*4+vl; original row r = q*64+u.
// Bias stored as per-unit quads g_bias[u*4+q].
__global__ void prep_weights(const float* __restrict__ W_ih, const float* __restrict__ W_hh,
                             const float* __restrict__ b_ih, const float* __restrict__ b_hh,
                             const float* __restrict__ W_rel, const float* __restrict__ b_rel,
                             const float* __restrict__ W_root) {
    int rp = blockIdx.x;
    int block16 = rp >> 4, within = rp & 15;
    int vl, q;
    if (within < 8) { vl = within >> 1; q = within & 1; }
    else            { vl = (within - 8) >> 1; q = 2 + ((within - 8) & 1); }
    int u = block16 * 4 + vl;
    int r = q * 64 + u;
    __shared__ float wg[64];
    int tid = threadIdx.x;  // 64 threads
    wg[tid] = W_ih[r * 84 + 20 + tid];
    __syncthreads();
    int c = tid;
    float m1 = 0.f, m2 = 0.f;
    #pragma unroll 8
    for (int j = 0; j < 64; j++) {
        float w = wg[j];
        m1 += w * W_rel[j * 64 + c];
        m2 += w * W_root[j * 64 + c];
    }
    m2 += W_hh[r * 64 + c];
    g_Wb[rp * 160 + 20 + c] = __float2bfloat16_rn(m1);
    g_Wb[rp * 160 + 84 + c] = __float2bfloat16_rn(m2);
    if (c < 20) g_Wb[rp * 160 + c] = __float2bfloat16_rn(W_ih[r * 84 + c]);
    if (c < 12) g_Wb[rp * 160 + 148 + c] = __float2bfloat16_rn(0.f);
    if (c == 0) {
        float s = b_ih[r] + b_hh[r];
        for (int j = 0; j < 64; j++) s += wg[j] * b_rel[j];
        g_bias[u * 4 + q] = s;
    }
}

// bf16 copies of head weights.
__global__ void prep_head(const float* __restrict__ W1, const float* __restrict__ W2,
                          const float* __restrict__ W_rel, const float* __restrict__ W_root) {
    int i = blockIdx.x * 256 + threadIdx.x;
    if (i < 8192) {
        g_W1b[i] = __float2bfloat16_rn(W1[i]);
    } else if (i < 16384) {
        g_W2b[i - 8192] = __float2bfloat16_rn(W2[i - 8192]);
    } else if (i < 24576) {
        int j = i - 16384;
        int o = j >> 7, k = j & 127;
        float v = (k < 64) ? W_rel[o * 64 + k] : W_root[o * 64 + k - 64];
        g_Whb[j] = __float2bfloat16_rn(v);
    }
}

// ---------------- aggregation: warp per dst node, bf16 gather ----------------
__global__ void agg_kernel(const __nv_bfloat16* __restrict__ h16) {
    int gw = (blockIdx.x * blockDim.x + threadIdx.x) >> 5;
    int lane = threadIdx.x & 31;
    if (gw >= N_NODES) return;
    int beg = g_offs[gw], end = g_offs[gw + 1];
    float2 acc = make_float2(0.f, 0.f);
    int e = beg;
    for (; e + 4 <= end; e += 4) {
        int s0 = g_ssrc[e], s1 = g_ssrc[e + 1], s2 = g_ssrc[e + 2], s3 = g_ssrc[e + 3];
        float2 v0 = __bfloat1622float2(
            *reinterpret_cast<const __nv_bfloat162*>(h16 + (size_t)s0 * 64 + lane * 2));
        float2 v1 = __bfloat1622float2(
            *reinterpret_cast<const __nv_bfloat162*>(h16 + (size_t)s1 * 64 + lane * 2));
        float2 v2 = __bfloat1622float2(
            *reinterpret_cast<const __nv_bfloat162*>(h16 + (size_t)s2 * 64 + lane * 2));
        float2 v3 = __bfloat1622float2(
            *reinterpret_cast<const __nv_bfloat162*>(h16 + (size_t)s3 * 64 + lane * 2));
        acc.x += (v0.x + v1.x) + (v2.x + v3.x);
        acc.y += (v0.y + v1.y) + (v2.y + v3.y);
    }
    for (; e < end; e++) {
        int s = g_ssrc[e];
        float2 v = __bfloat1622float2(
            *reinterpret_cast<const __nv_bfloat162*>(h16 + (size_t)s * 64 + lane * 2));
        acc.x += v.x;
        acc.y += v.y;
    }
    *reinterpret_cast<__nv_bfloat162*>(g_agg16 + (size_t)gw * 64 + lane * 2) =
        __float22bfloat162_rn(acc);
}

// ---------------- bf16 mma.sync gate GEMM + fused LSTM epilogue ----------------
// Tile: 128 nodes x 64 gate cols (grid y = 4). 8 warps = 4m x 2n, warp 32x32.
// smem: A[128][336B] @0 (43008), B[64][336B] @43008 (21504). 3 CTAs/SM.
// Weight rows interleaved so each lane's acc frags hold complete (i,f,g,o) quads.
#define GATE_SMEM 64512

__global__ void __launch_bounds__(256, 3)
gate_kernel(const __nv_bfloat16* __restrict__ xTt16,
            const __nv_bfloat16* __restrict__ h16_in,
            float* __restrict__ h_out, __nv_bfloat16* __restrict__ h16_out,
            int t0, int wf32) {
    extern __shared__ char smem[];
    const int tid = threadIdx.x;
    const int wid = tid >> 5;
    const int lane = tid & 31;
    const int n0 = blockIdx.x * 128;
    const int col0 = blockIdx.y * 64;    // gate-col base (0/64/128/192)
    const int ubase = col0 >> 2;         // unit base (16 units per CTA)
    const uint32_t sbase = smem_u32(smem);

    // ---- stage B via cp.async: 64 interleaved weight rows x 160 bf16 ----
    {
        const char* wsrc = reinterpret_cast<const char*>(g_Wb) + (size_t)col0 * 320;
        #pragma unroll
        for (int it = 0; it < 5; it++) {
            int idx = tid + it * 256;        // 0..1279 = r*20 + c
            int r = idx / 20;
            int c = idx - r * 20;
            CP_ASYNC_16(sbase + 43008u + r * 336 + c * 16, wsrc + r * 320 + c * 16);
        }
    }
    // ---- stage A: x bf16 (k 0..19), 4B cp.async with zfill ----
    {
        const char* xsrc = reinterpret_cast<const char*>(xTt16);
        #pragma unroll
        for (int it = 0; it < 5; it++) {
            int idx = tid + it * 256;        // 0..1279 = nl*10 + p
            int nl = idx / 10;
            int p = idx - nl * 10;
            int n = n0 + nl;
            int ncl = (n < N_NODES) ? n : (N_NODES - 1);
            uint32_t ssz = (n < N_NODES) ? 4u : 0u;
            CP_ASYNC_4S(sbase + nl * 336 + p * 4, xsrc + (size_t)ncl * 40 + p * 4, ssz);
        }
    }
    // ---- A: agg bf16 (k 20..83) + h bf16 (k 84..147): 8B cp.async with zfill ----
    {
        const char* asrc = reinterpret_cast<const char*>(g_agg16);
        const char* hsrc = reinterpret_cast<const char*>(h16_in);
        #pragma unroll
        for (int it = 0; it < 8; it++) {
            int idx = tid + it * 256;        // 0..2047 = nl*16 + cp
            int nl = idx >> 4;
            int cp = idx & 15;
            int n = n0 + nl;
            int ncl = (n < N_NODES) ? n : (N_NODES - 1);
            uint32_t ssz = (!t0 && n < N_NODES) ? 8u : 0u;
            CP_ASYNC_8S(sbase + nl * 336 + 40 + cp * 8, asrc + (size_t)ncl * 128 + cp * 8, ssz);
            CP_ASYNC_8S(sbase + nl * 336 + 168 + cp * 8, hsrc + (size_t)ncl * 128 + cp * 8, ssz);
        }
    }
    // ---- A: zero pad (k 148..167) plain stores ----
    #pragma unroll
    for (int it = 0; it < 3; it++) {
        int idx = tid + it * 256;
        if (idx < 640) {
            int nl = idx / 5;
            int p = idx - nl * 5;
            *reinterpret_cast<uint2*>(smem + nl * 336 + 296 + p * 8) = make_uint2(0u, 0u);
        }
    }
    CP_ASYNC_COMMIT();
    CP_ASYNC_WAIT0();
    __syncthreads();

    // ---- mma mainloop: warp tile 32 rows x 32 cols ----
    const int mw = wid >> 1;                 // 0..3
    const int nw = wid & 1;                  // 0..1
    const int mr = mw * 32;
    const int ncw = nw * 32;                 // col within CTA tile (0 or 32)
    uint32_t aAddr = sbase + (mr + (lane & 15)) * 336 + ((lane >> 4) << 4);
    uint32_t bAddr = sbase + 43008u + (ncw + (lane & 15)) * 336 + ((lane >> 4) << 4);

    float acc[2][4][4];
    #pragma unroll
    for (int mi = 0; mi < 2; mi++)
        #pragma unroll
        for (int nj = 0; nj < 4; nj++)
            #pragma unroll
            for (int e = 0; e < 4; e++) acc[mi][nj][e] = 0.f;

    #pragma unroll
    for (int ks = 0; ks < 10; ks++) {
        uint32_t a[2][4];
        ldsm_x4(a[0], aAddr + ks * 32);
        ldsm_x4(a[1], aAddr + 16 * 336 + ks * 32);
        uint32_t b[2][4];
        ldsm_x4(b[0], bAddr + ks * 32);
        ldsm_x4(b[1], bAddr + 16 * 336 + ks * 32);
        #pragma unroll
        for (int mi = 0; mi < 2; mi++)
            #pragma unroll
            for (int nj2 = 0; nj2 < 4; nj2++) {
                int nj = nj2 >> 1, hi = nj2 & 1;
                mma_bf16(acc[mi][nj2], a[mi], b[nj][hi], b[nj][hi + 2]);
            }
    }
    __syncthreads();

    // ---- repurpose smem: Cs[128][17], Hs[128][17], sb4[16] float4 ----
    float* Cs = reinterpret_cast<float*>(smem);
    float* Hs = Cs + 128 * 17;
    float4* sb4 = reinterpret_cast<float4*>(Hs + 128 * 17);
    #pragma unroll
    for (int it = 0; it < 8; it++) {
        int idx = tid + it * 256;            // 0..2047 = rr*16 + u
        int rr = idx >> 4;
        int u = idx & 15;
        int n = n0 + rr;
        Cs[rr * 17 + u] = (n < N_NODES) ? g_c[(size_t)n * 64 + ubase + u] : 0.f;
    }
    if (tid < 16)
        sb4[tid] = reinterpret_cast<const float4*>(g_bias)[ubase + tid];
    __syncthreads();

    // ---- fused LSTM epilogue (shuffle-free; frags hold complete quads) ----
    const int vl = lane & 3;
    #pragma unroll
    for (int mi = 0; mi < 2; mi++) {
        int r = mr + mi * 16 + (lane >> 2);
        #pragma unroll
        for (int b = 0; b < 2; b++) {
            int u = nw * 8 + b * 4 + vl;     // unit within CTA (0..15)
            float4 bq = sb4[u];
            float ig0 = acc[mi][2 * b][0] + bq.x;
            float fg0 = acc[mi][2 * b][1] + bq.y;
            float gg0 = acc[mi][2 * b + 1][0] + bq.z;
            float og0 = acc[mi][2 * b + 1][1] + bq.w;
            float ig1 = acc[mi][2 * b][2] + bq.x;
            float fg1 = acc[mi][2 * b][3] + bq.y;
            float gg1 = acc[mi][2 * b + 1][2] + bq.z;
            float og1 = acc[mi][2 * b + 1][3] + bq.w;
            {
                float si = fast_sigmoid(ig0), sf = fast_sigmoid(fg0);
                float so = fast_sigmoid(og0), tg = fast_tanh(gg0);
                float cold = Cs[r * 17 + u];
                float cn = sf * cold + si * tg;
                Cs[r * 17 + u] = cn;
                Hs[r * 17 + u] = so * fast_tanh(cn);
            }
            {
                float si = fast_sigmoid(ig1), sf = fast_sigmoid(fg1);
                float so = fast_sigmoid(og1), tg = fast_tanh(gg1);
                float cold = Cs[(r + 8) * 17 + u];
                float cn = sf * cold + si * tg;
                Cs[(r + 8) * 17 + u] = cn;
                Hs[(r + 8) * 17 + u] = so * fast_tanh(cn);
            }
        }
    }
    __syncthreads();

    // ---- coalesced writeback (32B per node per CTA) ----
    #pragma unroll
    for (int it = 0; it < 8; it++) {
        int idx = tid + it * 256;
        int rr = idx >> 4;
        int u = idx & 15;
        int n = n0 + rr;
        if (n < N_NODES) {
            size_t o = (size_t)n * 64 + ubase + u;
            float cn = Cs[rr * 17 + u];
            float hv = Hs[rr * 17 + u];
            g_c[o] = cn;
            h16_out[o] = __float2bfloat16_rn(hv);
            if (wf32) h_out[o] = hv;
        }
    }
}

// ---------------- head1: gnn = [agg|h] @ [W_rel|W_root]^T + b_rel (mma) ------
#define H1_SMEM 52480

__global__ void __launch_bounds__(256)
head1_kernel(const __nv_bfloat16* __restrict__ h16in, const float* __restrict__ b_rel) {
    extern __shared__ char smem[];
    const int tid = threadIdx.x;
    const int wid = tid >> 5;
    const int lane = tid & 31;
    const int n0 = blockIdx.x * 128;
    float* sb = reinterpret_cast<float*>(smem + 52224);

    {
        const uint4* Wh4 = reinterpret_cast<const uint4*>(g_Whb);
        #pragma unroll
        for (int it = 0; it < 4; it++) {
            int idx = tid + it * 256;
            int r = idx >> 4, c16 = idx & 15;
            *reinterpret_cast<uint4*>(smem + 34816 + r * 272 + c16 * 16) = Wh4[idx];
        }
    }
    #pragma unroll
    for (int it = 0; it < 8; it++) {
        int idx = tid + it * 256;
        int nl = idx >> 4, q = idx & 15;
        int n = n0 + nl;
        uint4 v = make_uint4(0u, 0u, 0u, 0u);
        if (n < N_NODES) {
            if (q < 8) v = reinterpret_cast<const uint4*>(g_agg16 + (size_t)n * 64)[q];
            else       v = reinterpret_cast<const uint4*>(h16in + (size_t)n * 64)[q - 8];
        }
        *reinterpret_cast<uint4*>(smem + nl * 272 + q * 16) = v;
    }
    if (tid < 128)
        *reinterpret_cast<uint4*>(smem + tid * 272 + 256) = make_uint4(0u, 0u, 0u, 0u);
    if (tid < 64) sb[tid] = b_rel[tid];
    __syncthreads();

    const int mw = wid >> 1;
    const int nw = wid & 1;
    const int mr = mw * 32;
    const int nc = nw * 32;
    const uint32_t sbase = smem_u32(smem);
    uint32_t aAddr = sbase + (mr + (lane & 15)) * 272 + ((lane >> 4) << 4);
    uint32_t bAddr = sbase + 34816u + (nc + (lane & 15)) * 272 + ((lane >> 4) << 4);

    float acc[2][4][4];
    #pragma unroll
    for (int mi = 0; mi < 2; mi++)
        #pragma unroll
        for (int nj = 0; nj < 4; nj++)
            #pragma unroll
            for (int e = 0; e < 4; e++) acc[mi][nj][e] = 0.f;

    #pragma unroll
    for (int ks = 0; ks < 8; ks++) {
        uint32_t a[2][4];
        ldsm_x4(a[0], aAddr + ks * 32);
        ldsm_x4(a[1], aAddr + 16 * 272 + ks * 32);
        uint32_t b[2][4];
        ldsm_x4(b[0], bAddr + ks * 32);
        ldsm_x4(b[1], bAddr + 16 * 272 + ks * 32);
        #pragma unroll
        for (int mi = 0; mi < 2; mi++)
            #pragma unroll
            for (int nj2 = 0; nj2 < 4; nj2++) {
                int nj = nj2 >> 1, hi = nj2 & 1;
                mma_bf16(acc[mi][nj2], a[mi], b[nj][hi], b[nj][hi + 2]);
            }
    }
    __syncthreads();

    float* Gs = reinterpret_cast<float*>(smem);
    #pragma unroll
    for (int mi = 0; mi < 2; mi++) {
        int row = mr + mi * 16 + (lane >> 2);
        #pragma unroll
        for (int nj2 = 0; nj2 < 4; nj2++) {
            int c = nc + nj2 * 8 + (lane & 3) * 2;
            *reinterpret_cast<float2*>(&Gs[row * 68 + c]) =
                make_float2(acc[mi][nj2][0] + sb[c], acc[mi][nj2][1] + sb[c + 1]);
            *reinterpret_cast<float2*>(&Gs[(row + 8) * 68 + c]) =
                make_float2(acc[mi][nj2][2] + sb[c], acc[mi][nj2][3] + sb[c + 1]);
        }
    }
    __syncthreads();

    #pragma unroll
    for (int it = 0; it < 32; it++) {
        int idx = tid + it * 256;
        int rr = idx >> 6, u = idx & 63;
        int n = n0 + rr;
        if (n < N_NODES) g_gnn[(size_t)n * 64 + u] = Gs[rr * 68 + u];
    }
}

// ---------------- head2: fused layernorm + MLP + out-projection (mma) --------
#define H2_SMEM 90880

__global__ void __launch_bounds__(256)
head2_kernel(const float* __restrict__ hfin, const float* __restrict__ b1,
             const float* __restrict__ b2, const float* __restrict__ Wout,
             const float* __restrict__ bout, float* __restrict__ out) {
    extern __shared__ char smem[];
    const int tid = threadIdx.x;
    const int wid = tid >> 5;
    const int lane = tid & 31;
    const int n0 = blockIdx.x * 128;
    float* sb1 = reinterpret_cast<float*>(smem + 89088);
    float* sb2 = reinterpret_cast<float*>(smem + 89344);
    float* sWout = reinterpret_cast<float*>(smem + 89856);
    float* sdot = reinterpret_cast<float*>(smem + 90368);

    #pragma unroll
    for (int it = 0; it < 32; it++) {
        int idx = tid + it * 256;
        int nl = idx >> 6, cp = idx & 63;
        int c = cp * 2;
        int n = n0 + nl;
        float2 v = make_float2(0.f, 0.f);
        if (n < N_NODES) {
            v = (cp < 32)
                ? reinterpret_cast<const float2*>(hfin)[(size_t)n * 32 + cp]
                : reinterpret_cast<const float2*>(g_gnn)[(size_t)n * 32 + cp - 32];
        }
        float2 nv = make_float2(v.x * g_scale[c] + g_shift[c],
                                v.y * g_scale[c + 1] + g_shift[c + 1]);
        *reinterpret_cast<__nv_bfloat162*>(smem + nl * 272 + c * 2) =
            __float22bfloat162_rn(nv);
    }
    if (tid < 128)
        *reinterpret_cast<uint4*>(smem + tid * 272 + 256) = make_uint4(0u, 0u, 0u, 0u);
    {
        const uint4* W14 = reinterpret_cast<const uint4*>(g_W1b);
        #pragma unroll
        for (int it = 0; it < 4; it++) {
            int idx = tid + it * 256;
            int r = idx >> 4, c16 = idx & 15;
            *reinterpret_cast<uint4*>(smem + 34816 + r * 272 + c16 * 16) = W14[idx];
        }
        const uint4* W24 = reinterpret_cast<const uint4*>(g_W2b);
        #pragma unroll
        for (int it = 0; it < 4; it++) {
            int idx = tid + it * 256;
            int r = idx >> 3, c8 = idx & 7;
            *reinterpret_cast<uint4*>(smem + 70656 + r * 144 + c8 * 16) = W24[idx];
        }
    }
    if (tid < 64) sb1[tid] = b1[tid];
    if (tid < 128) {
        sb2[tid] = b2[tid];
        sWout[tid] = Wout[tid];
        sdot[tid] = 0.f;
    }
    __syncthreads();

    const int mw = wid >> 1;
    const int nw = wid & 1;
    const int mr = mw * 32;
    const uint32_t sbase = smem_u32(smem);

    {
        const int nc = nw * 32;
        uint32_t aAddr = sbase + (mr + (lane & 15)) * 272 + ((lane >> 4) << 4);
        uint32_t bAddr = sbase + 34816u + (nc + (lane & 15)) * 272 + ((lane >> 4) << 4);
        float acc1[2][4][4];
        #pragma unroll
        for (int mi = 0; mi < 2; mi++)
            #pragma unroll
            for (int nj = 0; nj < 4; nj++)
                #pragma unroll
                for (int e = 0; e < 4; e++) acc1[mi][nj][e] = 0.f;
        #pragma unroll
        for (int ks = 0; ks < 8; ks++) {
            uint32_t a[2][4];
            ldsm_x4(a[0], aAddr + ks * 32);
            ldsm_x4(a[1], aAddr + 16 * 272 + ks * 32);
            uint32_t b[2][4];
            ldsm_x4(b[0], bAddr + ks * 32);
            ldsm_x4(b[1], bAddr + 16 * 272 + ks * 32);
            #pragma unroll
            for (int mi = 0; mi < 2; mi++)
                #pragma unroll
                for (int nj2 = 0; nj2 < 4; nj2++) {
                    int nj = nj2 >> 1, hi = nj2 & 1;
                    mma_bf16(acc1[mi][nj2], a[mi], b[nj][hi], b[nj][hi + 2]);
                }
        }
        #pragma unroll
        for (int mi = 0; mi < 2; mi++) {
            int row = mr + mi * 16 + (lane >> 2);
            #pragma unroll
            for (int nj2 = 0; nj2 < 4; nj2++) {
                int c = nc + nj2 * 8 + (lane & 3) * 2;
                float v0 = fmaxf(acc1[mi][nj2][0] + sb1[c], 0.f);
                float v1 = fmaxf(acc1[mi][nj2][1] + sb1[c + 1], 0.f);
                float v2 = fmaxf(acc1[mi][nj2][2] + sb1[c], 0.f);
                float v3 = fmaxf(acc1[mi][nj2][3] + sb1[c + 1], 0.f);
                *reinterpret_cast<__nv_bfloat162*>(smem + 52224 + row * 144 + c * 2) =
                    __float22bfloat162_rn(make_float2(v0, v1));
                *reinterpret_cast<__nv_bfloat162*>(smem + 52224 + (row + 8) * 144 + c * 2) =
                    __float22bfloat162_rn(make_float2(v2, v3));
            }
        }
    }
    __syncthreads();

    {
        const int nc = nw * 64;
        uint32_t aAddr = sbase + 52224u + (mr + (lane & 15)) * 144 + ((lane >> 4) << 4);
        uint32_t bAddr = sbase + 70656u + (nc + (lane & 15)) * 144 + ((lane >> 4) << 4);
        float acc2[2][8][4];
        #pragma unroll
        for (int mi = 0; mi < 2; mi++)
            #pragma unroll
            for (int nj = 0; nj < 8; nj++)
                #pragma unroll
                for (int e = 0; e < 4; e++) acc2[mi][nj][e] = 0.f;
        #pragma unroll
        for (int ks = 0; ks < 4; ks++) {
            uint32_t a[2][4];
            ldsm_x4(a[0], aAddr + ks * 32);
            ldsm_x4(a[1], aAddr + 16 * 144 + ks * 32);
            uint32_t b[4][4];
            #pragma unroll
            for (int nj = 0; nj < 4; nj++)
                ldsm_x4(b[nj], bAddr + nj * 16 * 144 + ks * 32);
            #pragma unroll
            for (int mi = 0; mi < 2; mi++)
                #pragma unroll
                for (int nj2 = 0; nj2 < 8; nj2++) {
                    int nj = nj2 >> 1, hi = nj2 & 1;
                    mma_bf16(acc2[mi][nj2], a[mi], b[nj][hi], b[nj][hi + 2]);
                }
        }
        #pragma unroll
        for (int mi = 0; mi < 2; mi++) {
            float p0 = 0.f, p1 = 0.f;
            #pragma unroll
            for (int nj2 = 0; nj2 < 8; nj2++) {
                int c = nc + nj2 * 8 + (lane & 3) * 2;
                float w0 = sWout[c], w1 = sWout[c + 1];
                p0 += fmaxf(acc2[mi][nj2][0] + sb2[c], 0.f) * w0
                    + fmaxf(acc2[mi][nj2][1] + sb2[c + 1], 0.f) * w1;
                p1 += fmaxf(acc2[mi][nj2][2] + sb2[c], 0.f) * w0
                    + fmaxf(acc2[mi][nj2][3] + sb2[c + 1], 0.f) * w1;
            }
            p0 += __shfl_xor_sync(0xFFFFFFFFu, p0, 1);
            p0 += __shfl_xor_sync(0xFFFFFFFFu, p0, 2);
            p1 += __shfl_xor_sync(0xFFFFFFFFu, p1, 1);
            p1 += __shfl_xor_sync(0xFFFFFFFFu, p1, 2);
            if ((lane & 3) == 0) {
                int row = mr + mi * 16 + (lane >> 2);
                atomicAdd(&sdot[row], p0);
                atomicAdd(&sdot[row + 8], p1);
            }
        }
    }
    __syncthreads();

    if (tid < 128) {
        int n = n0 + tid;
        if (n < N_NODES) {
            float s = sdot[tid] + bout[0];
            out[n] = 1.f / (1.f + __expf(-s));
        }
    }
}

// ---------------- per-feature stats over nodes ----------------
__global__ void stats_kernel(const float* __restrict__ h, const float* __restrict__ gnn) {
    int c = threadIdx.x & 127;
    int grp = threadIdx.x >> 7;
    int r0 = blockIdx.x * 256;
    int rend = min(r0 + 256, N_NODES);
    float s = 0.f, q = 0.f;
    for (int r = r0 + grp; r < rend; r += 2) {
        float v = (c < 64) ? h[(size_t)r * 64 + c] : gnn[(size_t)r * 64 + c - 64];
        s += v;
        q += v * v;
    }
    atomicAdd(&g_stats[c], s);
    atomicAdd(&g_stats[128 + c], q);
}

__global__ void finalize_stats(const float* __restrict__ gamma, const float* __restrict__ beta) {
    int c = threadIdx.x;
    float mean = g_stats[c] / (float)N_NODES;
    float var = g_stats[128 + c] / (float)N_NODES - mean * mean;
    float rstd = rsqrtf(var + 1e-5f);
    float sc = rstd * gamma[c];
    g_scale[c] = sc;
    g_shift[c] = beta[c] - mean * sc;
}

// ---------------- launch ----------------
extern "C" void kernel_launch(void* const* d_in, const int* in_sizes, int n_in,
                              void* d_out, int out_size) {
    const float* x      = (const float*)d_in[0];
    const void*  ei     = d_in[1];
    const float* W_ih   = (const float*)d_in[4];
    const float* W_hh   = (const float*)d_in[5];
    const float* b_ih   = (const float*)d_in[6];
    const float* b_hh   = (const float*)d_in[7];
    const float* W_rel  = (const float*)d_in[8];
    const float* b_rel  = (const float*)d_in[9];
    const float* W_root = (const float*)d_in[10];
    const float* gamma  = (const float*)d_in[11];
    const float* beta   = (const float*)d_in[12];
    const float* W1     = (const float*)d_in[13];
    const float* b1     = (const float*)d_in[14];
    const float* W2     = (const float*)d_in[15];
    const float* b2     = (const float*)d_in[16];
    const float* W_out  = (const float*)d_in[17];
    const float* b_out  = (const float*)d_in[18];

    float *hbuf, *gnn;
    __nv_bfloat16 *h16, *xT16;
    cudaGetSymbolAddress((void**)&hbuf, g_hbuf);
    cudaGetSymbolAddress((void**)&h16, g_h16);
    cudaGetSymbolAddress((void**)&gnn, g_gnn);
    cudaGetSymbolAddress((void**)&xT16, g_xT16);

    cudaFuncSetAttribute(gate_kernel, cudaFuncAttributeMaxDynamicSharedMemorySize, GATE_SMEM);
    cudaFuncSetAttribute(head1_kernel, cudaFuncAttributeMaxDynamicSharedMemorySize, H1_SMEM);
    cudaFuncSetAttribute(head2_kernel, cudaFuncAttributeMaxDynamicSharedMemorySize, H2_SMEM);

    const int scan_blocks = (N_NODES + 1023) / 1024;   // 98
    dim3 ggrid((N_NODES + 127) / 128, 4);

    // t=0 gate only needs zero_state + prep_weights + transpose_x.
    // (gate_kernel stays launch #4 for the fixed ncu window.)
    zero_state<<<512, 256>>>();
    prep_weights<<<256, 64>>>(W_ih, W_hh, b_ih, b_hh, W_rel, b_rel, W_root);
    transpose_x<<<N_NODES / 32, 256>>>(x);
    gate_kernel<<<ggrid, 256, GATE_SMEM>>>(xT16, h16, hbuf, h16 + (size_t)N_NODES * 64, 1, 0);

    detect_kernel<<<1, 256>>>((const unsigned int*)ei);
    prep_head<<<96, 256>>>(W1, W2, W_rel, W_root);
    hist2_kernel<<<512, 256>>>(ei);
    scan1_kernel<<<scan_blocks, 1024>>>();
    scan2_kernel<<<1, 128>>>(scan_blocks);
    scan3_kernel<<<(N_NODES + 255) / 256, 256>>>();
    scatter_kernel<<<512, 256>>>(ei);

    for (int t = 1; t < T_STEPS; t++) {
        const __nv_bfloat16* h16_in = h16 + (size_t)(t & 1) * N_NODES * 64;
        __nv_bfloat16* h16_out = h16 + (size_t)((t + 1) & 1) * N_NODES * 64;
        agg_kernel<<<(N_NODES * 32 + 255) / 256, 256>>>(h16_in);
        gate_kernel<<<ggrid, 256, GATE_SMEM>>>(
            xT16 + (size_t)t * N_NODES * 20, h16_in, hbuf, h16_out,
            0, t == T_STEPS - 1 ? 1 : 0);
    }
    // h16 buffer 1 = h at start of step 7 (used by gnn); hbuf = final h fp32.
    int n_tiles = (N_NODES + 127) / 128;   // 782
    head1_kernel<<<n_tiles, 256, H1_SMEM>>>(h16 + (size_t)N_NODES * 64, b_rel);
    stats_kernel<<<(N_NODES + 255) / 256, 256>>>(hbuf, gnn);
    finalize_stats<<<1, 128>>>(gamma, beta);
    head2_kernel<<<n_tiles, 256, H2_SMEM>>>(hbuf, b1, b2, W_out, b_out, (float*)d_out);
}

// round 12
// speedup vs baseline: 2.2580x; 1.1298x over previous
#include <cuda_runtime.h>
#include <cuda_bf16.h>
#include <math.h>
#include <cstdint>

#define N_NODES 100000
#define N_EDGES 1600000
#define T_STEPS 8
#define N_TILES 782   // ceil(N_NODES/128)

// ---------------- device scratch (no allocations allowed) ----------------
__device__ float g_hbuf[N_NODES * 64];                     // fp32 final h (t=7 only)
__device__ __nv_bfloat16 g_h16[2 * N_NODES * 64];          // bf16 h double buffer
__device__ __align__(16) float g_cperm[N_TILES * 4 * 256 * 8];  // c in fragment order
__device__ __nv_bfloat16 g_agg16[N_NODES * 64];
__device__ float g_gnn[N_NODES * 64];
__device__ __align__(16) __nv_bfloat16 g_xT16[T_STEPS * N_NODES * 20];  // [t][n][20]
__device__ __align__(16) __nv_bfloat16 g_Wb[256 * 160];    // fused gate weights (interleaved rows)
__device__ __align__(16) __nv_bfloat16 g_W1b[64 * 128];
__device__ __align__(16) __nv_bfloat16 g_W2b[128 * 64];
__device__ __align__(16) __nv_bfloat16 g_Whb[64 * 128];    // [W_rel | W_root]
__device__ __align__(16) float g_bias[256];                // per-unit quads (i,f,g,o)
__device__ float g_stats[256];
__device__ float g_scale[128];
__device__ float g_shift[128];
__device__ int   g_deg4[4 * N_NODES];
__device__ int   g_cur4[4 * N_NODES];
__device__ int   g_offs[N_NODES + 1];
__device__ int   g_ssrc[N_EDGES];
__device__ int   g_bsums[128];
__device__ int   g_boffs[128];
__device__ int   g_is64;

// ---------------- mma/ldmatrix/cp.async helpers ----------------
__device__ __forceinline__ uint32_t smem_u32(const void* p) {
    uint32_t a;
    asm("{ .reg .u64 tmp; cvta.to.shared.u64 tmp, %1; cvt.u32.u64 %0, tmp; }"
        : "=r"(a) : "l"(p));
    return a;
}
__device__ __forceinline__ void ldsm_x4(uint32_t* r, uint32_t addr) {
    asm volatile("ldmatrix.sync.aligned.m8n8.x4.shared.b16 {%0,%1,%2,%3}, [%4];"
                 : "=r"(r[0]), "=r"(r[1]), "=r"(r[2]), "=r"(r[3]) : "r"(addr));
}
__device__ __forceinline__ void mma_bf16(float* d, const uint32_t* a,
                                         uint32_t b0, uint32_t b1) {
    asm volatile(
        "mma.sync.aligned.m16n8k16.row.col.f32.bf16.bf16.f32 "
        "{%0,%1,%2,%3}, {%4,%5,%6,%7}, {%8,%9}, {%0,%1,%2,%3};"
        : "+f"(d[0]), "+f"(d[1]), "+f"(d[2]), "+f"(d[3])
        : "r"(a[0]), "r"(a[1]), "r"(a[2]), "r"(a[3]), "r"(b0), "r"(b1));
}
__device__ __forceinline__ float fast_tanh(float x) {
    float y;
    asm("tanh.approx.f32 %0, %1;" : "=f"(y) : "f"(x));
    return y;
}
__device__ __forceinline__ float fast_sigmoid(float x) {
    return 0.5f * fast_tanh(0.5f * x) + 0.5f;
}
#define CP_ASYNC_16(dst, src) \
    asm volatile("cp.async.ca.shared.global [%0], [%1], 16;" :: "r"(dst), "l"(src))
#define CP_ASYNC_8S(dst, src, ssz) \
    asm volatile("cp.async.ca.shared.global [%0], [%1], 8, %2;" :: "r"(dst), "l"(src), "r"(ssz))
#define CP_ASYNC_COMMIT() asm volatile("cp.async.commit_group;" ::: "memory")
#define CP_ASYNC_WAIT0()  asm volatile("cp.async.wait_group 0;" ::: "memory")

// ---------------- small utility kernels ----------------
__global__ void zero_state() {
    int stride = gridDim.x * blockDim.x;
    int i0 = blockIdx.x * blockDim.x + threadIdx.x;
    for (int k = i0; k < 4 * N_NODES; k += stride) g_deg4[k] = 0;
    if (i0 < 256) g_stats[i0] = 0.f;
}

__global__ void detect_kernel(const unsigned int* __restrict__ w) {
    __shared__ unsigned int acc;
    if (threadIdx.x == 0) acc = 0u;
    __syncthreads();
    unsigned int v = 0u;
    for (int i = threadIdx.x; i < 2048; i += blockDim.x) v |= w[2 * i + 1];
    atomicOr(&acc, v);
    __syncthreads();
    if (threadIdx.x == 0) g_is64 = (acc == 0u) ? 1 : 0;
}

__device__ __forceinline__ int edge_val(const void* ei, long long idx) {
    if (g_is64) return (int)((const long long*)ei)[idx];
    return ((const int*)ei)[idx];
}

__global__ void hist2_kernel(const void* __restrict__ ei) {
    int stride = gridDim.x * blockDim.x;
    for (int e = blockIdx.x * blockDim.x + threadIdx.x; e < N_EDGES; e += stride) {
        int d = edge_val(ei, (long long)N_EDGES + e);
        atomicAdd(&g_deg4[(e & 3) * N_NODES + d], 1);
    }
}

__global__ void scan1_kernel() {
    __shared__ int warpsums[32];
    int tid = threadIdx.x, lane = tid & 31, wid = tid >> 5;
    int i = blockIdx.x * 1024 + tid;
    int v = 0;
    if (i < N_NODES)
        v = g_deg4[i] + g_deg4[N_NODES + i] + g_deg4[2 * N_NODES + i]
          + g_deg4[3 * N_NODES + i];
    int x = v;
    #pragma unroll
    for (int off = 1; off < 32; off <<= 1) {
        int y = __shfl_up_sync(0xFFFFFFFFu, x, off);
        if (lane >= off) x += y;
    }
    if (lane == 31) warpsums[wid] = x;
    __syncthreads();
    if (wid == 0) {
        int wv = warpsums[lane];
        #pragma unroll
        for (int off = 1; off < 32; off <<= 1) {
            int y = __shfl_up_sync(0xFFFFFFFFu, wv, off);
            if (lane >= off) wv += y;
        }
        warpsums[lane] = wv;
    }
    __syncthreads();
    int woff = (wid == 0) ? 0 : warpsums[wid - 1];
    if (i < N_NODES) g_offs[i] = x - v + woff;
    if (tid == 1023) g_bsums[blockIdx.x] = warpsums[31];
}

__global__ void scan2_kernel(int nblk) {
    __shared__ int warpsums[4];
    int tid = threadIdx.x, lane = tid & 31, wid = tid >> 5;
    int v = (tid < nblk) ? g_bsums[tid] : 0;
    int x = v;
    #pragma unroll
    for (int off = 1; off < 32; off <<= 1) {
        int y = __shfl_up_sync(0xFFFFFFFFu, x, off);
        if (lane >= off) x += y;
    }
    if (lane == 31) warpsums[wid] = x;
    __syncthreads();
    if (wid == 0 && lane < 4) {
        int wv = warpsums[lane];
        #pragma unroll
        for (int off = 1; off < 4; off <<= 1) {
            int y = __shfl_up_sync(0xFu, wv, off);
            if (lane >= off) wv += y;
        }
        warpsums[lane] = wv;
    }
    __syncthreads();
    int woff = (wid == 0) ? 0 : warpsums[wid - 1];
    int excl = x - v + woff;
    if (tid < nblk) g_boffs[tid] = excl;
    if (tid == nblk - 1) g_offs[N_NODES] = excl + v;
}

__global__ void scan3_kernel() {
    int i = blockIdx.x * blockDim.x + threadIdx.x;
    if (i >= N_NODES) return;
    int o = g_offs[i] + g_boffs[i >> 10];
    g_offs[i] = o;
    int d0 = g_deg4[i];
    int d1 = g_deg4[N_NODES + i];
    int d2 = g_deg4[2 * N_NODES + i];
    g_cur4[i] = o;
    g_cur4[N_NODES + i] = o + d0;
    g_cur4[2 * N_NODES + i] = o + d0 + d1;
    g_cur4[3 * N_NODES + i] = o + d0 + d1 + d2;
}

__global__ void scatter_kernel(const void* __restrict__ ei) {
    int stride = gridDim.x * blockDim.x;
    for (int e = blockIdx.x * blockDim.x + threadIdx.x; e < N_EDGES; e += stride) {
        int s = edge_val(ei, e);
        int d = edge_val(ei, (long long)N_EDGES + e);
        int p = atomicAdd(&g_cur4[(e & 3) * N_NODES + d], 1);
        g_ssrc[p] = s;
    }
}

// x (N, 30, 8) -> g_xT16[t][n][20] bf16, node-major, coalesced out.
__global__ void __launch_bounds__(256) transpose_x(const float* __restrict__ x) {
    __shared__ float sm[32 * 161];
    __shared__ __nv_bfloat16 so[8 * 32 * 20];   // [t][nl][j]
    int n0 = blockIdx.x * 32;
    #pragma unroll
    for (int w = 0; w < 20; w++) {
        int i = threadIdx.x + w * 256;
        int nl = i / 160, off = i - nl * 160;
        sm[nl * 161 + off] = x[(size_t)(n0 + nl) * 240 + 80 + off];
    }
    __syncthreads();
    #pragma unroll
    for (int w = 0; w < 20; w++) {
        int idx = threadIdx.x + w * 256;
        int nl = idx & 31;
        int p = idx >> 5;
        int t = p / 20, j = p - t * 20;
        so[(t * 32 + nl) * 20 + j] = __float2bfloat16_rn(sm[nl * 161 + j * 8 + t]);
    }
    __syncthreads();
    const uint32_t* sou = reinterpret_cast<const uint32_t*>(so);
    uint32_t* dst = reinterpret_cast<uint32_t*>(g_xT16);
    #pragma unroll
    for (int w = 0; w < 10; w++) {
        int idx = threadIdx.x + w * 256;           // 0..2559
        int t = idx / 320;
        int rem = idx - t * 320;
        dst[((size_t)t * N_NODES + n0) * 10 + rem] = sou[idx];
    }
}

// Fold GNN projection into gate weights; interleaved row layout:
// block16 = rp>>4, within = rp&15; within<8: (i,f) vl=within>>1 q=within&1;
// else (g,o). unit u = block16*4+vl; original row r = q*64+u.
__global__ void prep_weights(const float* __restrict__ W_ih, const float* __restrict__ W_hh,
                             const float* __restrict__ b_ih, const float* __restrict__ b_hh,
                             const float* __restrict__ W_rel, const float* __restrict__ b_rel,
                             const float* __restrict__ W_root) {
    int rp = blockIdx.x;
    int block16 = rp >> 4, within = rp & 15;
    int vl, q;
    if (within < 8) { vl = within >> 1; q = within & 1; }
    else            { vl = (within - 8) >> 1; q = 2 + ((within - 8) & 1); }
    int u = block16 * 4 + vl;
    int r = q * 64 + u;
    __shared__ float wg[64];
    int tid = threadIdx.x;  // 64 threads
    wg[tid] = W_ih[r * 84 + 20 + tid];
    __syncthreads();
    int c = tid;
    float m1 = 0.f, m2 = 0.f;
    #pragma unroll 8
    for (int j = 0; j < 64; j++) {
        float w = wg[j];
        m1 += w * W_rel[j * 64 + c];
        m2 += w * W_root[j * 64 + c];
    }
    m2 += W_hh[r * 64 + c];
    g_Wb[rp * 160 + 20 + c] = __float2bfloat16_rn(m1);
    g_Wb[rp * 160 + 84 + c] = __float2bfloat16_rn(m2);
    if (c < 20) g_Wb[rp * 160 + c] = __float2bfloat16_rn(W_ih[r * 84 + c]);
    if (c < 12) g_Wb[rp * 160 + 148 + c] = __float2bfloat16_rn(0.f);
    if (c == 0) {
        float s = b_ih[r] + b_hh[r];
        for (int j = 0; j < 64; j++) s += wg[j] * b_rel[j];
        g_bias[u * 4 + q] = s;
    }
}

// bf16 copies of head weights.
__global__ void prep_head(const float* __restrict__ W1, const float* __restrict__ W2,
                          const float* __restrict__ W_rel, const float* __restrict__ W_root) {
    int i = blockIdx.x * 256 + threadIdx.x;
    if (i < 8192) {
        g_W1b[i] = __float2bfloat16_rn(W1[i]);
    } else if (i < 16384) {
        g_W2b[i - 8192] = __float2bfloat16_rn(W2[i - 8192]);
    } else if (i < 24576) {
        int j = i - 16384;
        int o = j >> 7, k = j & 127;
        float v = (k < 64) ? W_rel[o * 64 + k] : W_root[o * 64 + k - 64];
        g_Whb[j] = __float2bfloat16_rn(v);
    }
}

// ---------------- aggregation: warp per dst node, bf16 gather ----------------
__global__ void agg_kernel(const __nv_bfloat16* __restrict__ h16) {
    int gw = (blockIdx.x * blockDim.x + threadIdx.x) >> 5;
    int lane = threadIdx.x & 31;
    if (gw >= N_NODES) return;
    int beg = g_offs[gw], end = g_offs[gw + 1];
    float2 acc = make_float2(0.f, 0.f);
    int e = beg;
    for (; e + 4 <= end; e += 4) {
        int s0 = g_ssrc[e], s1 = g_ssrc[e + 1], s2 = g_ssrc[e + 2], s3 = g_ssrc[e + 3];
        float2 v0 = __bfloat1622float2(
            *reinterpret_cast<const __nv_bfloat162*>(h16 + (size_t)s0 * 64 + lane * 2));
        float2 v1 = __bfloat1622float2(
            *reinterpret_cast<const __nv_bfloat162*>(h16 + (size_t)s1 * 64 + lane * 2));
        float2 v2 = __bfloat1622float2(
            *reinterpret_cast<const __nv_bfloat162*>(h16 + (size_t)s2 * 64 + lane * 2));
        float2 v3 = __bfloat1622float2(
            *reinterpret_cast<const __nv_bfloat162*>(h16 + (size_t)s3 * 64 + lane * 2));
        acc.x += (v0.x + v1.x) + (v2.x + v3.x);
        acc.y += (v0.y + v1.y) + (v2.y + v3.y);
    }
    for (; e < end; e++) {
        int s = g_ssrc[e];
        float2 v = __bfloat1622float2(
            *reinterpret_cast<const __nv_bfloat162*>(h16 + (size_t)s * 64 + lane * 2));
        acc.x += v.x;
        acc.y += v.y;
    }
    *reinterpret_cast<__nv_bfloat162*>(g_agg16 + (size_t)gw * 64 + lane * 2) =
        __float22bfloat162_rn(acc);
}

// ---------------- bf16 mma.sync gate GEMM + fused LSTM epilogue ----------------
// Tile: 128 nodes x 64 gate cols (grid y = 4). 8 warps = 4m x 2n, warp 32x32.
// smem: A[128][336B] @0 (43008), B[64][336B] @43008 (21504). 3 CTAs/SM.
// c kept in fragment-permuted gmem layout (private to this kernel).
#define GATE_SMEM 64512

__global__ void __launch_bounds__(256, 3)
gate_kernel(const __nv_bfloat16* __restrict__ xTt16,
            const __nv_bfloat16* __restrict__ h16_in,
            float* __restrict__ h_out, __nv_bfloat16* __restrict__ h16_out,
            int t0, int wf32) {
    extern __shared__ char smem[];
    const int tid = threadIdx.x;
    const int wid = tid >> 5;
    const int lane = tid & 31;
    const int n0 = blockIdx.x * 128;
    const int col0 = blockIdx.y * 64;    // gate-col base (0/64/128/192)
    const int ubase = col0 >> 2;         // unit base (16 units per CTA)
    const uint32_t sbase = smem_u32(smem);

    // ---- stage B via cp.async: 64 interleaved weight rows x 160 bf16 ----
    {
        const char* wsrc = reinterpret_cast<const char*>(g_Wb) + (size_t)col0 * 320;
        #pragma unroll
        for (int it = 0; it < 5; it++) {
            int idx = tid + it * 256;        // 0..1279 = r*20 + c
            int r = idx / 20;
            int c = idx - r * 20;
            CP_ASYNC_16(sbase + 43008u + r * 336 + c * 16, wsrc + r * 320 + c * 16);
        }
    }
    // ---- stage A: x bf16 (k 0..19): 8B cp.async (40B row is 8-aligned) ----
    {
        const char* xsrc = reinterpret_cast<const char*>(xTt16);
        #pragma unroll
        for (int it = 0; it < 3; it++) {
            int idx = tid + it * 256;        // need 640 = nl*5 + p
            if (idx < 640) {
                int nl = idx / 5;
                int p = idx - nl * 5;
                int n = n0 + nl;
                int ncl = (n < N_NODES) ? n : (N_NODES - 1);
                uint32_t ssz = (n < N_NODES) ? 8u : 0u;
                CP_ASYNC_8S(sbase + nl * 336 + p * 8, xsrc + (size_t)ncl * 40 + p * 8, ssz);
            }
        }
    }
    // ---- A: agg bf16 (k 20..83) + h bf16 (k 84..147): 8B cp.async with zfill ----
    {
        const char* asrc = reinterpret_cast<const char*>(g_agg16);
        const char* hsrc = reinterpret_cast<const char*>(h16_in);
        #pragma unroll
        for (int it = 0; it < 8; it++) {
            int idx = tid + it * 256;        // 0..2047 = nl*16 + cp
            int nl = idx >> 4;
            int cp = idx & 15;
            int n = n0 + nl;
            int ncl = (n < N_NODES) ? n : (N_NODES - 1);
            uint32_t ssz = (!t0 && n < N_NODES) ? 8u : 0u;
            CP_ASYNC_8S(sbase + nl * 336 + 40 + cp * 8, asrc + (size_t)ncl * 128 + cp * 8, ssz);
            CP_ASYNC_8S(sbase + nl * 336 + 168 + cp * 8, hsrc + (size_t)ncl * 128 + cp * 8, ssz);
        }
    }
    // ---- A: zero pad (k 148..167) plain stores ----
    #pragma unroll
    for (int it = 0; it < 3; it++) {
        int idx = tid + it * 256;
        if (idx < 640) {
            int nl = idx / 5;
            int p = idx - nl * 5;
            *reinterpret_cast<uint2*>(smem + nl * 336 + 296 + p * 8) = make_uint2(0u, 0u);
        }
    }
    CP_ASYNC_COMMIT();
    CP_ASYNC_WAIT0();
    __syncthreads();

    // ---- mma mainloop: warp tile 32 rows x 32 cols ----
    const int mw = wid >> 1;                 // 0..3
    const int nw = wid & 1;                  // 0..1
    const int mr = mw * 32;
    const int ncw = nw * 32;                 // col within CTA tile (0 or 32)
    uint32_t aAddr = sbase + (mr + (lane & 15)) * 336 + ((lane >> 4) << 4);
    uint32_t bAddr = sbase + 43008u + (ncw + (lane & 15)) * 336 + ((lane >> 4) << 4);

    float acc[2][4][4];
    #pragma unroll
    for (int mi = 0; mi < 2; mi++)
        #pragma unroll
        for (int nj = 0; nj < 4; nj++)
            #pragma unroll
            for (int e = 0; e < 4; e++) acc[mi][nj][e] = 0.f;

    #pragma unroll
    for (int ks = 0; ks < 10; ks++) {
        uint32_t a[2][4];
        ldsm_x4(a[0], aAddr + ks * 32);
        ldsm_x4(a[1], aAddr + 16 * 336 + ks * 32);
        uint32_t b[2][4];
        ldsm_x4(b[0], bAddr + ks * 32);
        ldsm_x4(b[1], bAddr + 16 * 336 + ks * 32);
        #pragma unroll
        for (int mi = 0; mi < 2; mi++)
            #pragma unroll
            for (int nj2 = 0; nj2 < 4; nj2++) {
                int nj = nj2 >> 1, hi = nj2 & 1;
                mma_bf16(acc[mi][nj2], a[mi], b[nj][hi], b[nj][hi + 2]);
            }
    }
    __syncthreads();

    // ---- c fragments: direct gmem <-> registers (fragment-permuted layout) ----
    float* cptr = g_cperm + (((size_t)(blockIdx.x * 4 + blockIdx.y)) * 256 + tid) * 8;
    float creg[8];
    if (!t0) {
        float4 ca = *reinterpret_cast<const float4*>(cptr);
        float4 cb = *reinterpret_cast<const float4*>(cptr + 4);
        creg[0] = ca.x; creg[1] = ca.y; creg[2] = ca.z; creg[3] = ca.w;
        creg[4] = cb.x; creg[5] = cb.y; creg[6] = cb.z; creg[7] = cb.w;
    } else {
        #pragma unroll
        for (int i = 0; i < 8; i++) creg[i] = 0.f;
    }

    // ---- repurpose smem: Hs fp32 [128][18] @0, sb4[16] float4 @9216 ----
    float* Hs = reinterpret_cast<float*>(smem);
    float4* sb4 = reinterpret_cast<float4*>(smem + 9216);
    if (tid < 16)
        sb4[tid] = reinterpret_cast<const float4*>(g_bias)[ubase + tid];
    __syncthreads();

    // ---- fused LSTM epilogue (shuffle-free; c in registers) ----
    const int vl = lane & 3;
    #pragma unroll
    for (int mi = 0; mi < 2; mi++) {
        int r = mr + mi * 16 + (lane >> 2);
        #pragma unroll
        for (int b = 0; b < 2; b++) {
            int u = nw * 8 + b * 4 + vl;     // unit within CTA (0..15)
            float4 bq = sb4[u];
            int ci = mi * 4 + b * 2;
            {
                float ig = acc[mi][2 * b][0] + bq.x;
                float fg = acc[mi][2 * b][1] + bq.y;
                float gg = acc[mi][2 * b + 1][0] + bq.z;
                float og = acc[mi][2 * b + 1][1] + bq.w;
                float si = fast_sigmoid(ig), sf = fast_sigmoid(fg);
                float so = fast_sigmoid(og), tg = fast_tanh(gg);
                float cn = sf * creg[ci] + si * tg;
                creg[ci] = cn;
                Hs[r * 18 + u] = so * fast_tanh(cn);
            }
            {
                float ig = acc[mi][2 * b][2] + bq.x;
                float fg = acc[mi][2 * b][3] + bq.y;
                float gg = acc[mi][2 * b + 1][2] + bq.z;
                float og = acc[mi][2 * b + 1][3] + bq.w;
                float si = fast_sigmoid(ig), sf = fast_sigmoid(fg);
                float so = fast_sigmoid(og), tg = fast_tanh(gg);
                float cn = sf * creg[ci + 1] + si * tg;
                creg[ci + 1] = cn;
                Hs[(r + 8) * 18 + u] = so * fast_tanh(cn);
            }
        }
    }
    // store c fragments back
    *reinterpret_cast<float4*>(cptr) = make_float4(creg[0], creg[1], creg[2], creg[3]);
    *reinterpret_cast<float4*>(cptr + 4) = make_float4(creg[4], creg[5], creg[6], creg[7]);
    __syncthreads();

    // ---- coalesced h writeback ----
    #pragma unroll
    for (int it = 0; it < 4; it++) {
        int idx = tid + it * 256;            // 0..1023 = rr*8 + up
        int rr = idx >> 3;
        int up = idx & 7;
        int n = n0 + rr;
        if (n < N_NODES) {
            float2 hv = *reinterpret_cast<const float2*>(&Hs[rr * 18 + up * 2]);
            size_t o = (size_t)n * 64 + ubase + up * 2;
            *reinterpret_cast<__nv_bfloat162*>(h16_out + o) = __float22bfloat162_rn(hv);
            if (wf32) *reinterpret_cast<float2*>(h_out + o) = hv;
        }
    }
}

// ---------------- head1: gnn = [agg|h] @ [W_rel|W_root]^T + b_rel (mma) ------
#define H1_SMEM 52480

__global__ void __launch_bounds__(256)
head1_kernel(const __nv_bfloat16* __restrict__ h16in, const float* __restrict__ b_rel) {
    extern __shared__ char smem[];
    const int tid = threadIdx.x;
    const int wid = tid >> 5;
    const int lane = tid & 31;
    const int n0 = blockIdx.x * 128;
    float* sb = reinterpret_cast<float*>(smem + 52224);

    {
        const uint4* Wh4 = reinterpret_cast<const uint4*>(g_Whb);
        #pragma unroll
        for (int it = 0; it < 4; it++) {
            int idx = tid + it * 256;
            int r = idx >> 4, c16 = idx & 15;
            *reinterpret_cast<uint4*>(smem + 34816 + r * 272 + c16 * 16) = Wh4[idx];
        }
    }
    #pragma unroll
    for (int it = 0; it < 8; it++) {
        int idx = tid + it * 256;
        int nl = idx >> 4, q = idx & 15;
        int n = n0 + nl;
        uint4 v = make_uint4(0u, 0u, 0u, 0u);
        if (n < N_NODES) {
            if (q < 8) v = reinterpret_cast<const uint4*>(g_agg16 + (size_t)n * 64)[q];
            else       v = reinterpret_cast<const uint4*>(h16in + (size_t)n * 64)[q - 8];
        }
        *reinterpret_cast<uint4*>(smem + nl * 272 + q * 16) = v;
    }
    if (tid < 128)
        *reinterpret_cast<uint4*>(smem + tid * 272 + 256) = make_uint4(0u, 0u, 0u, 0u);
    if (tid < 64) sb[tid] = b_rel[tid];
    __syncthreads();

    const int mw = wid >> 1;
    const int nw = wid & 1;
    const int mr = mw * 32;
    const int nc = nw * 32;
    const uint32_t sbase = smem_u32(smem);
    uint32_t aAddr = sbase + (mr + (lane & 15)) * 272 + ((lane >> 4) << 4);
    uint32_t bAddr = sbase + 34816u + (nc + (lane & 15)) * 272 + ((lane >> 4) << 4);

    float acc[2][4][4];
    #pragma unroll
    for (int mi = 0; mi < 2; mi++)
        #pragma unroll
        for (int nj = 0; nj < 4; nj++)
            #pragma unroll
            for (int e = 0; e < 4; e++) acc[mi][nj][e] = 0.f;

    #pragma unroll
    for (int ks = 0; ks < 8; ks++) {
        uint32_t a[2][4];
        ldsm_x4(a[0], aAddr + ks * 32);
        ldsm_x4(a[1], aAddr + 16 * 272 + ks * 32);
        uint32_t b[2][4];
        ldsm_x4(b[0], bAddr + ks * 32);
        ldsm_x4(b[1], bAddr + 16 * 272 + ks * 32);
        #pragma unroll
        for (int mi = 0; mi < 2; mi++)
            #pragma unroll
            for (int nj2 = 0; nj2 < 4; nj2++) {
                int nj = nj2 >> 1, hi = nj2 & 1;
                mma_bf16(acc[mi][nj2], a[mi], b[nj][hi], b[nj][hi + 2]);
            }
    }
    __syncthreads();

    float* Gs = reinterpret_cast<float*>(smem);
    #pragma unroll
    for (int mi = 0; mi < 2; mi++) {
        int row = mr + mi * 16 + (lane >> 2);
        #pragma unroll
        for (int nj2 = 0; nj2 < 4; nj2++) {
            int c = nc + nj2 * 8 + (lane & 3) * 2;
            *reinterpret_cast<float2*>(&Gs[row * 68 + c]) =
                make_float2(acc[mi][nj2][0] + sb[c], acc[mi][nj2][1] + sb[c + 1]);
            *reinterpret_cast<float2*>(&Gs[(row + 8) * 68 + c]) =
                make_float2(acc[mi][nj2][2] + sb[c], acc[mi][nj2][3] + sb[c + 1]);
        }
    }
    __syncthreads();

    #pragma unroll
    for (int it = 0; it < 32; it++) {
        int idx = tid + it * 256;
        int rr = idx >> 6, u = idx & 63;
        int n = n0 + rr;
        if (n < N_NODES) g_gnn[(size_t)n * 64 + u] = Gs[rr * 68 + u];
    }
}

// ---------------- head2: fused layernorm + MLP + out-projection (mma) --------
#define H2_SMEM 90880

__global__ void __launch_bounds__(256)
head2_kernel(const float* __restrict__ hfin, const float* __restrict__ b1,
             const float* __restrict__ b2, const float* __restrict__ Wout,
             const float* __restrict__ bout, float* __restrict__ out) {
    extern __shared__ char smem[];
    const int tid = threadIdx.x;
    const int wid = tid >> 5;
    const int lane = tid & 31;
    const int n0 = blockIdx.x * 128;
    float* sb1 = reinterpret_cast<float*>(smem + 89088);
    float* sb2 = reinterpret_cast<float*>(smem + 89344);
    float* sWout = reinterpret_cast<float*>(smem + 89856);
    float* sdot = reinterpret_cast<float*>(smem + 90368);

    #pragma unroll
    for (int it = 0; it < 32; it++) {
        int idx = tid + it * 256;
        int nl = idx >> 6, cp = idx & 63;
        int c = cp * 2;
        int n = n0 + nl;
        float2 v = make_float2(0.f, 0.f);
        if (n < N_NODES) {
            v = (cp < 32)
                ? reinterpret_cast<const float2*>(hfin)[(size_t)n * 32 + cp]
                : reinterpret_cast<const float2*>(g_gnn)[(size_t)n * 32 + cp - 32];
        }
        float2 nv = make_float2(v.x * g_scale[c] + g_shift[c],
                                v.y * g_scale[c + 1] + g_shift[c + 1]);
        *reinterpret_cast<__nv_bfloat162*>(smem + nl * 272 + c * 2) =
            __float22bfloat162_rn(nv);
    }
    if (tid < 128)
        *reinterpret_cast<uint4*>(smem + tid * 272 + 256) = make_uint4(0u, 0u, 0u, 0u);
    {
        const uint4* W14 = reinterpret_cast<const uint4*>(g_W1b);
        #pragma unroll
        for (int it = 0; it < 4; it++) {
            int idx = tid + it * 256;
            int r = idx >> 4, c16 = idx & 15;
            *reinterpret_cast<uint4*>(smem + 34816 + r * 272 + c16 * 16) = W14[idx];
        }
        const uint4* W24 = reinterpret_cast<const uint4*>(g_W2b);
        #pragma unroll
        for (int it = 0; it < 4; it++) {
            int idx = tid + it * 256;
            int r = idx >> 3, c8 = idx & 7;
            *reinterpret_cast<uint4*>(smem + 70656 + r * 144 + c8 * 16) = W24[idx];
        }
    }
    if (tid < 64) sb1[tid] = b1[tid];
    if (tid < 128) {
        sb2[tid] = b2[tid];
        sWout[tid] = Wout[tid];
        sdot[tid] = 0.f;
    }
    __syncthreads();

    const int mw = wid >> 1;
    const int nw = wid & 1;
    const int mr = mw * 32;
    const uint32_t sbase = smem_u32(smem);

    {
        const int nc = nw * 32;
        uint32_t aAddr = sbase + (mr + (lane & 15)) * 272 + ((lane >> 4) << 4);
        uint32_t bAddr = sbase + 34816u + (nc + (lane & 15)) * 272 + ((lane >> 4) << 4);
        float acc1[2][4][4];
        #pragma unroll
        for (int mi = 0; mi < 2; mi++)
            #pragma unroll
            for (int nj = 0; nj < 4; nj++)
                #pragma unroll
                for (int e = 0; e < 4; e++) acc1[mi][nj][e] = 0.f;
        #pragma unroll
        for (int ks = 0; ks < 8; ks++) {
            uint32_t a[2][4];
            ldsm_x4(a[0], aAddr + ks * 32);
            ldsm_x4(a[1], aAddr + 16 * 272 + ks * 32);
            uint32_t b[2][4];
            ldsm_x4(b[0], bAddr + ks * 32);
            ldsm_x4(b[1], bAddr + 16 * 272 + ks * 32);
            #pragma unroll
            for (int mi = 0; mi < 2; mi++)
                #pragma unroll
                for (int nj2 = 0; nj2 < 4; nj2++) {
                    int nj = nj2 >> 1, hi = nj2 & 1;
                    mma_bf16(acc1[mi][nj2], a[mi], b[nj][hi], b[nj][hi + 2]);
                }
        }
        #pragma unroll
        for (int mi = 0; mi < 2; mi++) {
            int row = mr + mi * 16 + (lane >> 2);
            #pragma unroll
            for (int nj2 = 0; nj2 < 4; nj2++) {
                int c = nc + nj2 * 8 + (lane & 3) * 2;
                float v0 = fmaxf(acc1[mi][nj2][0] + sb1[c], 0.f);
                float v1 = fmaxf(acc1[mi][nj2][1] + sb1[c + 1], 0.f);
                float v2 = fmaxf(acc1[mi][nj2][2] + sb1[c], 0.f);
                float v3 = fmaxf(acc1[mi][nj2][3] + sb1[c + 1], 0.f);
                *reinterpret_cast<__nv_bfloat162*>(smem + 52224 + row * 144 + c * 2) =
                    __float22bfloat162_rn(make_float2(v0, v1));
                *reinterpret_cast<__nv_bfloat162*>(smem + 52224 + (row + 8) * 144 + c * 2) =
                    __float22bfloat162_rn(make_float2(v2, v3));
            }
        }
    }
    __syncthreads();

    {
        const int nc = nw * 64;
        uint32_t aAddr = sbase + 52224u + (mr + (lane & 15)) * 144 + ((lane >> 4) << 4);
        uint32_t bAddr = sbase + 70656u + (nc + (lane & 15)) * 144 + ((lane >> 4) << 4);
        float acc2[2][8][4];
        #pragma unroll
        for (int mi = 0; mi < 2; mi++)
            #pragma unroll
            for (int nj = 0; nj < 8; nj++)
                #pragma unroll
                for (int e = 0; e < 4; e++) acc2[mi][nj][e] = 0.f;
        #pragma unroll
        for (int ks = 0; ks < 4; ks++) {
            uint32_t a[2][4];
            ldsm_x4(a[0], aAddr + ks * 32);
            ldsm_x4(a[1], aAddr + 16 * 144 + ks * 32);
            uint32_t b[4][4];
            #pragma unroll
            for (int nj = 0; nj < 4; nj++)
                ldsm_x4(b[nj], bAddr + nj * 16 * 144 + ks * 32);
            #pragma unroll
            for (int mi = 0; mi < 2; mi++)
                #pragma unroll
                for (int nj2 = 0; nj2 < 8; nj2++) {
                    int nj = nj2 >> 1, hi = nj2 & 1;
                    mma_bf16(acc2[mi][nj2], a[mi], b[nj][hi], b[nj][hi + 2]);
                }
        }
        #pragma unroll
        for (int mi = 0; mi < 2; mi++) {
            float p0 = 0.f, p1 = 0.f;
            #pragma unroll
            for (int nj2 = 0; nj2 < 8; nj2++) {
                int c = nc + nj2 * 8 + (lane & 3) * 2;
                float w0 = sWout[c], w1 = sWout[c + 1];
                p0 += fmaxf(acc2[mi][nj2][0] + sb2[c], 0.f) * w0
                    + fmaxf(acc2[mi][nj2][1] + sb2[c + 1], 0.f) * w1;
                p1 += fmaxf(acc2[mi][nj2][2] + sb2[c], 0.f) * w0
                    + fmaxf(acc2[mi][nj2][3] + sb2[c + 1], 0.f) * w1;
            }
            p0 += __shfl_xor_sync(0xFFFFFFFFu, p0, 1);
            p0 += __shfl_xor_sync(0xFFFFFFFFu, p0, 2);
            p1 += __shfl_xor_sync(0xFFFFFFFFu, p1, 1);
            p1 += __shfl_xor_sync(0xFFFFFFFFu, p1, 2);
            if ((lane & 3) == 0) {
                int row = mr + mi * 16 + (lane >> 2);
                atomicAdd(&sdot[row], p0);
                atomicAdd(&sdot[row + 8], p1);
            }
        }
    }
    __syncthreads();

    if (tid < 128) {
        int n = n0 + tid;
        if (n < N_NODES) {
            float s = sdot[tid] + bout[0];
            out[n] = 1.f / (1.f + __expf(-s));
        }
    }
}

// ---------------- per-feature stats over nodes ----------------
__global__ void stats_kernel(const float* __restrict__ h, const float* __restrict__ gnn) {
    int c = threadIdx.x & 127;
    int grp = threadIdx.x >> 7;
    int r0 = blockIdx.x * 256;
    int rend = min(r0 + 256, N_NODES);
    float s = 0.f, q = 0.f;
    for (int r = r0 + grp; r < rend; r += 2) {
        float v = (c < 64) ? h[(size_t)r * 64 + c] : gnn[(size_t)r * 64 + c - 64];
        s += v;
        q += v * v;
    }
    atomicAdd(&g_stats[c], s);
    atomicAdd(&g_stats[128 + c], q);
}

__global__ void finalize_stats(const float* __restrict__ gamma, const float* __restrict__ beta) {
    int c = threadIdx.x;
    float mean = g_stats[c] / (float)N_NODES;
    float var = g_stats[128 + c] / (float)N_NODES - mean * mean;
    float rstd = rsqrtf(var + 1e-5f);
    float sc = rstd * gamma[c];
    g_scale[c] = sc;
    g_shift[c] = beta[c] - mean * sc;
}

// ---------------- launch ----------------
extern "C" void kernel_launch(void* const* d_in, const int* in_sizes, int n_in,
                              void* d_out, int out_size) {
    const float* x      = (const float*)d_in[0];
    const void*  ei     = d_in[1];
    const float* W_ih   = (const float*)d_in[4];
    const float* W_hh   = (const float*)d_in[5];
    const float* b_ih   = (const float*)d_in[6];
    const float* b_hh   = (const float*)d_in[7];
    const float* W_rel  = (const float*)d_in[8];
    const float* b_rel  = (const float*)d_in[9];
    const float* W_root = (const float*)d_in[10];
    const float* gamma  = (const float*)d_in[11];
    const float* beta   = (const float*)d_in[12];
    const float* W1     = (const float*)d_in[13];
    const float* b1     = (const float*)d_in[14];
    const float* W2     = (const float*)d_in[15];
    const float* b2     = (const float*)d_in[16];
    const float* W_out  = (const float*)d_in[17];
    const float* b_out  = (const float*)d_in[18];

    float *hbuf, *gnn;
    __nv_bfloat16 *h16, *xT16;
    cudaGetSymbolAddress((void**)&hbuf, g_hbuf);
    cudaGetSymbolAddress((void**)&h16, g_h16);
    cudaGetSymbolAddress((void**)&gnn, g_gnn);
    cudaGetSymbolAddress((void**)&xT16, g_xT16);

    cudaFuncSetAttribute(gate_kernel, cudaFuncAttributeMaxDynamicSharedMemorySize, GATE_SMEM);
    cudaFuncSetAttribute(head1_kernel, cudaFuncAttributeMaxDynamicSharedMemorySize, H1_SMEM);
    cudaFuncSetAttribute(head2_kernel, cudaFuncAttributeMaxDynamicSharedMemorySize, H2_SMEM);

    const int scan_blocks = (N_NODES + 1023) / 1024;   // 98
    dim3 ggrid(N_TILES, 4);

    // t=0 gate only needs zero_state + prep_weights + transpose_x.
    // (gate_kernel stays launch #4 for the fixed ncu window.)
    zero_state<<<512, 256>>>();
    prep_weights<<<256, 64>>>(W_ih, W_hh, b_ih, b_hh, W_rel, b_rel, W_root);
    transpose_x<<<N_NODES / 32, 256>>>(x);
    gate_kernel<<<ggrid, 256, GATE_SMEM>>>(xT16, h16, hbuf, h16 + (size_t)N_NODES * 64, 1, 0);

    detect_kernel<<<1, 256>>>((const unsigned int*)ei);
    prep_head<<<96, 256>>>(W1, W2, W_rel, W_root);
    hist2_kernel<<<512, 256>>>(ei);
    scan1_kernel<<<scan_blocks, 1024>>>();
    scan2_kernel<<<1, 128>>>(scan_blocks);
    scan3_kernel<<<(N_NODES + 255) / 256, 256>>>();
    scatter_kernel<<<512, 256>>>(ei);

    for (int t = 1; t < T_STEPS; t++) {
        const __nv_bfloat16* h16_in = h16 + (size_t)(t & 1) * N_NODES * 64;
        __nv_bfloat16* h16_out = h16 + (size_t)((t + 1) & 1) * N_NODES * 64;
        agg_kernel<<<(N_NODES * 32 + 255) / 256, 256>>>(h16_in);
        gate_kernel<<<ggrid, 256, GATE_SMEM>>>(
            xT16 + (size_t)t * N_NODES * 20, h16_in, hbuf, h16_out,
            0, t == T_STEPS - 1 ? 1 : 0);
    }
    // h16 buffer 1 = h at start of step 7 (used by gnn); hbuf = final h fp32.
    head1_kernel<<<N_TILES, 256, H1_SMEM>>>(h16 + (size_t)N_NODES * 64, b_rel);
    stats_kernel<<<(N_NODES + 255) / 256, 256>>>(hbuf, gnn);
    finalize_stats<<<1, 128>>>(gamma, beta);
    head2_kernel<<<N_TILES, 256, H2_SMEM>>>(hbuf, b1, b2, W_out, b_out, (float*)d_out);
}

// round 14
// speedup vs baseline: 2.2594x; 1.0006x over previous
#include <cuda_runtime.h>
#include <cuda_bf16.h>
#include <math.h>
#include <cstdint>

#define N_NODES 100000
#define N_EDGES 1600000
#define T_STEPS 8
#define N_TILES 782   // ceil(N_NODES/128)

// ---------------- device scratch (no allocations allowed) ----------------
__device__ float g_hbuf[N_NODES * 64];                     // fp32 final h (t=7 only)
// interleaved per-node record: [0:64)=agg, [64:128)=h ; double buffered
__device__ __align__(16) __nv_bfloat16 g_ah[2 * N_NODES * 128];
__device__ __align__(16) float g_cperm[N_TILES * 4 * 256 * 8];  // c in fragment order
__device__ float g_gnn[N_NODES * 64];
__device__ __align__(16) __nv_bfloat16 g_xT16[T_STEPS * N_NODES * 20];  // [t][n][20]
// gate weights, K-order [agg(64)|h(64)|x(20)|pad(12)], interleaved rows
__device__ __align__(16) __nv_bfloat16 g_Wb[256 * 160];
__device__ __align__(16) __nv_bfloat16 g_W1b[64 * 128];
__device__ __align__(16) __nv_bfloat16 g_W2b[128 * 64];
__device__ __align__(16) __nv_bfloat16 g_Whb[64 * 128];    // [W_rel | W_root]
__device__ __align__(16) float g_bias[256];                // per-unit quads (i,f,g,o)
__device__ float g_stats[256];
__device__ float g_scale[128];
__device__ float g_shift[128];
__device__ int   g_deg4[4 * N_NODES];
__device__ int   g_cur4[4 * N_NODES];
__device__ int   g_offs[N_NODES + 1];
__device__ int   g_ssrc[N_EDGES];
__device__ int   g_bsums[128];
__device__ int   g_boffs[128];
__device__ int   g_is64;

// ---------------- mma/ldmatrix/cp.async helpers ----------------
__device__ __forceinline__ uint32_t smem_u32(const void* p) {
    uint32_t a;
    asm("{ .reg .u64 tmp; cvta.to.shared.u64 tmp, %1; cvt.u32.u64 %0, tmp; }"
        : "=r"(a) : "l"(p));
    return a;
}
__device__ __forceinline__ void ldsm_x4(uint32_t* r, uint32_t addr) {
    asm volatile("ldmatrix.sync.aligned.m8n8.x4.shared.b16 {%0,%1,%2,%3}, [%4];"
                 : "=r"(r[0]), "=r"(r[1]), "=r"(r[2]), "=r"(r[3]) : "r"(addr));
}
__device__ __forceinline__ void mma_bf16(float* d, const uint32_t* a,
                                         uint32_t b0, uint32_t b1) {
    asm volatile(
        "mma.sync.aligned.m16n8k16.row.col.f32.bf16.bf16.f32 "
        "{%0,%1,%2,%3}, {%4,%5,%6,%7}, {%8,%9}, {%0,%1,%2,%3};"
        : "+f"(d[0]), "+f"(d[1]), "+f"(d[2]), "+f"(d[3])
        : "r"(a[0]), "r"(a[1]), "r"(a[2]), "r"(a[3]), "r"(b0), "r"(b1));
}
__device__ __forceinline__ float fast_tanh(float x) {
    float y;
    asm("tanh.approx.f32 %0, %1;" : "=f"(y) : "f"(x));
    return y;
}
__device__ __forceinline__ float fast_sigmoid(float x) {
    return 0.5f * fast_tanh(0.5f * x) + 0.5f;
}
#define CP_ASYNC_16(dst, src) \
    asm volatile("cp.async.ca.shared.global [%0], [%1], 16;" :: "r"(dst), "l"(src))
#define CP_ASYNC_16S(dst, src, ssz) \
    asm volatile("cp.async.ca.shared.global [%0], [%1], 16, %2;" :: "r"(dst), "l"(src), "r"(ssz))
#define CP_ASYNC_8S(dst, src, ssz) \
    asm volatile("cp.async.ca.shared.global [%0], [%1], 8, %2;" :: "r"(dst), "l"(src), "r"(ssz))
#define CP_ASYNC_COMMIT() asm volatile("cp.async.commit_group;" ::: "memory")
#define CP_ASYNC_WAIT0()  asm volatile("cp.async.wait_group 0;" ::: "memory")

// ---------------- small utility kernels ----------------
__global__ void zero_state() {
    int stride = gridDim.x * blockDim.x;
    int i0 = blockIdx.x * blockDim.x + threadIdx.x;
    for (int k = i0; k < 4 * N_NODES; k += stride) g_deg4[k] = 0;
    if (i0 < 256) g_stats[i0] = 0.f;
}

__global__ void detect_kernel(const unsigned int* __restrict__ w) {
    __shared__ unsigned int acc;
    if (threadIdx.x == 0) acc = 0u;
    __syncthreads();
    unsigned int v = 0u;
    for (int i = threadIdx.x; i < 2048; i += blockDim.x) v |= w[2 * i + 1];
    atomicOr(&acc, v);
    __syncthreads();
    if (threadIdx.x == 0) g_is64 = (acc == 0u) ? 1 : 0;
}

__device__ __forceinline__ int edge_val(const void* ei, long long idx) {
    if (g_is64) return (int)((const long long*)ei)[idx];
    return ((const int*)ei)[idx];
}

__global__ void hist2_kernel(const void* __restrict__ ei) {
    int stride = gridDim.x * blockDim.x;
    for (int e = blockIdx.x * blockDim.x + threadIdx.x; e < N_EDGES; e += stride) {
        int d = edge_val(ei, (long long)N_EDGES + e);
        atomicAdd(&g_deg4[(e & 3) * N_NODES + d], 1);
    }
}

__global__ void scan1_kernel() {
    __shared__ int warpsums[32];
    int tid = threadIdx.x, lane = tid & 31, wid = tid >> 5;
    int i = blockIdx.x * 1024 + tid;
    int v = 0;
    if (i < N_NODES)
        v = g_deg4[i] + g_deg4[N_NODES + i] + g_deg4[2 * N_NODES + i]
          + g_deg4[3 * N_NODES + i];
    int x = v;
    #pragma unroll
    for (int off = 1; off < 32; off <<= 1) {
        int y = __shfl_up_sync(0xFFFFFFFFu, x, off);
        if (lane >= off) x += y;
    }
    if (lane == 31) warpsums[wid] = x;
    __syncthreads();
    if (wid == 0) {
        int wv = warpsums[lane];
        #pragma unroll
        for (int off = 1; off < 32; off <<= 1) {
            int y = __shfl_up_sync(0xFFFFFFFFu, wv, off);
            if (lane >= off) wv += y;
        }
        warpsums[lane] = wv;
    }
    __syncthreads();
    int woff = (wid == 0) ? 0 : warpsums[wid - 1];
    if (i < N_NODES) g_offs[i] = x - v + woff;
    if (tid == 1023) g_bsums[blockIdx.x] = warpsums[31];
}

__global__ void scan2_kernel(int nblk) {
    __shared__ int warpsums[4];
    int tid = threadIdx.x, lane = tid & 31, wid = tid >> 5;
    int v = (tid < nblk) ? g_bsums[tid] : 0;
    int x = v;
    #pragma unroll
    for (int off = 1; off < 32; off <<= 1) {
        int y = __shfl_up_sync(0xFFFFFFFFu, x, off);
        if (lane >= off) x += y;
    }
    if (lane == 31) warpsums[wid] = x;
    __syncthreads();
    if (wid == 0 && lane < 4) {
        int wv = warpsums[lane];
        #pragma unroll
        for (int off = 1; off < 4; off <<= 1) {
            int y = __shfl_up_sync(0xFu, wv, off);
            if (lane >= off) wv += y;
        }
        warpsums[lane] = wv;
    }
    __syncthreads();
    int woff = (wid == 0) ? 0 : warpsums[wid - 1];
    int excl = x - v + woff;
    if (tid < nblk) g_boffs[tid] = excl;
    if (tid == nblk - 1) g_offs[N_NODES] = excl + v;
}

__global__ void scan3_kernel() {
    int i = blockIdx.x * blockDim.x + threadIdx.x;
    if (i >= N_NODES) return;
    int o = g_offs[i] + g_boffs[i >> 10];
    g_offs[i] = o;
    int d0 = g_deg4[i];
    int d1 = g_deg4[N_NODES + i];
    int d2 = g_deg4[2 * N_NODES + i];
    g_cur4[i] = o;
    g_cur4[N_NODES + i] = o + d0;
    g_cur4[2 * N_NODES + i] = o + d0 + d1;
    g_cur4[3 * N_NODES + i] = o + d0 + d1 + d2;
}

__global__ void scatter_kernel(const void* __restrict__ ei) {
    int stride = gridDim.x * blockDim.x;
    for (int e = blockIdx.x * blockDim.x + threadIdx.x; e < N_EDGES; e += stride) {
        int s = edge_val(ei, e);
        int d = edge_val(ei, (long long)N_EDGES + e);
        int p = atomicAdd(&g_cur4[(e & 3) * N_NODES + d], 1);
        g_ssrc[p] = s;
    }
}

// x (N, 30, 8) -> g_xT16[t][n][20] bf16, node-major, coalesced out.
__global__ void __launch_bounds__(256) transpose_x(const float* __restrict__ x) {
    __shared__ float sm[32 * 161];
    __shared__ __nv_bfloat16 so[8 * 32 * 20];   // [t][nl][j]
    int n0 = blockIdx.x * 32;
    #pragma unroll
    for (int w = 0; w < 20; w++) {
        int i = threadIdx.x + w * 256;
        int nl = i / 160, off = i - nl * 160;
        sm[nl * 161 + off] = x[(size_t)(n0 + nl) * 240 + 80 + off];
    }
    __syncthreads();
    #pragma unroll
    for (int w = 0; w < 20; w++) {
        int idx = threadIdx.x + w * 256;
        int nl = idx & 31;
        int p = idx >> 5;
        int t = p / 20, j = p - t * 20;
        so[(t * 32 + nl) * 20 + j] = __float2bfloat16_rn(sm[nl * 161 + j * 8 + t]);
    }
    __syncthreads();
    const uint32_t* sou = reinterpret_cast<const uint32_t*>(so);
    uint32_t* dst = reinterpret_cast<uint32_t*>(g_xT16);
    #pragma unroll
    for (int w = 0; w < 10; w++) {
        int idx = threadIdx.x + w * 256;           // 0..2559
        int t = idx / 320;
        int rem = idx - t * 320;
        dst[((size_t)t * N_NODES + n0) * 10 + rem] = sou[idx];
    }
}

// Fold GNN projection into gate weights; interleaved row layout + K-order
// [agg(0..63) | h(64..127) | x(128..147) | pad(148..159)].
__global__ void prep_weights(const float* __restrict__ W_ih, const float* __restrict__ W_hh,
                             const float* __restrict__ b_ih, const float* __restrict__ b_hh,
                             const float* __restrict__ W_rel, const float* __restrict__ b_rel,
                             const float* __restrict__ W_root) {
    int rp = blockIdx.x;
    int block16 = rp >> 4, within = rp & 15;
    int vl, q;
    if (within < 8) { vl = within >> 1; q = within & 1; }
    else            { vl = (within - 8) >> 1; q = 2 + ((within - 8) & 1); }
    int u = block16 * 4 + vl;
    int r = q * 64 + u;
    __shared__ float wg[64];
    int tid = threadIdx.x;  // 64 threads
    wg[tid] = W_ih[r * 84 + 20 + tid];
    __syncthreads();
    int c = tid;
    float m1 = 0.f, m2 = 0.f;
    #pragma unroll 8
    for (int j = 0; j < 64; j++) {
        float w = wg[j];
        m1 += w * W_rel[j * 64 + c];
        m2 += w * W_root[j * 64 + c];
    }
    m2 += W_hh[r * 64 + c];
    g_Wb[rp * 160 + c] = __float2bfloat16_rn(m1);        // agg block
    g_Wb[rp * 160 + 64 + c] = __float2bfloat16_rn(m2);   // h block
    if (c < 20) g_Wb[rp * 160 + 128 + c] = __float2bfloat16_rn(W_ih[r * 84 + c]); // x
    if (c < 12) g_Wb[rp * 160 + 148 + c] = __float2bfloat16_rn(0.f);
    if (c == 0) {
        float s = b_ih[r] + b_hh[r];
        for (int j = 0; j < 64; j++) s += wg[j] * b_rel[j];
        g_bias[u * 4 + q] = s;
    }
}

// bf16 copies of head weights.
__global__ void prep_head(const float* __restrict__ W1, const float* __restrict__ W2,
                          const float* __restrict__ W_rel, const float* __restrict__ W_root) {
    int i = blockIdx.x * 256 + threadIdx.x;
    if (i < 8192) {
        g_W1b[i] = __float2bfloat16_rn(W1[i]);
    } else if (i < 16384) {
        g_W2b[i - 8192] = __float2bfloat16_rn(W2[i - 8192]);
    } else if (i < 24576) {
        int j = i - 16384;
        int o = j >> 7, k = j & 127;
        float v = (k < 64) ? W_rel[o * 64 + k] : W_root[o * 64 + k - 64];
        g_Whb[j] = __float2bfloat16_rn(v);
    }
}

// ---------------- aggregation: warp per dst node, bf16 gather ----------------
// ah record: [n][0:64)=agg, [64:128)=h. Reads h from buf, writes agg into buf.
__global__ void agg_kernel(__nv_bfloat16* __restrict__ ah) {
    int gw = (blockIdx.x * blockDim.x + threadIdx.x) >> 5;
    int lane = threadIdx.x & 31;
    if (gw >= N_NODES) return;
    int beg = g_offs[gw], end = g_offs[gw + 1];
    float2 acc = make_float2(0.f, 0.f);
    int e = beg;
    for (; e + 4 <= end; e += 4) {
        int s0 = g_ssrc[e], s1 = g_ssrc[e + 1], s2 = g_ssrc[e + 2], s3 = g_ssrc[e + 3];
        float2 v0 = __bfloat1622float2(
            *reinterpret_cast<const __nv_bfloat162*>(ah + (size_t)s0 * 128 + 64 + lane * 2));
        float2 v1 = __bfloat1622float2(
            *reinterpret_cast<const __nv_bfloat162*>(ah + (size_t)s1 * 128 + 64 + lane * 2));
        float2 v2 = __bfloat1622float2(
            *reinterpret_cast<const __nv_bfloat162*>(ah + (size_t)s2 * 128 + 64 + lane * 2));
        float2 v3 = __bfloat1622float2(
            *reinterpret_cast<const __nv_bfloat162*>(ah + (size_t)s3 * 128 + 64 + lane * 2));
        acc.x += (v0.x + v1.x) + (v2.x + v3.x);
        acc.y += (v0.y + v1.y) + (v2.y + v3.y);
    }
    for (; e < end; e++) {
        int s = g_ssrc[e];
        float2 v = __bfloat1622float2(
            *reinterpret_cast<const __nv_bfloat162*>(ah + (size_t)s * 128 + 64 + lane * 2));
        acc.x += v.x;
        acc.y += v.y;
    }
    *reinterpret_cast<__nv_bfloat162*>(ah + (size_t)gw * 128 + lane * 2) =
        __float22bfloat162_rn(acc);
}

// ---------------- bf16 mma.sync gate GEMM + fused LSTM epilogue ----------------
// Tile: 128 nodes x 64 gate cols (grid y = 4). 8 warps = 4m x 2n, warp 32x32.
// smem: A[128][336B] @0 (43008), B[64][336B] @43008 (21504). 3 CTAs/SM.
// A K-order: [agg|h @0 (256B, 16-aligned) | x @256 | pad @296].
#define GATE_SMEM 64512

__global__ void __launch_bounds__(256, 3)
gate_kernel(const __nv_bfloat16* __restrict__ xTt16,
            const __nv_bfloat16* __restrict__ ah_in,
            float* __restrict__ h_out, __nv_bfloat16* __restrict__ ah_out,
            int t0, int wf32) {
    extern __shared__ char smem[];
    const int tid = threadIdx.x;
    const int wid = tid >> 5;
    const int lane = tid & 31;
    const int n0 = blockIdx.x * 128;
    const int col0 = blockIdx.y * 64;    // gate-col base (0/64/128/192)
    const int ubase = col0 >> 2;         // unit base (16 units per CTA)
    const uint32_t sbase = smem_u32(smem);

    // ---- stage B via cp.async: 64 interleaved weight rows x 160 bf16 ----
    {
        const char* wsrc = reinterpret_cast<const char*>(g_Wb) + (size_t)col0 * 320;
        #pragma unroll
        for (int it = 0; it < 5; it++) {
            int idx = tid + it * 256;        // 0..1279 = r*20 + c
            int r = idx / 20;
            int c = idx - r * 20;
            CP_ASYNC_16(sbase + 43008u + r * 336 + c * 16, wsrc + r * 320 + c * 16);
        }
    }
    // ---- A: agg|h record (k 0..127): 256B contiguous, 16B cp.async (both aligned) ----
    {
        const char* asrc = reinterpret_cast<const char*>(ah_in);
        #pragma unroll
        for (int it = 0; it < 8; it++) {
            int idx = tid + it * 256;        // 0..2047 = nl*16 + q
            int nl = idx >> 4;
            int q = idx & 15;
            int n = n0 + nl;
            int ncl = (n < N_NODES) ? n : (N_NODES - 1);
            uint32_t ssz = (!t0 && n < N_NODES) ? 16u : 0u;
            CP_ASYNC_16S(sbase + nl * 336 + q * 16, asrc + (size_t)ncl * 256 + q * 16, ssz);
        }
    }
    // ---- A: x bf16 (k 128..147): 8B cp.async (40B row is 8-aligned) ----
    {
        const char* xsrc = reinterpret_cast<const char*>(xTt16);
        #pragma unroll
        for (int it = 0; it < 3; it++) {
            int idx = tid + it * 256;        // need 640 = nl*5 + p
            if (idx < 640) {
                int nl = idx / 5;
                int p = idx - nl * 5;
                int n = n0 + nl;
                int ncl = (n < N_NODES) ? n : (N_NODES - 1);
                uint32_t ssz = (n < N_NODES) ? 8u : 0u;
                CP_ASYNC_8S(sbase + nl * 336 + 256 + p * 8, xsrc + (size_t)ncl * 40 + p * 8, ssz);
            }
        }
    }
    // ---- A: zero pad (k 148..167) plain stores ----
    #pragma unroll
    for (int it = 0; it < 3; it++) {
        int idx = tid + it * 256;
        if (idx < 640) {
            int nl = idx / 5;
            int p = idx - nl * 5;
            *reinterpret_cast<uint2*>(smem + nl * 336 + 296 + p * 8) = make_uint2(0u, 0u);
        }
    }
    CP_ASYNC_COMMIT();
    CP_ASYNC_WAIT0();
    __syncthreads();

    // ---- mma mainloop: warp tile 32 rows x 32 cols ----
    const int mw = wid >> 1;                 // 0..3
    const int nw = wid & 1;                  // 0..1
    const int mr = mw * 32;
    const int ncw = nw * 32;                 // col within CTA tile (0 or 32)
    uint32_t aAddr = sbase + (mr + (lane & 15)) * 336 + ((lane >> 4) << 4);
    uint32_t bAddr = sbase + 43008u + (ncw + (lane & 15)) * 336 + ((lane >> 4) << 4);

    float acc[2][4][4];
    #pragma unroll
    for (int mi = 0; mi < 2; mi++)
        #pragma unroll
        for (int nj = 0; nj < 4; nj++)
            #pragma unroll
            for (int e = 0; e < 4; e++) acc[mi][nj][e] = 0.f;

    #pragma unroll
    for (int ks = 0; ks < 10; ks++) {
        uint32_t a[2][4];
        ldsm_x4(a[0], aAddr + ks * 32);
        ldsm_x4(a[1], aAddr + 16 * 336 + ks * 32);
        uint32_t b[2][4];
        ldsm_x4(b[0], bAddr + ks * 32);
        ldsm_x4(b[1], bAddr + 16 * 336 + ks * 32);
        #pragma unroll
        for (int mi = 0; mi < 2; mi++)
            #pragma unroll
            for (int nj2 = 0; nj2 < 4; nj2++) {
                int nj = nj2 >> 1, hi = nj2 & 1;
                mma_bf16(acc[mi][nj2], a[mi], b[nj][hi], b[nj][hi + 2]);
            }
    }

    // ---- c fragments + bias quads: direct gmem -> registers ----
    float* cptr = g_cperm + (((size_t)(blockIdx.x * 4 + blockIdx.y)) * 256 + tid) * 8;
    float creg[8];
    if (!t0) {
        float4 ca = *reinterpret_cast<const float4*>(cptr);
        float4 cb = *reinterpret_cast<const float4*>(cptr + 4);
        creg[0] = ca.x; creg[1] = ca.y; creg[2] = ca.z; creg[3] = ca.w;
        creg[4] = cb.x; creg[5] = cb.y; creg[6] = cb.z; creg[7] = cb.w;
    } else {
        #pragma unroll
        for (int i = 0; i < 8; i++) creg[i] = 0.f;
    }
    const int vl = lane & 3;
    const float4* bias4 = reinterpret_cast<const float4*>(g_bias) + ubase;
    float4 bq[2];
    bq[0] = bias4[(wid & 1) * 8 + vl];
    bq[1] = bias4[(wid & 1) * 8 + 4 + vl];

    __syncthreads();

    // ---- repurpose smem: Hs fp32 [128][18] @0 ----
    float* Hs = reinterpret_cast<float*>(smem);

    // ---- fused LSTM epilogue (shuffle-free; c in registers) ----
    #pragma unroll
    for (int mi = 0; mi < 2; mi++) {
        int r = mr + mi * 16 + (lane >> 2);
        #pragma unroll
        for (int b = 0; b < 2; b++) {
            int u = nw * 8 + b * 4 + vl;     // unit within CTA (0..15)
            float4 q = bq[b];
            int ci = mi * 4 + b * 2;
            {
                float ig = acc[mi][2 * b][0] + q.x;
                float fg = acc[mi][2 * b][1] + q.y;
                float gg = acc[mi][2 * b + 1][0] + q.z;
                float og = acc[mi][2 * b + 1][1] + q.w;
                float si = fast_sigmoid(ig), sf = fast_sigmoid(fg);
                float so = fast_sigmoid(og), tg = fast_tanh(gg);
                float cn = sf * creg[ci] + si * tg;
                creg[ci] = cn;
                Hs[r * 18 + u] = so * fast_tanh(cn);
            }
            {
                float ig = acc[mi][2 * b][2] + q.x;
                float fg = acc[mi][2 * b][3] + q.y;
                float gg = acc[mi][2 * b + 1][2] + q.z;
                float og = acc[mi][2 * b + 1][3] + q.w;
                float si = fast_sigmoid(ig), sf = fast_sigmoid(fg);
                float so = fast_sigmoid(og), tg = fast_tanh(gg);
                float cn = sf * creg[ci + 1] + si * tg;
                creg[ci + 1] = cn;
                Hs[(r + 8) * 18 + u] = so * fast_tanh(cn);
            }
        }
    }
    // store c fragments back
    *reinterpret_cast<float4*>(cptr) = make_float4(creg[0], creg[1], creg[2], creg[3]);
    *reinterpret_cast<float4*>(cptr + 4) = make_float4(creg[4], creg[5], creg[6], creg[7]);
    __syncthreads();

    // ---- coalesced h writeback into ah record [64:128) ----
    #pragma unroll
    for (int it = 0; it < 4; it++) {
        int idx = tid + it * 256;            // 0..1023 = rr*8 + up
        int rr = idx >> 3;
        int up = idx & 7;
        int n = n0 + rr;
        if (n < N_NODES) {
            float2 hv = *reinterpret_cast<const float2*>(&Hs[rr * 18 + up * 2]);
            *reinterpret_cast<__nv_bfloat162*>(
                ah_out + (size_t)n * 128 + 64 + ubase + up * 2) = __float22bfloat162_rn(hv);
            if (wf32)
                *reinterpret_cast<float2*>(h_out + (size_t)n * 64 + ubase + up * 2) = hv;
        }
    }
}

// ---------------- head1: gnn = [agg|h] @ [W_rel|W_root]^T + b_rel (mma) ------
#define H1_SMEM 52480

__global__ void __launch_bounds__(256)
head1_kernel(const __nv_bfloat16* __restrict__ ah, const float* __restrict__ b_rel) {
    extern __shared__ char smem[];
    const int tid = threadIdx.x;
    const int wid = tid >> 5;
    const int lane = tid & 31;
    const int n0 = blockIdx.x * 128;
    float* sb = reinterpret_cast<float*>(smem + 52224);

    {
        const uint4* Wh4 = reinterpret_cast<const uint4*>(g_Whb);
        #pragma unroll
        for (int it = 0; it < 4; it++) {
            int idx = tid + it * 256;
            int r = idx >> 4, c16 = idx & 15;
            *reinterpret_cast<uint4*>(smem + 34816 + r * 272 + c16 * 16) = Wh4[idx];
        }
    }
    #pragma unroll
    for (int it = 0; it < 8; it++) {
        int idx = tid + it * 256;
        int nl = idx >> 4, q = idx & 15;
        int n = n0 + nl;
        uint4 v = make_uint4(0u, 0u, 0u, 0u);
        if (n < N_NODES)
            v = reinterpret_cast<const uint4*>(ah + (size_t)n * 128)[q];
        *reinterpret_cast<uint4*>(smem + nl * 272 + q * 16) = v;
    }
    if (tid < 128)
        *reinterpret_cast<uint4*>(smem + tid * 272 + 256) = make_uint4(0u, 0u, 0u, 0u);
    if (tid < 64) sb[tid] = b_rel[tid];
    __syncthreads();

    const int mw = wid >> 1;
    const int nw = wid & 1;
    const int mr = mw * 32;
    const int nc = nw * 32;
    const uint32_t sbase = smem_u32(smem);
    uint32_t aAddr = sbase + (mr + (lane & 15)) * 272 + ((lane >> 4) << 4);
    uint32_t bAddr = sbase + 34816u + (nc + (lane & 15)) * 272 + ((lane >> 4) << 4);

    float acc[2][4][4];
    #pragma unroll
    for (int mi = 0; mi < 2; mi++)
        #pragma unroll
        for (int nj = 0; nj < 4; nj++)
            #pragma unroll
            for (int e = 0; e < 4; e++) acc[mi][nj][e] = 0.f;

    #pragma unroll
    for (int ks = 0; ks < 8; ks++) {
        uint32_t a[2][4];
        ldsm_x4(a[0], aAddr + ks * 32);
        ldsm_x4(a[1], aAddr + 16 * 272 + ks * 32);
        uint32_t b[2][4];
        ldsm_x4(b[0], bAddr + ks * 32);
        ldsm_x4(b[1], bAddr + 16 * 272 + ks * 32);
        #pragma unroll
        for (int mi = 0; mi < 2; mi++)
            #pragma unroll
            for (int nj2 = 0; nj2 < 4; nj2++) {
                int nj = nj2 >> 1, hi = nj2 & 1;
                mma_bf16(acc[mi][nj2], a[mi], b[nj][hi], b[nj][hi + 2]);
            }
    }
    __syncthreads();

    float* Gs = reinterpret_cast<float*>(smem);
    #pragma unroll
    for (int mi = 0; mi < 2; mi++) {
        int row = mr + mi * 16 + (lane >> 2);
        #pragma unroll
        for (int nj2 = 0; nj2 < 4; nj2++) {
            int c = nc + nj2 * 8 + (lane & 3) * 2;
            *reinterpret_cast<float2*>(&Gs[row * 68 + c]) =
                make_float2(acc[mi][nj2][0] + sb[c], acc[mi][nj2][1] + sb[c + 1]);
            *reinterpret_cast<float2*>(&Gs[(row + 8) * 68 + c]) =
                make_float2(acc[mi][nj2][2] + sb[c], acc[mi][nj2][3] + sb[c + 1]);
        }
    }
    __syncthreads();

    #pragma unroll
    for (int it = 0; it < 32; it++) {
        int idx = tid + it * 256;
        int rr = idx >> 6, u = idx & 63;
        int n = n0 + rr;
        if (n < N_NODES) g_gnn[(size_t)n * 64 + u] = Gs[rr * 68 + u];
    }
}

// ---------------- head2: fused layernorm + MLP + out-projection (mma) --------
#define H2_SMEM 90880

__global__ void __launch_bounds__(256)
head2_kernel(const float* __restrict__ hfin, const float* __restrict__ b1,
             const float* __restrict__ b2, const float* __restrict__ Wout,
             const float* __restrict__ bout, float* __restrict__ out) {
    extern __shared__ char smem[];
    const int tid = threadIdx.x;
    const int wid = tid >> 5;
    const int lane = tid & 31;
    const int n0 = blockIdx.x * 128;
    float* sb1 = reinterpret_cast<float*>(smem + 89088);
    float* sb2 = reinterpret_cast<float*>(smem + 89344);
    float* sWout = reinterpret_cast<float*>(smem + 89856);
    float* sdot = reinterpret_cast<float*>(smem + 90368);

    #pragma unroll
    for (int it = 0; it < 32; it++) {
        int idx = tid + it * 256;
        int nl = idx >> 6, cp = idx & 63;
        int c = cp * 2;
        int n = n0 + nl;
        float2 v = make_float2(0.f, 0.f);
        if (n < N_NODES) {
            v = (cp < 32)
                ? reinterpret_cast<const float2*>(hfin)[(size_t)n * 32 + cp]
                : reinterpret_cast<const float2*>(g_gnn)[(size_t)n * 32 + cp - 32];
        }
        float2 nv = make_float2(v.x * g_scale[c] + g_shift[c],
                                v.y * g_scale[c + 1] + g_shift[c + 1]);
        *reinterpret_cast<__nv_bfloat162*>(smem + nl * 272 + c * 2) =
            __float22bfloat162_rn(nv);
    }
    if (tid < 128)
        *reinterpret_cast<uint4*>(smem + tid * 272 + 256) = make_uint4(0u, 0u, 0u, 0u);
    {
        const uint4* W14 = reinterpret_cast<const uint4*>(g_W1b);
        #pragma unroll
        for (int it = 0; it < 4; it++) {
            int idx = tid + it * 256;
            int r = idx >> 4, c16 = idx & 15;
            *reinterpret_cast<uint4*>(smem + 34816 + r * 272 + c16 * 16) = W14[idx];
        }
        const uint4* W24 = reinterpret_cast<const uint4*>(g_W2b);
        #pragma unroll
        for (int it = 0; it < 4; it++) {
            int idx = tid + it * 256;
            int r = idx >> 3, c8 = idx & 7;
            *reinterpret_cast<uint4*>(smem + 70656 + r * 144 + c8 * 16) = W24[idx];
        }
    }
    if (tid < 64) sb1[tid] = b1[tid];
    if (tid < 128) {
        sb2[tid] = b2[tid];
        sWout[tid] = Wout[tid];
        sdot[tid] = 0.f;
    }
    __syncthreads();

    const int mw = wid >> 1;
    const int nw = wid & 1;
    const int mr = mw * 32;
    const uint32_t sbase = smem_u32(smem);

    {
        const int nc = nw * 32;
        uint32_t aAddr = sbase + (mr + (lane & 15)) * 272 + ((lane >> 4) << 4);
        uint32_t bAddr = sbase + 34816u + (nc + (lane & 15)) * 272 + ((lane >> 4) << 4);
        float acc1[2][4][4];
        #pragma unroll
        for (int mi = 0; mi < 2; mi++)
            #pragma unroll
            for (int nj = 0; nj < 4; nj++)
                #pragma unroll
                for (int e = 0; e < 4; e++) acc1[mi][nj][e] = 0.f;
        #pragma unroll
        for (int ks = 0; ks < 8; ks++) {
            uint32_t a[2][4];
            ldsm_x4(a[0], aAddr + ks * 32);
            ldsm_x4(a[1], aAddr + 16 * 272 + ks * 32);
            uint32_t b[2][4];
            ldsm_x4(b[0], bAddr + ks * 32);
            ldsm_x4(b[1], bAddr + 16 * 272 + ks * 32);
            #pragma unroll
            for (int mi = 0; mi < 2; mi++)
                #pragma unroll
                for (int nj2 = 0; nj2 < 4; nj2++) {
                    int nj = nj2 >> 1, hi = nj2 & 1;
                    mma_bf16(acc1[mi][nj2], a[mi], b[nj][hi], b[nj][hi + 2]);
                }
        }
        #pragma unroll
        for (int mi = 0; mi < 2; mi++) {
            int row = mr + mi * 16 + (lane >> 2);
            #pragma unroll
            for (int nj2 = 0; nj2 < 4; nj2++) {
                int c = nc + nj2 * 8 + (lane & 3) * 2;
                float v0 = fmaxf(acc1[mi][nj2][0] + sb1[c], 0.f);
                float v1 = fmaxf(acc1[mi][nj2][1] + sb1[c + 1], 0.f);
                float v2 = fmaxf(acc1[mi][nj2][2] + sb1[c], 0.f);
                float v3 = fmaxf(acc1[mi][nj2][3] + sb1[c + 1], 0.f);
                *reinterpret_cast<__nv_bfloat162*>(smem + 52224 + row * 144 + c * 2) =
                    __float22bfloat162_rn(make_float2(v0, v1));
                *reinterpret_cast<__nv_bfloat162*>(smem + 52224 + (row + 8) * 144 + c * 2) =
                    __float22bfloat162_rn(make_float2(v2, v3));
            }
        }
    }
    __syncthreads();

    {
        const int nc = nw * 64;
        uint32_t aAddr = sbase + 52224u + (mr + (lane & 15)) * 144 + ((lane >> 4) << 4);
        uint32_t bAddr = sbase + 70656u + (nc + (lane & 15)) * 144 + ((lane >> 4) << 4);
        float acc2[2][8][4];
        #pragma unroll
        for (int mi = 0; mi < 2; mi++)
            #pragma unroll
            for (int nj = 0; nj < 8; nj++)
                #pragma unroll
                for (int e = 0; e < 4; e++) acc2[mi][nj][e] = 0.f;
        #pragma unroll
        for (int ks = 0; ks < 4; ks++) {
            uint32_t a[2][4];
            ldsm_x4(a[0], aAddr + ks * 32);
            ldsm_x4(a[1], aAddr + 16 * 144 + ks * 32);
            uint32_t b[4][4];
            #pragma unroll
            for (int nj = 0; nj < 4; nj++)
                ldsm_x4(b[nj], bAddr + nj * 16 * 144 + ks * 32);
            #pragma unroll
            for (int mi = 0; mi < 2; mi++)
                #pragma unroll
                for (int nj2 = 0; nj2 < 8; nj2++) {
                    int nj = nj2 >> 1, hi = nj2 & 1;
                    mma_bf16(acc2[mi][nj2], a[mi], b[nj][hi], b[nj][hi + 2]);
                }
        }
        #pragma unroll
        for (int mi = 0; mi < 2; mi++) {
            float p0 = 0.f, p1 = 0.f;
            #pragma unroll
            for (int nj2 = 0; nj2 < 8; nj2++) {
                int c = nc + nj2 * 8 + (lane & 3) * 2;
                float w0 = sWout[c], w1 = sWout[c + 1];
                p0 += fmaxf(acc2[mi][nj2][0] + sb2[c], 0.f) * w0
                    + fmaxf(acc2[mi][nj2][1] + sb2[c + 1], 0.f) * w1;
                p1 += fmaxf(acc2[mi][nj2][2] + sb2[c], 0.f) * w0
                    + fmaxf(acc2[mi][nj2][3] + sb2[c + 1], 0.f) * w1;
            }
            p0 += __shfl_xor_sync(0xFFFFFFFFu, p0, 1);
            p0 += __shfl_xor_sync(0xFFFFFFFFu, p0, 2);
            p1 += __shfl_xor_sync(0xFFFFFFFFu, p1, 1);
            p1 += __shfl_xor_sync(0xFFFFFFFFu, p1, 2);
            if ((lane & 3) == 0) {
                int row = mr + mi * 16 + (lane >> 2);
                atomicAdd(&sdot[row], p0);
                atomicAdd(&sdot[row + 8], p1);
            }
        }
    }
    __syncthreads();

    if (tid < 128) {
        int n = n0 + tid;
        if (n < N_NODES) {
            float s = sdot[tid] + bout[0];
            out[n] = 1.f / (1.f + __expf(-s));
        }
    }
}

// ---------------- per-feature stats over nodes ----------------
__global__ void stats_kernel(const float* __restrict__ h, const float* __restrict__ gnn) {
    int c = threadIdx.x & 127;
    int grp = threadIdx.x >> 7;
    int r0 = blockIdx.x * 256;
    int rend = min(r0 + 256, N_NODES);
    float s = 0.f, q = 0.f;
    for (int r = r0 + grp; r < rend; r += 2) {
        float v = (c < 64) ? h[(size_t)r * 64 + c] : gnn[(size_t)r * 64 + c - 64];
        s += v;
        q += v * v;
    }
    atomicAdd(&g_stats[c], s);
    atomicAdd(&g_stats[128 + c], q);
}

__global__ void finalize_stats(const float* __restrict__ gamma, const float* __restrict__ beta) {
    int c = threadIdx.x;
    float mean = g_stats[c] / (float)N_NODES;
    float var = g_stats[128 + c] / (float)N_NODES - mean * mean;
    float rstd = rsqrtf(var + 1e-5f);
    float sc = rstd * gamma[c];
    g_scale[c] = sc;
    g_shift[c] = beta[c] - mean * sc;
}

// ---------------- launch ----------------
extern "C" void kernel_launch(void* const* d_in, const int* in_sizes, int n_in,
                              void* d_out, int out_size) {
    const float* x      = (const float*)d_in[0];
    const void*  ei     = d_in[1];
    const float* W_ih   = (const float*)d_in[4];
    const float* W_hh   = (const float*)d_in[5];
    const float* b_ih   = (const float*)d_in[6];
    const float* b_hh   = (const float*)d_in[7];
    const float* W_rel  = (const float*)d_in[8];
    const float* b_rel  = (const float*)d_in[9];
    const float* W_root = (const float*)d_in[10];
    const float* gamma  = (const float*)d_in[11];
    const float* beta   = (const float*)d_in[12];
    const float* W1     = (const float*)d_in[13];
    const float* b1     = (const float*)d_in[14];
    const float* W2     = (const float*)d_in[15];
    const float* b2     = (const float*)d_in[16];
    const float* W_out  = (const float*)d_in[17];
    const float* b_out  = (const float*)d_in[18];

    float *hbuf, *gnn;
    __nv_bfloat16 *ah, *xT16;
    cudaGetSymbolAddress((void**)&hbuf, g_hbuf);
    cudaGetSymbolAddress((void**)&ah, g_ah);
    cudaGetSymbolAddress((void**)&gnn, g_gnn);
    cudaGetSymbolAddress((void**)&xT16, g_xT16);

    cudaFuncSetAttribute(gate_kernel, cudaFuncAttributeMaxDynamicSharedMemorySize, GATE_SMEM);
    cudaFuncSetAttribute(head1_kernel, cudaFuncAttributeMaxDynamicSharedMemorySize, H1_SMEM);
    cudaFuncSetAttribute(head2_kernel, cudaFuncAttributeMaxDynamicSharedMemorySize, H2_SMEM);

    const int scan_blocks = (N_NODES + 1023) / 1024;   // 98
    dim3 ggrid(N_TILES, 4);

    // t=0 gate only needs zero_state + prep_weights + transpose_x.
    // (gate_kernel stays launch #4 for the fixed ncu window.)
    zero_state<<<512, 256>>>();
    prep_weights<<<256, 64>>>(W_ih, W_hh, b_ih, b_hh, W_rel, b_rel, W_root);
    transpose_x<<<N_NODES / 32, 256>>>(x);
    gate_kernel<<<ggrid, 256, GATE_SMEM>>>(xT16, ah, hbuf, ah + (size_t)N_NODES * 128, 1, 0);

    detect_kernel<<<1, 256>>>((const unsigned int*)ei);
    prep_head<<<96, 256>>>(W1, W2, W_rel, W_root);
    hist2_kernel<<<512, 256>>>(ei);
    scan1_kernel<<<scan_blocks, 1024>>>();
    scan2_kernel<<<1, 128>>>(scan_blocks);
    scan3_kernel<<<(N_NODES + 255) / 256, 256>>>();
    scatter_kernel<<<512, 256>>>(ei);

    for (int t = 1; t < T_STEPS; t++) {
        __nv_bfloat16* ah_in = ah + (size_t)(t & 1) * N_NODES * 128;
        __nv_bfloat16* ah_out = ah + (size_t)((t + 1) & 1) * N_NODES * 128;
        agg_kernel<<<(N_NODES * 32 + 255) / 256, 256>>>(ah_in);
        gate_kernel<<<ggrid, 256, GATE_SMEM>>>(
            xT16 + (size_t)t * N_NODES * 20, ah_in, hbuf, ah_out,
            0, t == T_STEPS - 1 ? 1 : 0);
    }
    // ah buffer 1 = [agg|h] of step 7 (head1 input); hbuf = final h fp32.
    head1_kernel<<<N_TILES, 256, H1_SMEM>>>(ah + (size_t)N_NODES * 128, b_rel);
    stats_kernel<<<(N_NODES + 255) / 256, 256>>>(hbuf, gnn);
    finalize_stats<<<1, 128>>>(gamma, beta);
    head2_kernel<<<N_TILES, 256, H2_SMEM>>>(hbuf, b1, b2, W_out, b_out, (float*)d_out);
}

// round 16
// speedup vs baseline: 2.2695x; 1.0045x over previous
#include <cuda_runtime.h>
#include <cuda_bf16.h>
#include <math.h>
#include <cstdint>

#define N_NODES 100000
#define N_EDGES 1600000
#define T_STEPS 8
#define N_TILES 782   // ceil(N_NODES/128)

// ---------------- device scratch (no allocations allowed) ----------------
__device__ float g_hbuf[N_NODES * 64];                     // fp32 final h (t=7 only)
// interleaved per-node record: [0:64)=agg, [64:128)=h ; double buffered
__device__ __align__(16) __nv_bfloat16 g_ah[2 * N_NODES * 128];
__device__ __align__(16) float g_cperm[N_TILES * 4 * 256 * 8];  // c in fragment order
__device__ float g_gnn[N_NODES * 64];
__device__ __align__(16) __nv_bfloat16 g_xT16[T_STEPS * N_NODES * 20];  // [t][n][20]
// gate weights, K-order [agg(64)|h(64)|x(20)|pad(12)], interleaved rows
__device__ __align__(16) __nv_bfloat16 g_Wb[256 * 160];
__device__ __align__(16) __nv_bfloat16 g_W1b[64 * 128];
__device__ __align__(16) __nv_bfloat16 g_W2b[128 * 64];
__device__ __align__(16) __nv_bfloat16 g_Whb[64 * 128];    // [W_rel | W_root]
__device__ __align__(16) float g_bias[256];                // per-unit quads (i,f,g,o)
__device__ float g_stats[256];
__device__ float g_scale[128];
__device__ float g_shift[128];
__device__ int   g_deg4[4 * N_NODES];
__device__ int   g_cur4[4 * N_NODES];
__device__ int   g_offs[N_NODES + 1];
__device__ int   g_ssrc[N_EDGES];
__device__ int   g_bsums[128];
__device__ int   g_boffs[128];
__device__ int   g_is64;

// ---------------- mma/ldmatrix/cp.async helpers ----------------
__device__ __forceinline__ uint32_t smem_u32(const void* p) {
    uint32_t a;
    asm("{ .reg .u64 tmp; cvta.to.shared.u64 tmp, %1; cvt.u32.u64 %0, tmp; }"
        : "=r"(a) : "l"(p));
    return a;
}
__device__ __forceinline__ void ldsm_x4(uint32_t* r, uint32_t addr) {
    asm volatile("ldmatrix.sync.aligned.m8n8.x4.shared.b16 {%0,%1,%2,%3}, [%4];"
                 : "=r"(r[0]), "=r"(r[1]), "=r"(r[2]), "=r"(r[3]) : "r"(addr));
}
__device__ __forceinline__ void mma_bf16(float* d, const uint32_t* a,
                                         uint32_t b0, uint32_t b1) {
    asm volatile(
        "mma.sync.aligned.m16n8k16.row.col.f32.bf16.bf16.f32 "
        "{%0,%1,%2,%3}, {%4,%5,%6,%7}, {%8,%9}, {%0,%1,%2,%3};"
        : "+f"(d[0]), "+f"(d[1]), "+f"(d[2]), "+f"(d[3])
        : "r"(a[0]), "r"(a[1]), "r"(a[2]), "r"(a[3]), "r"(b0), "r"(b1));
}
__device__ __forceinline__ float fast_tanh(float x) {
    float y;
    asm("tanh.approx.f32 %0, %1;" : "=f"(y) : "f"(x));
    return y;
}
__device__ __forceinline__ float fast_sigmoid(float x) {
    return 0.5f * fast_tanh(0.5f * x) + 0.5f;
}
#define CP_ASYNC_16(dst, src) \
    asm volatile("cp.async.ca.shared.global [%0], [%1], 16;" :: "r"(dst), "l"(src))
#define CP_ASYNC_16S(dst, src, ssz) \
    asm volatile("cp.async.ca.shared.global [%0], [%1], 16, %2;" :: "r"(dst), "l"(src), "r"(ssz))
#define CP_ASYNC_8S(dst, src, ssz) \
    asm volatile("cp.async.ca.shared.global [%0], [%1], 8, %2;" :: "r"(dst), "l"(src), "r"(ssz))
#define CP_ASYNC_COMMIT() asm volatile("cp.async.commit_group;" ::: "memory")
#define CP_ASYNC_WAIT0()  asm volatile("cp.async.wait_group 0;" ::: "memory")

// ---------------- small utility kernels ----------------
__global__ void zero_stats() {
    if (threadIdx.x < 256 && blockIdx.x == 0) g_stats[threadIdx.x] = 0.f;
}

__global__ void zero_deg() {
    int stride = gridDim.x * blockDim.x;
    int i0 = blockIdx.x * blockDim.x + threadIdx.x;
    for (int k = i0; k < 4 * N_NODES; k += stride) g_deg4[k] = 0;
}

__global__ void detect_kernel(const unsigned int* __restrict__ w) {
    __shared__ unsigned int acc;
    if (threadIdx.x == 0) acc = 0u;
    __syncthreads();
    unsigned int v = 0u;
    for (int i = threadIdx.x; i < 2048; i += blockDim.x) v |= w[2 * i + 1];
    atomicOr(&acc, v);
    __syncthreads();
    if (threadIdx.x == 0) g_is64 = (acc == 0u) ? 1 : 0;
}

__device__ __forceinline__ int edge_val(const void* ei, long long idx) {
    if (g_is64) return (int)((const long long*)ei)[idx];
    return ((const int*)ei)[idx];
}

__global__ void hist2_kernel(const void* __restrict__ ei) {
    int stride = gridDim.x * blockDim.x;
    for (int e = blockIdx.x * blockDim.x + threadIdx.x; e < N_EDGES; e += stride) {
        int d = edge_val(ei, (long long)N_EDGES + e);
        atomicAdd(&g_deg4[(e & 3) * N_NODES + d], 1);
    }
}

__global__ void scan1_kernel() {
    __shared__ int warpsums[32];
    int tid = threadIdx.x, lane = tid & 31, wid = tid >> 5;
    int i = blockIdx.x * 1024 + tid;
    int v = 0;
    if (i < N_NODES)
        v = g_deg4[i] + g_deg4[N_NODES + i] + g_deg4[2 * N_NODES + i]
          + g_deg4[3 * N_NODES + i];
    int x = v;
    #pragma unroll
    for (int off = 1; off < 32; off <<= 1) {
        int y = __shfl_up_sync(0xFFFFFFFFu, x, off);
        if (lane >= off) x += y;
    }
    if (lane == 31) warpsums[wid] = x;
    __syncthreads();
    if (wid == 0) {
        int wv = warpsums[lane];
        #pragma unroll
        for (int off = 1; off < 32; off <<= 1) {
            int y = __shfl_up_sync(0xFFFFFFFFu, wv, off);
            if (lane >= off) wv += y;
        }
        warpsums[lane] = wv;
    }
    __syncthreads();
    int woff = (wid == 0) ? 0 : warpsums[wid - 1];
    if (i < N_NODES) g_offs[i] = x - v + woff;
    if (tid == 1023) g_bsums[blockIdx.x] = warpsums[31];
}

__global__ void scan2_kernel(int nblk) {
    __shared__ int warpsums[4];
    int tid = threadIdx.x, lane = tid & 31, wid = tid >> 5;
    int v = (tid < nblk) ? g_bsums[tid] : 0;
    int x = v;
    #pragma unroll
    for (int off = 1; off < 32; off <<= 1) {
        int y = __shfl_up_sync(0xFFFFFFFFu, x, off);
        if (lane >= off) x += y;
    }
    if (lane == 31) warpsums[wid] = x;
    __syncthreads();
    if (wid == 0 && lane < 4) {
        int wv = warpsums[lane];
        #pragma unroll
        for (int off = 1; off < 4; off <<= 1) {
            int y = __shfl_up_sync(0xFu, wv, off);
            if (lane >= off) wv += y;
        }
        warpsums[lane] = wv;
    }
    __syncthreads();
    int woff = (wid == 0) ? 0 : warpsums[wid - 1];
    int excl = x - v + woff;
    if (tid < nblk) g_boffs[tid] = excl;
    if (tid == nblk - 1) g_offs[N_NODES] = excl + v;
}

__global__ void scan3_kernel() {
    int i = blockIdx.x * blockDim.x + threadIdx.x;
    if (i >= N_NODES) return;
    int o = g_offs[i] + g_boffs[i >> 10];
    g_offs[i] = o;
    int d0 = g_deg4[i];
    int d1 = g_deg4[N_NODES + i];
    int d2 = g_deg4[2 * N_NODES + i];
    g_cur4[i] = o;
    g_cur4[N_NODES + i] = o + d0;
    g_cur4[2 * N_NODES + i] = o + d0 + d1;
    g_cur4[3 * N_NODES + i] = o + d0 + d1 + d2;
}

__global__ void scatter_kernel(const void* __restrict__ ei) {
    int stride = gridDim.x * blockDim.x;
    for (int e = blockIdx.x * blockDim.x + threadIdx.x; e < N_EDGES; e += stride) {
        int s = edge_val(ei, e);
        int d = edge_val(ei, (long long)N_EDGES + e);
        int p = atomicAdd(&g_cur4[(e & 3) * N_NODES + d], 1);
        g_ssrc[p] = s;
    }
}

// x (N, 30, 8) -> g_xT16[t][n][20] bf16, node-major, coalesced out.
__global__ void __launch_bounds__(256) transpose_x(const float* __restrict__ x) {
    __shared__ float sm[32 * 161];
    __shared__ __nv_bfloat16 so[8 * 32 * 20];   // [t][nl][j]
    int n0 = blockIdx.x * 32;
    #pragma unroll
    for (int w = 0; w < 20; w++) {
        int i = threadIdx.x + w * 256;
        int nl = i / 160, off = i - nl * 160;
        sm[nl * 161 + off] = x[(size_t)(n0 + nl) * 240 + 80 + off];
    }
    __syncthreads();
    #pragma unroll
    for (int w = 0; w < 20; w++) {
        int idx = threadIdx.x + w * 256;
        int nl = idx & 31;
        int p = idx >> 5;
        int t = p / 20, j = p - t * 20;
        so[(t * 32 + nl) * 20 + j] = __float2bfloat16_rn(sm[nl * 161 + j * 8 + t]);
    }
    __syncthreads();
    const uint32_t* sou = reinterpret_cast<const uint32_t*>(so);
    uint32_t* dst = reinterpret_cast<uint32_t*>(g_xT16);
    #pragma unroll
    for (int w = 0; w < 10; w++) {
        int idx = threadIdx.x + w * 256;           // 0..2559
        int t = idx / 320;
        int rem = idx - t * 320;
        dst[((size_t)t * N_NODES + n0) * 10 + rem] = sou[idx];
    }
}

// Fold GNN projection into gate weights; interleaved row layout + K-order
// [agg(0..63) | h(64..127) | x(128..147) | pad(148..159)].
__global__ void prep_weights(const float* __restrict__ W_ih, const float* __restrict__ W_hh,
                             const float* __restrict__ b_ih, const float* __restrict__ b_hh,
                             const float* __restrict__ W_rel, const float* __restrict__ b_rel,
                             const float* __restrict__ W_root) {
    int rp = blockIdx.x;
    int block16 = rp >> 4, within = rp & 15;
    int vl, q;
    if (within < 8) { vl = within >> 1; q = within & 1; }
    else            { vl = (within - 8) >> 1; q = 2 + ((within - 8) & 1); }
    int u = block16 * 4 + vl;
    int r = q * 64 + u;
    __shared__ float wg[64];
    int tid = threadIdx.x;  // 64 threads
    wg[tid] = W_ih[r * 84 + 20 + tid];
    __syncthreads();
    int c = tid;
    float m1 = 0.f, m2 = 0.f;
    #pragma unroll 8
    for (int j = 0; j < 64; j++) {
        float w = wg[j];
        m1 += w * W_rel[j * 64 + c];
        m2 += w * W_root[j * 64 + c];
    }
    m2 += W_hh[r * 64 + c];
    g_Wb[rp * 160 + c] = __float2bfloat16_rn(m1);        // agg block
    g_Wb[rp * 160 + 64 + c] = __float2bfloat16_rn(m2);   // h block
    if (c < 20) g_Wb[rp * 160 + 128 + c] = __float2bfloat16_rn(W_ih[r * 84 + c]); // x
    if (c < 12) g_Wb[rp * 160 + 148 + c] = __float2bfloat16_rn(0.f);
    if (c == 0) {
        float s = b_ih[r] + b_hh[r];
        for (int j = 0; j < 64; j++) s += wg[j] * b_rel[j];
        g_bias[u * 4 + q] = s;
    }
}

// bf16 copies of head weights.
__global__ void prep_head(const float* __restrict__ W1, const float* __restrict__ W2,
                          const float* __restrict__ W_rel, const float* __restrict__ W_root) {
    int i = blockIdx.x * 256 + threadIdx.x;
    if (i < 8192) {
        g_W1b[i] = __float2bfloat16_rn(W1[i]);
    } else if (i < 16384) {
        g_W2b[i - 8192] = __float2bfloat16_rn(W2[i - 8192]);
    } else if (i < 24576) {
        int j = i - 16384;
        int o = j >> 7, k = j & 127;
        float v = (k < 64) ? W_rel[o * 64 + k] : W_root[o * 64 + k - 64];
        g_Whb[j] = __float2bfloat16_rn(v);
    }
}

// ---------------- aggregation: warp per dst node, bf16 gather ----------------
// ah record: [n][0:64)=agg, [64:128)=h. Reads h from buf, writes agg into buf.
__global__ void agg_kernel(__nv_bfloat16* __restrict__ ah) {
    int gw = (blockIdx.x * blockDim.x + threadIdx.x) >> 5;
    int lane = threadIdx.x & 31;
    if (gw >= N_NODES) return;
    int beg = g_offs[gw], end = g_offs[gw + 1];
    float2 acc = make_float2(0.f, 0.f);
    int e = beg;
    for (; e + 4 <= end; e += 4) {
        int s0 = g_ssrc[e], s1 = g_ssrc[e + 1], s2 = g_ssrc[e + 2], s3 = g_ssrc[e + 3];
        float2 v0 = __bfloat1622float2(
            *reinterpret_cast<const __nv_bfloat162*>(ah + (size_t)s0 * 128 + 64 + lane * 2));
        float2 v1 = __bfloat1622float2(
            *reinterpret_cast<const __nv_bfloat162*>(ah + (size_t)s1 * 128 + 64 + lane * 2));
        float2 v2 = __bfloat1622float2(
            *reinterpret_cast<const __nv_bfloat162*>(ah + (size_t)s2 * 128 + 64 + lane * 2));
        float2 v3 = __bfloat1622float2(
            *reinterpret_cast<const __nv_bfloat162*>(ah + (size_t)s3 * 128 + 64 + lane * 2));
        acc.x += (v0.x + v1.x) + (v2.x + v3.x);
        acc.y += (v0.y + v1.y) + (v2.y + v3.y);
    }
    for (; e < end; e++) {
        int s = g_ssrc[e];
        float2 v = __bfloat1622float2(
            *reinterpret_cast<const __nv_bfloat162*>(ah + (size_t)s * 128 + 64 + lane * 2));
        acc.x += v.x;
        acc.y += v.y;
    }
    *reinterpret_cast<__nv_bfloat162*>(ah + (size_t)gw * 128 + lane * 2) =
        __float22bfloat162_rn(acc);
}

// ---------------- bf16 mma.sync gate GEMM + fused LSTM epilogue ----------------
// Tile: 128 nodes x 64 gate cols (grid y = 4). 8 warps = 4m x 2n, warp 32x32.
// smem: A[128][336B] @0 (43008), B[64][336B] @43008 (21504). 3 CTAs/SM.
// A K-order: [agg|h @0 (256B, 16-aligned) | x @256 | pad @296].
#define GATE_SMEM 64512

__global__ void __launch_bounds__(256, 3)
gate_kernel(const __nv_bfloat16* __restrict__ xTt16,
            const __nv_bfloat16* __restrict__ ah_in,
            float* __restrict__ h_out, __nv_bfloat16* __restrict__ ah_out,
            int t0, int wf32) {
    extern __shared__ char smem[];
    const int tid = threadIdx.x;
    const int wid = tid >> 5;
    const int lane = tid & 31;
    const int n0 = blockIdx.x * 128;
    const int col0 = blockIdx.y * 64;    // gate-col base (0/64/128/192)
    const int ubase = col0 >> 2;         // unit base (16 units per CTA)
    const uint32_t sbase = smem_u32(smem);

    // ---- stage B via cp.async: 64 interleaved weight rows x 160 bf16 ----
    {
        const char* wsrc = reinterpret_cast<const char*>(g_Wb) + (size_t)col0 * 320;
        #pragma unroll
        for (int it = 0; it < 5; it++) {
            int idx = tid + it * 256;        // 0..1279 = r*20 + c
            int r = idx / 20;
            int c = idx - r * 20;
            CP_ASYNC_16(sbase + 43008u + r * 336 + c * 16, wsrc + r * 320 + c * 16);
        }
    }
    // ---- A: agg|h record (k 0..127): 256B contiguous, 16B cp.async (both aligned) ----
    {
        const char* asrc = reinterpret_cast<const char*>(ah_in);
        #pragma unroll
        for (int it = 0; it < 8; it++) {
            int idx = tid + it * 256;        // 0..2047 = nl*16 + q
            int nl = idx >> 4;
            int q = idx & 15;
            int n = n0 + nl;
            int ncl = (n < N_NODES) ? n : (N_NODES - 1);
            uint32_t ssz = (!t0 && n < N_NODES) ? 16u : 0u;
            CP_ASYNC_16S(sbase + nl * 336 + q * 16, asrc + (size_t)ncl * 256 + q * 16, ssz);
        }
    }
    // ---- A: x bf16 (k 128..147): 8B cp.async (40B row is 8-aligned) ----
    {
        const char* xsrc = reinterpret_cast<const char*>(xTt16);
        #pragma unroll
        for (int it = 0; it < 3; it++) {
            int idx = tid + it * 256;        // need 640 = nl*5 + p
            if (idx < 640) {
                int nl = idx / 5;
                int p = idx - nl * 5;
                int n = n0 + nl;
                int ncl = (n < N_NODES) ? n : (N_NODES - 1);
                uint32_t ssz = (n < N_NODES) ? 8u : 0u;
                CP_ASYNC_8S(sbase + nl * 336 + 256 + p * 8, xsrc + (size_t)ncl * 40 + p * 8, ssz);
            }
        }
    }
    // ---- A: zero pad (k 148..167) plain stores ----
    #pragma unroll
    for (int it = 0; it < 3; it++) {
        int idx = tid + it * 256;
        if (idx < 640) {
            int nl = idx / 5;
            int p = idx - nl * 5;
            *reinterpret_cast<uint2*>(smem + nl * 336 + 296 + p * 8) = make_uint2(0u, 0u);
        }
    }
    CP_ASYNC_COMMIT();
    CP_ASYNC_WAIT0();
    __syncthreads();

    // ---- mma mainloop: warp tile 32 rows x 32 cols ----
    const int mw = wid >> 1;                 // 0..3
    const int nw = wid & 1;                  // 0..1
    const int mr = mw * 32;
    const int ncw = nw * 32;                 // col within CTA tile (0 or 32)
    uint32_t aAddr = sbase + (mr + (lane & 15)) * 336 + ((lane >> 4) << 4);
    uint32_t bAddr = sbase + 43008u + (ncw + (lane & 15)) * 336 + ((lane >> 4) << 4);

    float acc[2][4][4];
    #pragma unroll
    for (int mi = 0; mi < 2; mi++)
        #pragma unroll
        for (int nj = 0; nj < 4; nj++)
            #pragma unroll
            for (int e = 0; e < 4; e++) acc[mi][nj][e] = 0.f;

    #pragma unroll
    for (int ks = 0; ks < 10; ks++) {
        uint32_t a[2][4];
        ldsm_x4(a[0], aAddr + ks * 32);
        ldsm_x4(a[1], aAddr + 16 * 336 + ks * 32);
        uint32_t b[2][4];
        ldsm_x4(b[0], bAddr + ks * 32);
        ldsm_x4(b[1], bAddr + 16 * 336 + ks * 32);
        #pragma unroll
        for (int mi = 0; mi < 2; mi++)
            #pragma unroll
            for (int nj2 = 0; nj2 < 4; nj2++) {
                int nj = nj2 >> 1, hi = nj2 & 1;
                mma_bf16(acc[mi][nj2], a[mi], b[nj][hi], b[nj][hi + 2]);
            }
    }

    // ---- c fragments + bias quads: direct gmem -> registers ----
    float* cptr = g_cperm + (((size_t)(blockIdx.x * 4 + blockIdx.y)) * 256 + tid) * 8;
    float creg[8];
    if (!t0) {
        float4 ca = *reinterpret_cast<const float4*>(cptr);
        float4 cb = *reinterpret_cast<const float4*>(cptr + 4);
        creg[0] = ca.x; creg[1] = ca.y; creg[2] = ca.z; creg[3] = ca.w;
        creg[4] = cb.x; creg[5] = cb.y; creg[6] = cb.z; creg[7] = cb.w;
    } else {
        #pragma unroll
        for (int i = 0; i < 8; i++) creg[i] = 0.f;
    }
    const int vl = lane & 3;
    const float4* bias4 = reinterpret_cast<const float4*>(g_bias) + ubase;
    float4 bq[2];
    bq[0] = bias4[(wid & 1) * 8 + vl];
    bq[1] = bias4[(wid & 1) * 8 + 4 + vl];

    __syncthreads();

    // ---- repurpose smem: Hs fp32 [128][18] @0 ----
    float* Hs = reinterpret_cast<float*>(smem);

    // ---- fused LSTM epilogue (shuffle-free; c in registers) ----
    #pragma unroll
    for (int mi = 0; mi < 2; mi++) {
        int r = mr + mi * 16 + (lane >> 2);
        #pragma unroll
        for (int b = 0; b < 2; b++) {
            int u = nw * 8 + b * 4 + vl;     // unit within CTA (0..15)
            float4 q = bq[b];
            int ci = mi * 4 + b * 2;
            {
                float ig = acc[mi][2 * b][0] + q.x;
                float fg = acc[mi][2 * b][1] + q.y;
                float gg = acc[mi][2 * b + 1][0] + q.z;
                float og = acc[mi][2 * b + 1][1] + q.w;
                float si = fast_sigmoid(ig), sf = fast_sigmoid(fg);
                float so = fast_sigmoid(og), tg = fast_tanh(gg);
                float cn = sf * creg[ci] + si * tg;
                creg[ci] = cn;
                Hs[r * 18 + u] = so * fast_tanh(cn);
            }
            {
                float ig = acc[mi][2 * b][2] + q.x;
                float fg = acc[mi][2 * b][3] + q.y;
                float gg = acc[mi][2 * b + 1][2] + q.z;
                float og = acc[mi][2 * b + 1][3] + q.w;
                float si = fast_sigmoid(ig), sf = fast_sigmoid(fg);
                float so = fast_sigmoid(og), tg = fast_tanh(gg);
                float cn = sf * creg[ci + 1] + si * tg;
                creg[ci + 1] = cn;
                Hs[(r + 8) * 18 + u] = so * fast_tanh(cn);
            }
        }
    }
    // store c fragments back
    *reinterpret_cast<float4*>(cptr) = make_float4(creg[0], creg[1], creg[2], creg[3]);
    *reinterpret_cast<float4*>(cptr + 4) = make_float4(creg[4], creg[5], creg[6], creg[7]);
    __syncthreads();

    // ---- coalesced h writeback into ah record [64:128) ----
    #pragma unroll
    for (int it = 0; it < 4; it++) {
        int idx = tid + it * 256;            // 0..1023 = rr*8 + up
        int rr = idx >> 3;
        int up = idx & 7;
        int n = n0 + rr;
        if (n < N_NODES) {
            float2 hv = *reinterpret_cast<const float2*>(&Hs[rr * 18 + up * 2]);
            *reinterpret_cast<__nv_bfloat162*>(
                ah_out + (size_t)n * 128 + 64 + ubase + up * 2) = __float22bfloat162_rn(hv);
            if (wf32)
                *reinterpret_cast<float2*>(h_out + (size_t)n * 64 + ubase + up * 2) = hv;
        }
    }
}

// ---------------- head1: gnn = [agg|h] @ [W_rel|W_root]^T + b_rel (mma) ------
#define H1_SMEM 52480

__global__ void __launch_bounds__(256)
head1_kernel(const __nv_bfloat16* __restrict__ ah, const float* __restrict__ b_rel) {
    extern __shared__ char smem[];
    const int tid = threadIdx.x;
    const int wid = tid >> 5;
    const int lane = tid & 31;
    const int n0 = blockIdx.x * 128;
    float* sb = reinterpret_cast<float*>(smem + 52224);

    {
        const uint4* Wh4 = reinterpret_cast<const uint4*>(g_Whb);
        #pragma unroll
        for (int it = 0; it < 4; it++) {
            int idx = tid + it * 256;
            int r = idx >> 4, c16 = idx & 15;
            *reinterpret_cast<uint4*>(smem + 34816 + r * 272 + c16 * 16) = Wh4[idx];
        }
    }
    #pragma unroll
    for (int it = 0; it < 8; it++) {
        int idx = tid + it * 256;
        int nl = idx >> 4, q = idx & 15;
        int n = n0 + nl;
        uint4 v = make_uint4(0u, 0u, 0u, 0u);
        if (n < N_NODES)
            v = reinterpret_cast<const uint4*>(ah + (size_t)n * 128)[q];
        *reinterpret_cast<uint4*>(smem + nl * 272 + q * 16) = v;
    }
    if (tid < 128)
        *reinterpret_cast<uint4*>(smem + tid * 272 + 256) = make_uint4(0u, 0u, 0u, 0u);
    if (tid < 64) sb[tid] = b_rel[tid];
    __syncthreads();

    const int mw = wid >> 1;
    const int nw = wid & 1;
    const int mr = mw * 32;
    const int nc = nw * 32;
    const uint32_t sbase = smem_u32(smem);
    uint32_t aAddr = sbase + (mr + (lane & 15)) * 272 + ((lane >> 4) << 4);
    uint32_t bAddr = sbase + 34816u + (nc + (lane & 15)) * 272 + ((lane >> 4) << 4);

    float acc[2][4][4];
    #pragma unroll
    for (int mi = 0; mi < 2; mi++)
        #pragma unroll
        for (int nj = 0; nj < 4; nj++)
            #pragma unroll
            for (int e = 0; e < 4; e++) acc[mi][nj][e] = 0.f;

    #pragma unroll
    for (int ks = 0; ks < 8; ks++) {
        uint32_t a[2][4];
        ldsm_x4(a[0], aAddr + ks * 32);
        ldsm_x4(a[1], aAddr + 16 * 272 + ks * 32);
        uint32_t b[2][4];
        ldsm_x4(b[0], bAddr + ks * 32);
        ldsm_x4(b[1], bAddr + 16 * 272 + ks * 32);
        #pragma unroll
        for (int mi = 0; mi < 2; mi++)
            #pragma unroll
            for (int nj2 = 0; nj2 < 4; nj2++) {
                int nj = nj2 >> 1, hi = nj2 & 1;
                mma_bf16(acc[mi][nj2], a[mi], b[nj][hi], b[nj][hi + 2]);
            }
    }
    __syncthreads();

    float* Gs = reinterpret_cast<float*>(smem);
    #pragma unroll
    for (int mi = 0; mi < 2; mi++) {
        int row = mr + mi * 16 + (lane >> 2);
        #pragma unroll
        for (int nj2 = 0; nj2 < 4; nj2++) {
            int c = nc + nj2 * 8 + (lane & 3) * 2;
            *reinterpret_cast<float2*>(&Gs[row * 68 + c]) =
                make_float2(acc[mi][nj2][0] + sb[c], acc[mi][nj2][1] + sb[c + 1]);
            *reinterpret_cast<float2*>(&Gs[(row + 8) * 68 + c]) =
                make_float2(acc[mi][nj2][2] + sb[c], acc[mi][nj2][3] + sb[c + 1]);
        }
    }
    __syncthreads();

    #pragma unroll
    for (int it = 0; it < 32; it++) {
        int idx = tid + it * 256;
        int rr = idx >> 6, u = idx & 63;
        int n = n0 + rr;
        if (n < N_NODES) g_gnn[(size_t)n * 64 + u] = Gs[rr * 68 + u];
    }
}

// ---------------- head2: fused layernorm + MLP + out-projection (mma) --------
#define H2_SMEM 90880

__global__ void __launch_bounds__(256)
head2_kernel(const float* __restrict__ hfin, const float* __restrict__ b1,
             const float* __restrict__ b2, const float* __restrict__ Wout,
             const float* __restrict__ bout, float* __restrict__ out) {
    extern __shared__ char smem[];
    const int tid = threadIdx.x;
    const int wid = tid >> 5;
    const int lane = tid & 31;
    const int n0 = blockIdx.x * 128;
    float* sb1 = reinterpret_cast<float*>(smem + 89088);
    float* sb2 = reinterpret_cast<float*>(smem + 89344);
    float* sWout = reinterpret_cast<float*>(smem + 89856);
    float* sdot = reinterpret_cast<float*>(smem + 90368);

    #pragma unroll
    for (int it = 0; it < 32; it++) {
        int idx = tid + it * 256;
        int nl = idx >> 6, cp = idx & 63;
        int c = cp * 2;
        int n = n0 + nl;
        float2 v = make_float2(0.f, 0.f);
        if (n < N_NODES) {
            v = (cp < 32)
                ? reinterpret_cast<const float2*>(hfin)[(size_t)n * 32 + cp]
                : reinterpret_cast<const float2*>(g_gnn)[(size_t)n * 32 + cp - 32];
        }
        float2 nv = make_float2(v.x * g_scale[c] + g_shift[c],
                                v.y * g_scale[c + 1] + g_shift[c + 1]);
        *reinterpret_cast<__nv_bfloat162*>(smem + nl * 272 + c * 2) =
            __float22bfloat162_rn(nv);
    }
    if (tid < 128)
        *reinterpret_cast<uint4*>(smem + tid * 272 + 256) = make_uint4(0u, 0u, 0u, 0u);
    {
        const uint4* W14 = reinterpret_cast<const uint4*>(g_W1b);
        #pragma unroll
        for (int it = 0; it < 4; it++) {
            int idx = tid + it * 256;
            int r = idx >> 4, c16 = idx & 15;
            *reinterpret_cast<uint4*>(smem + 34816 + r * 272 + c16 * 16) = W14[idx];
        }
        const uint4* W24 = reinterpret_cast<const uint4*>(g_W2b);
        #pragma unroll
        for (int it = 0; it < 4; it++) {
            int idx = tid + it * 256;
            int r = idx >> 3, c8 = idx & 7;
            *reinterpret_cast<uint4*>(smem + 70656 + r * 144 + c8 * 16) = W24[idx];
        }
    }
    if (tid < 64) sb1[tid] = b1[tid];
    if (tid < 128) {
        sb2[tid] = b2[tid];
        sWout[tid] = Wout[tid];
        sdot[tid] = 0.f;
    }
    __syncthreads();

    const int mw = wid >> 1;
    const int nw = wid & 1;
    const int mr = mw * 32;
    const uint32_t sbase = smem_u32(smem);

    {
        const int nc = nw * 32;
        uint32_t aAddr = sbase + (mr + (lane & 15)) * 272 + ((lane >> 4) << 4);
        uint32_t bAddr = sbase + 34816u + (nc + (lane & 15)) * 272 + ((lane >> 4) << 4);
        float acc1[2][4][4];
        #pragma unroll
        for (int mi = 0; mi < 2; mi++)
            #pragma unroll
            for (int nj = 0; nj < 4; nj++)
                #pragma unroll
                for (int e = 0; e < 4; e++) acc1[mi][nj][e] = 0.f;
        #pragma unroll
        for (int ks = 0; ks < 8; ks++) {
            uint32_t a[2][4];
            ldsm_x4(a[0], aAddr + ks * 32);
            ldsm_x4(a[1], aAddr + 16 * 272 + ks * 32);
            uint32_t b[2][4];
            ldsm_x4(b[0], bAddr + ks * 32);
            ldsm_x4(b[1], bAddr + 16 * 272 + ks * 32);
            #pragma unroll
            for (int mi = 0; mi < 2; mi++)
                #pragma unroll
                for (int nj2 = 0; nj2 < 4; nj2++) {
                    int nj = nj2 >> 1, hi = nj2 & 1;
                    mma_bf16(acc1[mi][nj2], a[mi], b[nj][hi], b[nj][hi + 2]);
                }
        }
        #pragma unroll
        for (int mi = 0; mi < 2; mi++) {
            int row = mr + mi * 16 + (lane >> 2);
            #pragma unroll
            for (int nj2 = 0; nj2 < 4; nj2++) {
                int c = nc + nj2 * 8 + (lane & 3) * 2;
                float v0 = fmaxf(acc1[mi][nj2][0] + sb1[c], 0.f);
                float v1 = fmaxf(acc1[mi][nj2][1] + sb1[c + 1], 0.f);
                float v2 = fmaxf(acc1[mi][nj2][2] + sb1[c], 0.f);
                float v3 = fmaxf(acc1[mi][nj2][3] + sb1[c + 1], 0.f);
                *reinterpret_cast<__nv_bfloat162*>(smem + 52224 + row * 144 + c * 2) =
                    __float22bfloat162_rn(make_float2(v0, v1));
                *reinterpret_cast<__nv_bfloat162*>(smem + 52224 + (row + 8) * 144 + c * 2) =
                    __float22bfloat162_rn(make_float2(v2, v3));
            }
        }
    }
    __syncthreads();

    {
        const int nc = nw * 64;
        uint32_t aAddr = sbase + 52224u + (mr + (lane & 15)) * 144 + ((lane >> 4) << 4);
        uint32_t bAddr = sbase + 70656u + (nc + (lane & 15)) * 144 + ((lane >> 4) << 4);
        float acc2[2][8][4];
        #pragma unroll
        for (int mi = 0; mi < 2; mi++)
            #pragma unroll
            for (int nj = 0; nj < 8; nj++)
                #pragma unroll
                for (int e = 0; e < 4; e++) acc2[mi][nj][e] = 0.f;
        #pragma unroll
        for (int ks = 0; ks < 4; ks++) {
            uint32_t a[2][4];
            ldsm_x4(a[0], aAddr + ks * 32);
            ldsm_x4(a[1], aAddr + 16 * 144 + ks * 32);
            uint32_t b[4][4];
            #pragma unroll
            for (int nj = 0; nj < 4; nj++)
                ldsm_x4(b[nj], bAddr + nj * 16 * 144 + ks * 32);
            #pragma unroll
            for (int mi = 0; mi < 2; mi++)
                #pragma unroll
                for (int nj2 = 0; nj2 < 8; nj2++) {
                    int nj = nj2 >> 1, hi = nj2 & 1;
                    mma_bf16(acc2[mi][nj2], a[mi], b[nj][hi], b[nj][hi + 2]);
                }
        }
        #pragma unroll
        for (int mi = 0; mi < 2; mi++) {
            float p0 = 0.f, p1 = 0.f;
            #pragma unroll
            for (int nj2 = 0; nj2 < 8; nj2++) {
                int c = nc + nj2 * 8 + (lane & 3) * 2;
                float w0 = sWout[c], w1 = sWout[c + 1];
                p0 += fmaxf(acc2[mi][nj2][0] + sb2[c], 0.f) * w0
                    + fmaxf(acc2[mi][nj2][1] + sb2[c + 1], 0.f) * w1;
                p1 += fmaxf(acc2[mi][nj2][2] + sb2[c], 0.f) * w0
                    + fmaxf(acc2[mi][nj2][3] + sb2[c + 1], 0.f) * w1;
            }
            p0 += __shfl_xor_sync(0xFFFFFFFFu, p0, 1);
            p0 += __shfl_xor_sync(0xFFFFFFFFu, p0, 2);
            p1 += __shfl_xor_sync(0xFFFFFFFFu, p1, 1);
            p1 += __shfl_xor_sync(0xFFFFFFFFu, p1, 2);
            if ((lane & 3) == 0) {
                int row = mr + mi * 16 + (lane >> 2);
                atomicAdd(&sdot[row], p0);
                atomicAdd(&sdot[row + 8], p1);
            }
        }
    }
    __syncthreads();

    if (tid < 128) {
        int n = n0 + tid;
        if (n < N_NODES) {
            float s = sdot[tid] + bout[0];
            out[n] = 1.f / (1.f + __expf(-s));
        }
    }
}

// ---------------- per-feature stats over nodes ----------------
__global__ void stats_kernel(const float* __restrict__ h, const float* __restrict__ gnn) {
    int c = threadIdx.x & 127;
    int grp = threadIdx.x >> 7;
    int r0 = blockIdx.x * 256;
    int rend = min(r0 + 256, N_NODES);
    float s = 0.f, q = 0.f;
    for (int r = r0 + grp; r < rend; r += 2) {
        float v = (c < 64) ? h[(size_t)r * 64 + c] : gnn[(size_t)r * 64 + c - 64];
        s += v;
        q += v * v;
    }
    atomicAdd(&g_stats[c], s);
    atomicAdd(&g_stats[128 + c], q);
}

__global__ void finalize_stats(const float* __restrict__ gamma, const float* __restrict__ beta) {
    int c = threadIdx.x;
    float mean = g_stats[c] / (float)N_NODES;
    float var = g_stats[128 + c] / (float)N_NODES - mean * mean;
    float rstd = rsqrtf(var + 1e-5f);
    float sc = rstd * gamma[c];
    g_scale[c] = sc;
    g_shift[c] = beta[c] - mean * sc;
}

// ---------------- launch (CSR chain forked onto a second stream) ----------------
extern "C" void kernel_launch(void* const* d_in, const int* in_sizes, int n_in,
                              void* d_out, int out_size) {
    const float* x      = (const float*)d_in[0];
    const void*  ei     = d_in[1];
    const float* W_ih   = (const float*)d_in[4];
    const float* W_hh   = (const float*)d_in[5];
    const float* b_ih   = (const float*)d_in[6];
    const float* b_hh   = (const float*)d_in[7];
    const float* W_rel  = (const float*)d_in[8];
    const float* b_rel  = (const float*)d_in[9];
    const float* W_root = (const float*)d_in[10];
    const float* gamma  = (const float*)d_in[11];
    const float* beta   = (const float*)d_in[12];
    const float* W1     = (const float*)d_in[13];
    const float* b1     = (const float*)d_in[14];
    const float* W2     = (const float*)d_in[15];
    const float* b2     = (const float*)d_in[16];
    const float* W_out  = (const float*)d_in[17];
    const float* b_out  = (const float*)d_in[18];

    float *hbuf, *gnn;
    __nv_bfloat16 *ah, *xT16;
    cudaGetSymbolAddress((void**)&hbuf, g_hbuf);
    cudaGetSymbolAddress((void**)&ah, g_ah);
    cudaGetSymbolAddress((void**)&gnn, g_gnn);
    cudaGetSymbolAddress((void**)&xT16, g_xT16);

    static cudaStream_t s2 = nullptr;
    static cudaEvent_t evA = nullptr, evB = nullptr;
    if (!s2) {
        cudaStreamCreateWithFlags(&s2, cudaStreamNonBlocking);
        cudaEventCreateWithFlags(&evA, cudaEventDisableTiming);
        cudaEventCreateWithFlags(&evB, cudaEventDisableTiming);
        cudaFuncSetAttribute(gate_kernel, cudaFuncAttributeMaxDynamicSharedMemorySize, GATE_SMEM);
        cudaFuncSetAttribute(head1_kernel, cudaFuncAttributeMaxDynamicSharedMemorySize, H1_SMEM);
        cudaFuncSetAttribute(head2_kernel, cudaFuncAttributeMaxDynamicSharedMemorySize, H2_SMEM);
    }

    const int scan_blocks = (N_NODES + 1023) / 1024;   // 98
    dim3 ggrid(N_TILES, 4);

    cudaEventRecord(evA, 0);   // fork point

    // ---- main stream: weights + x + gate t=0 (gate stays launch #4) ----
    zero_stats<<<1, 256>>>();
    prep_weights<<<256, 64>>>(W_ih, W_hh, b_ih, b_hh, W_rel, b_rel, W_root);
    transpose_x<<<N_NODES / 32, 256>>>(x);
    gate_kernel<<<ggrid, 256, GATE_SMEM>>>(xT16, ah, hbuf, ah + (size_t)N_NODES * 128, 1, 0);

    // ---- S2: CSR build chain, concurrent with the above (disjoint buffers) ----
    cudaStreamWaitEvent(s2, evA, 0);
    zero_deg<<<256, 256, 0, s2>>>();
    detect_kernel<<<1, 256, 0, s2>>>((const unsigned int*)ei);
    prep_head<<<96, 256, 0, s2>>>(W1, W2, W_rel, W_root);
    hist2_kernel<<<512, 256, 0, s2>>>(ei);
    scan1_kernel<<<scan_blocks, 1024, 0, s2>>>();
    scan2_kernel<<<1, 128, 0, s2>>>(scan_blocks);
    scan3_kernel<<<(N_NODES + 255) / 256, 256, 0, s2>>>();
    scatter_kernel<<<512, 256, 0, s2>>>(ei);
    cudaEventRecord(evB, s2);

    // ---- main: join CSR, then the recurrent loop ----
    cudaStreamWaitEvent(0, evB, 0);
    for (int t = 1; t < T_STEPS; t++) {
        __nv_bfloat16* ah_in = ah + (size_t)(t & 1) * N_NODES * 128;
        __nv_bfloat16* ah_out = ah + (size_t)((t + 1) & 1) * N_NODES * 128;
        agg_kernel<<<(N_NODES * 32 + 255) / 256, 256>>>(ah_in);
        gate_kernel<<<ggrid, 256, GATE_SMEM>>>(
            xT16 + (size_t)t * N_NODES * 20, ah_in, hbuf, ah_out,
            0, t == T_STEPS - 1 ? 1 : 0);
    }

    // ---- sequential tail (head1 writes gnn; stats reads it) ----
    head1_kernel<<<N_TILES, 256, H1_SMEM>>>(ah + (size_t)N_NODES * 128, b_rel);
    stats_kernel<<<(N_NODES + 255) / 256, 256>>>(hbuf, gnn);
    finalize_stats<<<1, 128>>>(gamma, beta);
    head2_kernel<<<N_TILES, 256, H2_SMEM>>>(hbuf, b1, b2, W_out, b_out, (float*)d_out);
}

// round 17
// speedup vs baseline: 2.3524x; 1.0365x over previous
#include <cuda_runtime.h>
#include <cuda_bf16.h>
#include <math.h>
#include <cstdint>

#define N_NODES 100000
#define N_EDGES 1600000
#define T_STEPS 8
#define N_TILES 782   // ceil(N_NODES/128)

// ---------------- device scratch (no allocations allowed) ----------------
__device__ float g_hbuf[N_NODES * 64];                     // fp32 final h (t=7 only)
// interleaved per-node record: [0:64)=agg, [64:128)=h ; double buffered
__device__ __align__(16) __nv_bfloat16 g_ah[2 * N_NODES * 128];
__device__ __align__(16) float g_cperm[N_TILES * 4 * 256 * 8];  // c in fragment order
__device__ float g_gnn[N_NODES * 64];
__device__ __align__(16) __nv_bfloat16 g_xT16[T_STEPS * N_NODES * 20];  // [t][n][20]
// gate weights, K-order [agg(64)|h(64)|x(20)|pad(12)], interleaved rows
__device__ __align__(16) __nv_bfloat16 g_Wb[256 * 160];
__device__ __align__(16) __nv_bfloat16 g_W1b[64 * 128];
__device__ __align__(16) __nv_bfloat16 g_W2b[128 * 64];
__device__ __align__(16) __nv_bfloat16 g_Whb[64 * 128];    // [W_rel | W_root]
__device__ __align__(16) float g_bias[256];                // per-unit quads (i,f,g,o)
__device__ float g_stats[256];    // [0:64) h-sum, [64:128) gnn-sum, [128:192) h-sq, [192:256) gnn-sq
__device__ float g_scale[128];
__device__ float g_shift[128];
__device__ int   g_deg4[4 * N_NODES];
__device__ int   g_cur4[4 * N_NODES];
__device__ int   g_offs[N_NODES + 1];
__device__ int   g_ssrc[N_EDGES];
__device__ int   g_bsums[128];
__device__ int   g_boffs[128];
__device__ int   g_is64;

// ---------------- mma/ldmatrix/cp.async helpers ----------------
__device__ __forceinline__ uint32_t smem_u32(const void* p) {
    uint32_t a;
    asm("{ .reg .u64 tmp; cvta.to.shared.u64 tmp, %1; cvt.u32.u64 %0, tmp; }"
        : "=r"(a) : "l"(p));
    return a;
}
__device__ __forceinline__ void ldsm_x4(uint32_t* r, uint32_t addr) {
    asm volatile("ldmatrix.sync.aligned.m8n8.x4.shared.b16 {%0,%1,%2,%3}, [%4];"
                 : "=r"(r[0]), "=r"(r[1]), "=r"(r[2]), "=r"(r[3]) : "r"(addr));
}
__device__ __forceinline__ void mma_bf16(float* d, const uint32_t* a,
                                         uint32_t b0, uint32_t b1) {
    asm volatile(
        "mma.sync.aligned.m16n8k16.row.col.f32.bf16.bf16.f32 "
        "{%0,%1,%2,%3}, {%4,%5,%6,%7}, {%8,%9}, {%0,%1,%2,%3};"
        : "+f"(d[0]), "+f"(d[1]), "+f"(d[2]), "+f"(d[3])
        : "r"(a[0]), "r"(a[1]), "r"(a[2]), "r"(a[3]), "r"(b0), "r"(b1));
}
__device__ __forceinline__ float fast_tanh(float x) {
    float y;
    asm("tanh.approx.f32 %0, %1;" : "=f"(y) : "f"(x));
    return y;
}
__device__ __forceinline__ float fast_sigmoid(float x) {
    return 0.5f * fast_tanh(0.5f * x) + 0.5f;
}
#define CP_ASYNC_16(dst, src) \
    asm volatile("cp.async.ca.shared.global [%0], [%1], 16;" :: "r"(dst), "l"(src))
#define CP_ASYNC_16S(dst, src, ssz) \
    asm volatile("cp.async.ca.shared.global [%0], [%1], 16, %2;" :: "r"(dst), "l"(src), "r"(ssz))
#define CP_ASYNC_8S(dst, src, ssz) \
    asm volatile("cp.async.ca.shared.global [%0], [%1], 8, %2;" :: "r"(dst), "l"(src), "r"(ssz))
#define CP_ASYNC_COMMIT() asm volatile("cp.async.commit_group;" ::: "memory")
#define CP_ASYNC_WAIT0()  asm volatile("cp.async.wait_group 0;" ::: "memory")

// ---------------- small utility kernels ----------------
__global__ void zero_stats() {
    if (threadIdx.x < 256 && blockIdx.x == 0) g_stats[threadIdx.x] = 0.f;
}

__global__ void zero_deg() {
    int stride = gridDim.x * blockDim.x;
    int i0 = blockIdx.x * blockDim.x + threadIdx.x;
    for (int k = i0; k < 4 * N_NODES; k += stride) g_deg4[k] = 0;
}

__global__ void detect_kernel(const unsigned int* __restrict__ w) {
    __shared__ unsigned int acc;
    if (threadIdx.x == 0) acc = 0u;
    __syncthreads();
    unsigned int v = 0u;
    for (int i = threadIdx.x; i < 2048; i += blockDim.x) v |= w[2 * i + 1];
    atomicOr(&acc, v);
    __syncthreads();
    if (threadIdx.x == 0) g_is64 = (acc == 0u) ? 1 : 0;
}

__device__ __forceinline__ int edge_val(const void* ei, long long idx) {
    if (g_is64) return (int)((const long long*)ei)[idx];
    return ((const int*)ei)[idx];
}

__global__ void hist2_kernel(const void* __restrict__ ei) {
    int stride = gridDim.x * blockDim.x;
    for (int e = blockIdx.x * blockDim.x + threadIdx.x; e < N_EDGES; e += stride) {
        int d = edge_val(ei, (long long)N_EDGES + e);
        atomicAdd(&g_deg4[(e & 3) * N_NODES + d], 1);
    }
}

__global__ void scan1_kernel() {
    __shared__ int warpsums[32];
    int tid = threadIdx.x, lane = tid & 31, wid = tid >> 5;
    int i = blockIdx.x * 1024 + tid;
    int v = 0;
    if (i < N_NODES)
        v = g_deg4[i] + g_deg4[N_NODES + i] + g_deg4[2 * N_NODES + i]
          + g_deg4[3 * N_NODES + i];
    int x = v;
    #pragma unroll
    for (int off = 1; off < 32; off <<= 1) {
        int y = __shfl_up_sync(0xFFFFFFFFu, x, off);
        if (lane >= off) x += y;
    }
    if (lane == 31) warpsums[wid] = x;
    __syncthreads();
    if (wid == 0) {
        int wv = warpsums[lane];
        #pragma unroll
        for (int off = 1; off < 32; off <<= 1) {
            int y = __shfl_up_sync(0xFFFFFFFFu, wv, off);
            if (lane >= off) wv += y;
        }
        warpsums[lane] = wv;
    }
    __syncthreads();
    int woff = (wid == 0) ? 0 : warpsums[wid - 1];
    if (i < N_NODES) g_offs[i] = x - v + woff;
    if (tid == 1023) g_bsums[blockIdx.x] = warpsums[31];
}

__global__ void scan2_kernel(int nblk) {
    __shared__ int warpsums[4];
    int tid = threadIdx.x, lane = tid & 31, wid = tid >> 5;
    int v = (tid < nblk) ? g_bsums[tid] : 0;
    int x = v;
    #pragma unroll
    for (int off = 1; off < 32; off <<= 1) {
        int y = __shfl_up_sync(0xFFFFFFFFu, x, off);
        if (lane >= off) x += y;
    }
    if (lane == 31) warpsums[wid] = x;
    __syncthreads();
    if (wid == 0 && lane < 4) {
        int wv = warpsums[lane];
        #pragma unroll
        for (int off = 1; off < 4; off <<= 1) {
            int y = __shfl_up_sync(0xFu, wv, off);
            if (lane >= off) wv += y;
        }
        warpsums[lane] = wv;
    }
    __syncthreads();
    int woff = (wid == 0) ? 0 : warpsums[wid - 1];
    int excl = x - v + woff;
    if (tid < nblk) g_boffs[tid] = excl;
    if (tid == nblk - 1) g_offs[N_NODES] = excl + v;
}

__global__ void scan3_kernel() {
    int i = blockIdx.x * blockDim.x + threadIdx.x;
    if (i >= N_NODES) return;
    int o = g_offs[i] + g_boffs[i >> 10];
    g_offs[i] = o;
    int d0 = g_deg4[i];
    int d1 = g_deg4[N_NODES + i];
    int d2 = g_deg4[2 * N_NODES + i];
    g_cur4[i] = o;
    g_cur4[N_NODES + i] = o + d0;
    g_cur4[2 * N_NODES + i] = o + d0 + d1;
    g_cur4[3 * N_NODES + i] = o + d0 + d1 + d2;
}

__global__ void scatter_kernel(const void* __restrict__ ei) {
    int stride = gridDim.x * blockDim.x;
    for (int e = blockIdx.x * blockDim.x + threadIdx.x; e < N_EDGES; e += stride) {
        int s = edge_val(ei, e);
        int d = edge_val(ei, (long long)N_EDGES + e);
        int p = atomicAdd(&g_cur4[(e & 3) * N_NODES + d], 1);
        g_ssrc[p] = s;
    }
}

// x (N, 30, 8) -> g_xT16[t][n][20] bf16, node-major, coalesced out.
__global__ void __launch_bounds__(256) transpose_x(const float* __restrict__ x) {
    __shared__ float sm[32 * 161];
    __shared__ __nv_bfloat16 so[8 * 32 * 20];   // [t][nl][j]
    int n0 = blockIdx.x * 32;
    #pragma unroll
    for (int w = 0; w < 20; w++) {
        int i = threadIdx.x + w * 256;
        int nl = i / 160, off = i - nl * 160;
        sm[nl * 161 + off] = x[(size_t)(n0 + nl) * 240 + 80 + off];
    }
    __syncthreads();
    #pragma unroll
    for (int w = 0; w < 20; w++) {
        int idx = threadIdx.x + w * 256;
        int nl = idx & 31;
        int p = idx >> 5;
        int t = p / 20, j = p - t * 20;
        so[(t * 32 + nl) * 20 + j] = __float2bfloat16_rn(sm[nl * 161 + j * 8 + t]);
    }
    __syncthreads();
    const uint32_t* sou = reinterpret_cast<const uint32_t*>(so);
    uint32_t* dst = reinterpret_cast<uint32_t*>(g_xT16);
    #pragma unroll
    for (int w = 0; w < 10; w++) {
        int idx = threadIdx.x + w * 256;           // 0..2559
        int t = idx / 320;
        int rem = idx - t * 320;
        dst[((size_t)t * N_NODES + n0) * 10 + rem] = sou[idx];
    }
}

// Fold GNN projection into gate weights; interleaved row layout + K-order
// [agg(0..63) | h(64..127) | x(128..147) | pad(148..159)].
__global__ void prep_weights(const float* __restrict__ W_ih, const float* __restrict__ W_hh,
                             const float* __restrict__ b_ih, const float* __restrict__ b_hh,
                             const float* __restrict__ W_rel, const float* __restrict__ b_rel,
                             const float* __restrict__ W_root) {
    int rp = blockIdx.x;
    int block16 = rp >> 4, within = rp & 15;
    int vl, q;
    if (within < 8) { vl = within >> 1; q = within & 1; }
    else            { vl = (within - 8) >> 1; q = 2 + ((within - 8) & 1); }
    int u = block16 * 4 + vl;
    int r = q * 64 + u;
    __shared__ float wg[64];
    int tid = threadIdx.x;  // 64 threads
    wg[tid] = W_ih[r * 84 + 20 + tid];
    __syncthreads();
    int c = tid;
    float m1 = 0.f, m2 = 0.f;
    #pragma unroll 8
    for (int j = 0; j < 64; j++) {
        float w = wg[j];
        m1 += w * W_rel[j * 64 + c];
        m2 += w * W_root[j * 64 + c];
    }
    m2 += W_hh[r * 64 + c];
    g_Wb[rp * 160 + c] = __float2bfloat16_rn(m1);        // agg block
    g_Wb[rp * 160 + 64 + c] = __float2bfloat16_rn(m2);   // h block
    if (c < 20) g_Wb[rp * 160 + 128 + c] = __float2bfloat16_rn(W_ih[r * 84 + c]); // x
    if (c < 12) g_Wb[rp * 160 + 148 + c] = __float2bfloat16_rn(0.f);
    if (c == 0) {
        float s = b_ih[r] + b_hh[r];
        for (int j = 0; j < 64; j++) s += wg[j] * b_rel[j];
        g_bias[u * 4 + q] = s;
    }
}

// bf16 copies of head weights.
__global__ void prep_head(const float* __restrict__ W1, const float* __restrict__ W2,
                          const float* __restrict__ W_rel, const float* __restrict__ W_root) {
    int i = blockIdx.x * 256 + threadIdx.x;
    if (i < 8192) {
        g_W1b[i] = __float2bfloat16_rn(W1[i]);
    } else if (i < 16384) {
        g_W2b[i - 8192] = __float2bfloat16_rn(W2[i - 8192]);
    } else if (i < 24576) {
        int j = i - 16384;
        int o = j >> 7, k = j & 127;
        float v = (k < 64) ? W_rel[o * 64 + k] : W_root[o * 64 + k - 64];
        g_Whb[j] = __float2bfloat16_rn(v);
    }
}

// ---------------- aggregation: warp per dst node, 2 edges/iter ----------------
// ah record: [n][0:64)=agg, [64:128)=h. Half-warps process alternate edges;
// lane li<16 owns 8B (4 bf16) of the row. Combined via shfl at the end.
__global__ void agg_kernel(__nv_bfloat16* __restrict__ ah) {
    int gw = (blockIdx.x * blockDim.x + threadIdx.x) >> 5;
    int lane = threadIdx.x & 31;
    if (gw >= N_NODES) return;
    int beg = g_offs[gw], end = g_offs[gw + 1];
    const int half = lane >> 4;      // 0 or 1
    const int li = lane & 15;        // 8B segment index
    float4 acc = make_float4(0.f, 0.f, 0.f, 0.f);
    int e = beg + half;
    // 2x unrolled: 4 edges in flight per warp
    for (; e + 2 < end; e += 4) {
        int s0 = g_ssrc[e], s1 = g_ssrc[e + 2];
        uint2 v0 = *reinterpret_cast<const uint2*>(ah + (size_t)s0 * 128 + 64 + li * 4);
        uint2 v1 = *reinterpret_cast<const uint2*>(ah + (size_t)s1 * 128 + 64 + li * 4);
        float2 a0 = __bfloat1622float2(*reinterpret_cast<__nv_bfloat162*>(&v0.x));
        float2 b0 = __bfloat1622float2(*reinterpret_cast<__nv_bfloat162*>(&v0.y));
        float2 a1 = __bfloat1622float2(*reinterpret_cast<__nv_bfloat162*>(&v1.x));
        float2 b1 = __bfloat1622float2(*reinterpret_cast<__nv_bfloat162*>(&v1.y));
        acc.x += a0.x + a1.x;
        acc.y += a0.y + a1.y;
        acc.z += b0.x + b1.x;
        acc.w += b0.y + b1.y;
    }
    if (e < end) {
        int s = g_ssrc[e];
        uint2 v = *reinterpret_cast<const uint2*>(ah + (size_t)s * 128 + 64 + li * 4);
        float2 a = __bfloat1622float2(*reinterpret_cast<__nv_bfloat162*>(&v.x));
        float2 b = __bfloat1622float2(*reinterpret_cast<__nv_bfloat162*>(&v.y));
        acc.x += a.x; acc.y += a.y; acc.z += b.x; acc.w += b.y;
    }
    acc.x += __shfl_down_sync(0xFFFFFFFFu, acc.x, 16);
    acc.y += __shfl_down_sync(0xFFFFFFFFu, acc.y, 16);
    acc.z += __shfl_down_sync(0xFFFFFFFFu, acc.z, 16);
    acc.w += __shfl_down_sync(0xFFFFFFFFu, acc.w, 16);
    if (lane < 16) {
        uint2 o;
        *reinterpret_cast<__nv_bfloat162*>(&o.x) =
            __float22bfloat162_rn(make_float2(acc.x, acc.y));
        *reinterpret_cast<__nv_bfloat162*>(&o.y) =
            __float22bfloat162_rn(make_float2(acc.z, acc.w));
        *reinterpret_cast<uint2*>(ah + (size_t)gw * 128 + li * 4) = o;
    }
}

// ---------------- bf16 mma.sync gate GEMM + fused LSTM epilogue ----------------
#define GATE_SMEM 64512

__global__ void __launch_bounds__(256, 3)
gate_kernel(const __nv_bfloat16* __restrict__ xTt16,
            const __nv_bfloat16* __restrict__ ah_in,
            float* __restrict__ h_out, __nv_bfloat16* __restrict__ ah_out,
            int t0, int wf32) {
    extern __shared__ char smem[];
    const int tid = threadIdx.x;
    const int wid = tid >> 5;
    const int lane = tid & 31;
    const int n0 = blockIdx.x * 128;
    const int col0 = blockIdx.y * 64;
    const int ubase = col0 >> 2;
    const uint32_t sbase = smem_u32(smem);

    {
        const char* wsrc = reinterpret_cast<const char*>(g_Wb) + (size_t)col0 * 320;
        #pragma unroll
        for (int it = 0; it < 5; it++) {
            int idx = tid + it * 256;
            int r = idx / 20;
            int c = idx - r * 20;
            CP_ASYNC_16(sbase + 43008u + r * 336 + c * 16, wsrc + r * 320 + c * 16);
        }
    }
    {
        const char* asrc = reinterpret_cast<const char*>(ah_in);
        #pragma unroll
        for (int it = 0; it < 8; it++) {
            int idx = tid + it * 256;
            int nl = idx >> 4;
            int q = idx & 15;
            int n = n0 + nl;
            int ncl = (n < N_NODES) ? n : (N_NODES - 1);
            uint32_t ssz = (!t0 && n < N_NODES) ? 16u : 0u;
            CP_ASYNC_16S(sbase + nl * 336 + q * 16, asrc + (size_t)ncl * 256 + q * 16, ssz);
        }
    }
    {
        const char* xsrc = reinterpret_cast<const char*>(xTt16);
        #pragma unroll
        for (int it = 0; it < 3; it++) {
            int idx = tid + it * 256;
            if (idx < 640) {
                int nl = idx / 5;
                int p = idx - nl * 5;
                int n = n0 + nl;
                int ncl = (n < N_NODES) ? n : (N_NODES - 1);
                uint32_t ssz = (n < N_NODES) ? 8u : 0u;
                CP_ASYNC_8S(sbase + nl * 336 + 256 + p * 8, xsrc + (size_t)ncl * 40 + p * 8, ssz);
            }
        }
    }
    #pragma unroll
    for (int it = 0; it < 3; it++) {
        int idx = tid + it * 256;
        if (idx < 640) {
            int nl = idx / 5;
            int p = idx - nl * 5;
            *reinterpret_cast<uint2*>(smem + nl * 336 + 296 + p * 8) = make_uint2(0u, 0u);
        }
    }
    CP_ASYNC_COMMIT();
    CP_ASYNC_WAIT0();
    __syncthreads();

    const int mw = wid >> 1;
    const int nw = wid & 1;
    const int mr = mw * 32;
    const int ncw = nw * 32;
    uint32_t aAddr = sbase + (mr + (lane & 15)) * 336 + ((lane >> 4) << 4);
    uint32_t bAddr = sbase + 43008u + (ncw + (lane & 15)) * 336 + ((lane >> 4) << 4);

    float acc[2][4][4];
    #pragma unroll
    for (int mi = 0; mi < 2; mi++)
        #pragma unroll
        for (int nj = 0; nj < 4; nj++)
            #pragma unroll
            for (int e = 0; e < 4; e++) acc[mi][nj][e] = 0.f;

    #pragma unroll
    for (int ks = 0; ks < 10; ks++) {
        uint32_t a[2][4];
        ldsm_x4(a[0], aAddr + ks * 32);
        ldsm_x4(a[1], aAddr + 16 * 336 + ks * 32);
        uint32_t b[2][4];
        ldsm_x4(b[0], bAddr + ks * 32);
        ldsm_x4(b[1], bAddr + 16 * 336 + ks * 32);
        #pragma unroll
        for (int mi = 0; mi < 2; mi++)
            #pragma unroll
            for (int nj2 = 0; nj2 < 4; nj2++) {
                int nj = nj2 >> 1, hi = nj2 & 1;
                mma_bf16(acc[mi][nj2], a[mi], b[nj][hi], b[nj][hi + 2]);
            }
    }

    float* cptr = g_cperm + (((size_t)(blockIdx.x * 4 + blockIdx.y)) * 256 + tid) * 8;
    float creg[8];
    if (!t0) {
        float4 ca = *reinterpret_cast<const float4*>(cptr);
        float4 cb = *reinterpret_cast<const float4*>(cptr + 4);
        creg[0] = ca.x; creg[1] = ca.y; creg[2] = ca.z; creg[3] = ca.w;
        creg[4] = cb.x; creg[5] = cb.y; creg[6] = cb.z; creg[7] = cb.w;
    } else {
        #pragma unroll
        for (int i = 0; i < 8; i++) creg[i] = 0.f;
    }
    const int vl = lane & 3;
    const float4* bias4 = reinterpret_cast<const float4*>(g_bias) + ubase;
    float4 bq[2];
    bq[0] = bias4[(wid & 1) * 8 + vl];
    bq[1] = bias4[(wid & 1) * 8 + 4 + vl];

    __syncthreads();

    float* Hs = reinterpret_cast<float*>(smem);

    #pragma unroll
    for (int mi = 0; mi < 2; mi++) {
        int r = mr + mi * 16 + (lane >> 2);
        #pragma unroll
        for (int b = 0; b < 2; b++) {
            int u = nw * 8 + b * 4 + vl;
            float4 q = bq[b];
            int ci = mi * 4 + b * 2;
            {
                float ig = acc[mi][2 * b][0] + q.x;
                float fg = acc[mi][2 * b][1] + q.y;
                float gg = acc[mi][2 * b + 1][0] + q.z;
                float og = acc[mi][2 * b + 1][1] + q.w;
                float si = fast_sigmoid(ig), sf = fast_sigmoid(fg);
                float so = fast_sigmoid(og), tg = fast_tanh(gg);
                float cn = sf * creg[ci] + si * tg;
                creg[ci] = cn;
                Hs[r * 18 + u] = so * fast_tanh(cn);
            }
            {
                float ig = acc[mi][2 * b][2] + q.x;
                float fg = acc[mi][2 * b][3] + q.y;
                float gg = acc[mi][2 * b + 1][2] + q.z;
                float og = acc[mi][2 * b + 1][3] + q.w;
                float si = fast_sigmoid(ig), sf = fast_sigmoid(fg);
                float so = fast_sigmoid(og), tg = fast_tanh(gg);
                float cn = sf * creg[ci + 1] + si * tg;
                creg[ci + 1] = cn;
                Hs[(r + 8) * 18 + u] = so * fast_tanh(cn);
            }
        }
    }
    *reinterpret_cast<float4*>(cptr) = make_float4(creg[0], creg[1], creg[2], creg[3]);
    *reinterpret_cast<float4*>(cptr + 4) = make_float4(creg[4], creg[5], creg[6], creg[7]);
    __syncthreads();

    #pragma unroll
    for (int it = 0; it < 4; it++) {
        int idx = tid + it * 256;
        int rr = idx >> 3;
        int up = idx & 7;
        int n = n0 + rr;
        if (n < N_NODES) {
            float2 hv = *reinterpret_cast<const float2*>(&Hs[rr * 18 + up * 2]);
            *reinterpret_cast<__nv_bfloat162*>(
                ah_out + (size_t)n * 128 + 64 + ubase + up * 2) = __float22bfloat162_rn(hv);
            if (wf32)
                *reinterpret_cast<float2*>(h_out + (size_t)n * 64 + ubase + up * 2) = hv;
        }
    }
}

// ---------------- head1: gnn = [agg|h] @ [W_rel|W_root]^T + b_rel (mma) ------
// Also accumulates gnn column stats into g_stats[64:128) and [192:256).
#define H1_SMEM 52480

__global__ void __launch_bounds__(256)
head1_kernel(const __nv_bfloat16* __restrict__ ah, const float* __restrict__ b_rel) {
    extern __shared__ char smem[];
    const int tid = threadIdx.x;
    const int wid = tid >> 5;
    const int lane = tid & 31;
    const int n0 = blockIdx.x * 128;
    float* sb = reinterpret_cast<float*>(smem + 52224);

    {
        const uint4* Wh4 = reinterpret_cast<const uint4*>(g_Whb);
        #pragma unroll
        for (int it = 0; it < 4; it++) {
            int idx = tid + it * 256;
            int r = idx >> 4, c16 = idx & 15;
            *reinterpret_cast<uint4*>(smem + 34816 + r * 272 + c16 * 16) = Wh4[idx];
        }
    }
    #pragma unroll
    for (int it = 0; it < 8; it++) {
        int idx = tid + it * 256;
        int nl = idx >> 4, q = idx & 15;
        int n = n0 + nl;
        uint4 v = make_uint4(0u, 0u, 0u, 0u);
        if (n < N_NODES)
            v = reinterpret_cast<const uint4*>(ah + (size_t)n * 128)[q];
        *reinterpret_cast<uint4*>(smem + nl * 272 + q * 16) = v;
    }
    if (tid < 128)
        *reinterpret_cast<uint4*>(smem + tid * 272 + 256) = make_uint4(0u, 0u, 0u, 0u);
    if (tid < 64) sb[tid] = b_rel[tid];
    __syncthreads();

    const int mw = wid >> 1;
    const int nw = wid & 1;
    const int mr = mw * 32;
    const int nc = nw * 32;
    const uint32_t sbase = smem_u32(smem);
    uint32_t aAddr = sbase + (mr + (lane & 15)) * 272 + ((lane >> 4) << 4);
    uint32_t bAddr = sbase + 34816u + (nc + (lane & 15)) * 272 + ((lane >> 4) << 4);

    float acc[2][4][4];
    #pragma unroll
    for (int mi = 0; mi < 2; mi++)
        #pragma unroll
        for (int nj = 0; nj < 4; nj++)
            #pragma unroll
            for (int e = 0; e < 4; e++) acc[mi][nj][e] = 0.f;

    #pragma unroll
    for (int ks = 0; ks < 8; ks++) {
        uint32_t a[2][4];
        ldsm_x4(a[0], aAddr + ks * 32);
        ldsm_x4(a[1], aAddr + 16 * 272 + ks * 32);
        uint32_t b[2][4];
        ldsm_x4(b[0], bAddr + ks * 32);
        ldsm_x4(b[1], bAddr + 16 * 272 + ks * 32);
        #pragma unroll
        for (int mi = 0; mi < 2; mi++)
            #pragma unroll
            for (int nj2 = 0; nj2 < 4; nj2++) {
                int nj = nj2 >> 1, hi = nj2 & 1;
                mma_bf16(acc[mi][nj2], a[mi], b[nj][hi], b[nj][hi + 2]);
            }
    }
    __syncthreads();

    float* Gs = reinterpret_cast<float*>(smem);   // [128][68]
    #pragma unroll
    for (int mi = 0; mi < 2; mi++) {
        int row = mr + mi * 16 + (lane >> 2);
        #pragma unroll
        for (int nj2 = 0; nj2 < 4; nj2++) {
            int c = nc + nj2 * 8 + (lane & 3) * 2;
            *reinterpret_cast<float2*>(&Gs[row * 68 + c]) =
                make_float2(acc[mi][nj2][0] + sb[c], acc[mi][nj2][1] + sb[c + 1]);
            *reinterpret_cast<float2*>(&Gs[(row + 8) * 68 + c]) =
                make_float2(acc[mi][nj2][2] + sb[c], acc[mi][nj2][3] + sb[c + 1]);
        }
    }
    __syncthreads();

    // writeback + per-thread stats over owned column
    int ucol = tid & 63;           // column 0..63
    int rbase = tid >> 6;          // 0..3
    float ssum = 0.f, sq = 0.f;
    #pragma unroll
    for (int k = 0; k < 32; k++) {
        int rr = rbase + k * 4;
        int n = n0 + rr;
        float v = Gs[rr * 68 + ucol];
        if (n < N_NODES) {
            g_gnn[(size_t)n * 64 + ucol] = v;
            ssum += v;
            sq += v * v;
        }
    }
    // block reduce 4 threads per column via smem beyond Gs (offset 34816 region reuse)
    float* red = reinterpret_cast<float*>(smem + 34816);   // [2][4][64]
    red[(rbase) * 64 + ucol] = ssum;
    red[256 + (rbase) * 64 + ucol] = sq;
    __syncthreads();
    if (tid < 64) {
        float s = red[tid] + red[64 + tid] + red[128 + tid] + red[192 + tid];
        float q = red[256 + tid] + red[320 + tid] + red[384 + tid] + red[448 + tid];
        atomicAdd(&g_stats[64 + tid], s);
        atomicAdd(&g_stats[192 + tid], q);
    }
}

// ---------------- stats over h only (g_stats [0:64) and [128:192)) ----------
__global__ void stats_h_kernel(const float* __restrict__ h) {
    int c = threadIdx.x & 63;
    int grp = threadIdx.x >> 6;      // 0..3
    int r0 = blockIdx.x * 256;
    int rend = min(r0 + 256, N_NODES);
    float s = 0.f, q = 0.f;
    for (int r = r0 + grp; r < rend; r += 4) {
        float v = h[(size_t)r * 64 + c];
        s += v;
        q += v * v;
    }
    atomicAdd(&g_stats[c], s);
    atomicAdd(&g_stats[128 + c], q);
}

__global__ void finalize_stats(const float* __restrict__ gamma, const float* __restrict__ beta) {
    int c = threadIdx.x;   // 0..127
    int slot = (c < 64) ? c : (64 + (c - 64));           // h block then gnn block
    float mean = g_stats[slot] / (float)N_NODES;
    float var = g_stats[128 + slot] / (float)N_NODES - mean * mean;
    float rstd = rsqrtf(var + 1e-5f);
    float sc = rstd * gamma[c];
    g_scale[c] = sc;
    g_shift[c] = beta[c] - mean * sc;
}

// ---------------- head2: fused layernorm + MLP + out-projection (mma) --------
#define H2_SMEM 90880

__global__ void __launch_bounds__(256)
head2_kernel(const float* __restrict__ hfin, const float* __restrict__ b1,
             const float* __restrict__ b2, const float* __restrict__ Wout,
             const float* __restrict__ bout, float* __restrict__ out) {
    extern __shared__ char smem[];
    const int tid = threadIdx.x;
    const int wid = tid >> 5;
    const int lane = tid & 31;
    const int n0 = blockIdx.x * 128;
    float* sb1 = reinterpret_cast<float*>(smem + 89088);
    float* sb2 = reinterpret_cast<float*>(smem + 89344);
    float* sWout = reinterpret_cast<float*>(smem + 89856);
    float* sdot = reinterpret_cast<float*>(smem + 90368);

    #pragma unroll
    for (int it = 0; it < 32; it++) {
        int idx = tid + it * 256;
        int nl = idx >> 6, cp = idx & 63;
        int c = cp * 2;
        int n = n0 + nl;
        float2 v = make_float2(0.f, 0.f);
        if (n < N_NODES) {
            v = (cp < 32)
                ? reinterpret_cast<const float2*>(hfin)[(size_t)n * 32 + cp]
                : reinterpret_cast<const float2*>(g_gnn)[(size_t)n * 32 + cp - 32];
        }
        float2 nv = make_float2(v.x * g_scale[c] + g_shift[c],
                                v.y * g_scale[c + 1] + g_shift[c + 1]);
        *reinterpret_cast<__nv_bfloat162*>(smem + nl * 272 + c * 2) =
            __float22bfloat162_rn(nv);
    }
    if (tid < 128)
        *reinterpret_cast<uint4*>(smem + tid * 272 + 256) = make_uint4(0u, 0u, 0u, 0u);
    {
        const uint4* W14 = reinterpret_cast<const uint4*>(g_W1b);
        #pragma unroll
        for (int it = 0; it < 4; it++) {
            int idx = tid + it * 256;
            int r = idx >> 4, c16 = idx & 15;
            *reinterpret_cast<uint4*>(smem + 34816 + r * 272 + c16 * 16) = W14[idx];
        }
        const uint4* W24 = reinterpret_cast<const uint4*>(g_W2b);
        #pragma unroll
        for (int it = 0; it < 4; it++) {
            int idx = tid + it * 256;
            int r = idx >> 3, c8 = idx & 7;
            *reinterpret_cast<uint4*>(smem + 70656 + r * 144 + c8 * 16) = W24[idx];
        }
    }
    if (tid < 64) sb1[tid] = b1[tid];
    if (tid < 128) {
        sb2[tid] = b2[tid];
        sWout[tid] = Wout[tid];
        sdot[tid] = 0.f;
    }
    __syncthreads();

    const int mw = wid >> 1;
    const int nw = wid & 1;
    const int mr = mw * 32;
    const uint32_t sbase = smem_u32(smem);

    {
        const int nc = nw * 32;
        uint32_t aAddr = sbase + (mr + (lane & 15)) * 272 + ((lane >> 4) << 4);
        uint32_t bAddr = sbase + 34816u + (nc + (lane & 15)) * 272 + ((lane >> 4) << 4);
        float acc1[2][4][4];
        #pragma unroll
        for (int mi = 0; mi < 2; mi++)
            #pragma unroll
            for (int nj = 0; nj < 4; nj++)
                #pragma unroll
                for (int e = 0; e < 4; e++) acc1[mi][nj][e] = 0.f;
        #pragma unroll
        for (int ks = 0; ks < 8; ks++) {
            uint32_t a[2][4];
            ldsm_x4(a[0], aAddr + ks * 32);
            ldsm_x4(a[1], aAddr + 16 * 272 + ks * 32);
            uint32_t b[2][4];
            ldsm_x4(b[0], bAddr + ks * 32);
            ldsm_x4(b[1], bAddr + 16 * 272 + ks * 32);
            #pragma unroll
            for (int mi = 0; mi < 2; mi++)
                #pragma unroll
                for (int nj2 = 0; nj2 < 4; nj2++) {
                    int nj = nj2 >> 1, hi = nj2 & 1;
                    mma_bf16(acc1[mi][nj2], a[mi], b[nj][hi], b[nj][hi + 2]);
                }
        }
        #pragma unroll
        for (int mi = 0; mi < 2; mi++) {
            int row = mr + mi * 16 + (lane >> 2);
            #pragma unroll
            for (int nj2 = 0; nj2 < 4; nj2++) {
                int c = nc + nj2 * 8 + (lane & 3) * 2;
                float v0 = fmaxf(acc1[mi][nj2][0] + sb1[c], 0.f);
                float v1 = fmaxf(acc1[mi][nj2][1] + sb1[c + 1], 0.f);
                float v2 = fmaxf(acc1[mi][nj2][2] + sb1[c], 0.f);
                float v3 = fmaxf(acc1[mi][nj2][3] + sb1[c + 1], 0.f);
                *reinterpret_cast<__nv_bfloat162*>(smem + 52224 + row * 144 + c * 2) =
                    __float22bfloat162_rn(make_float2(v0, v1));
                *reinterpret_cast<__nv_bfloat162*>(smem + 52224 + (row + 8) * 144 + c * 2) =
                    __float22bfloat162_rn(make_float2(v2, v3));
            }
        }
    }
    __syncthreads();

    {
        const int nc = nw * 64;
        uint32_t aAddr = sbase + 52224u + (mr + (lane & 15)) * 144 + ((lane >> 4) << 4);
        uint32_t bAddr = sbase + 70656u + (nc + (lane & 15)) * 144 + ((lane >> 4) << 4);
        float acc2[2][8][4];
        #pragma unroll
        for (int mi = 0; mi < 2; mi++)
            #pragma unroll
            for (int nj = 0; nj < 8; nj++)
                #pragma unroll
                for (int e = 0; e < 4; e++) acc2[mi][nj][e] = 0.f;
        #pragma unroll
        for (int ks = 0; ks < 4; ks++) {
            uint32_t a[2][4];
            ldsm_x4(a[0], aAddr + ks * 32);
            ldsm_x4(a[1], aAddr + 16 * 144 + ks * 32);
            uint32_t b[4][4];
            #pragma unroll
            for (int nj = 0; nj < 4; nj++)
                ldsm_x4(b[nj], bAddr + nj * 16 * 144 + ks * 32);
            #pragma unroll
            for (int mi = 0; mi < 2; mi++)
                #pragma unroll
                for (int nj2 = 0; nj2 < 8; nj2++) {
                    int nj = nj2 >> 1, hi = nj2 & 1;
                    mma_bf16(acc2[mi][nj2], a[mi], b[nj][hi], b[nj][hi + 2]);
                }
        }
        #pragma unroll
        for (int mi = 0; mi < 2; mi++) {
            float p0 = 0.f, p1 = 0.f;
            #pragma unroll
            for (int nj2 = 0; nj2 < 8; nj2++) {
                int c = nc + nj2 * 8 + (lane & 3) * 2;
                float w0 = sWout[c], w1 = sWout[c + 1];
                p0 += fmaxf(acc2[mi][nj2][0] + sb2[c], 0.f) * w0
                    + fmaxf(acc2[mi][nj2][1] + sb2[c + 1], 0.f) * w1;
                p1 += fmaxf(acc2[mi][nj2][2] + sb2[c], 0.f) * w0
                    + fmaxf(acc2[mi][nj2][3] + sb2[c + 1], 0.f) * w1;
            }
            p0 += __shfl_xor_sync(0xFFFFFFFFu, p0, 1);
            p0 += __shfl_xor_sync(0xFFFFFFFFu, p0, 2);
            p1 += __shfl_xor_sync(0xFFFFFFFFu, p1, 1);
            p1 += __shfl_xor_sync(0xFFFFFFFFu, p1, 2);
            if ((lane & 3) == 0) {
                int row = mr + mi * 16 + (lane >> 2);
                atomicAdd(&sdot[row], p0);
                atomicAdd(&sdot[row + 8], p1);
            }
        }
    }
    __syncthreads();

    if (tid < 128) {
        int n = n0 + tid;
        if (n < N_NODES) {
            float s = sdot[tid] + bout[0];
            out[n] = 1.f / (1.f + __expf(-s));
        }
    }
}

// ---------------- launch (CSR fork + stats_h overlap with head1) -------------
extern "C" void kernel_launch(void* const* d_in, const int* in_sizes, int n_in,
                              void* d_out, int out_size) {
    const float* x      = (const float*)d_in[0];
    const void*  ei     = d_in[1];
    const float* W_ih   = (const float*)d_in[4];
    const float* W_hh   = (const float*)d_in[5];
    const float* b_ih   = (const float*)d_in[6];
    const float* b_hh   = (const float*)d_in[7];
    const float* W_rel  = (const float*)d_in[8];
    const float* b_rel  = (const float*)d_in[9];
    const float* W_root = (const float*)d_in[10];
    const float* gamma  = (const float*)d_in[11];
    const float* beta   = (const float*)d_in[12];
    const float* W1     = (const float*)d_in[13];
    const float* b1     = (const float*)d_in[14];
    const float* W2     = (const float*)d_in[15];
    const float* b2     = (const float*)d_in[16];
    const float* W_out  = (const float*)d_in[17];
    const float* b_out  = (const float*)d_in[18];

    float *hbuf, *gnn;
    __nv_bfloat16 *ah, *xT16;
    cudaGetSymbolAddress((void**)&hbuf, g_hbuf);
    cudaGetSymbolAddress((void**)&ah, g_ah);
    cudaGetSymbolAddress((void**)&gnn, g_gnn);
    cudaGetSymbolAddress((void**)&xT16, g_xT16);

    static cudaStream_t s2 = nullptr;
    static cudaEvent_t evA = nullptr, evB = nullptr, evC = nullptr, evD = nullptr;
    if (!s2) {
        cudaStreamCreateWithFlags(&s2, cudaStreamNonBlocking);
        cudaEventCreateWithFlags(&evA, cudaEventDisableTiming);
        cudaEventCreateWithFlags(&evB, cudaEventDisableTiming);
        cudaEventCreateWithFlags(&evC, cudaEventDisableTiming);
        cudaEventCreateWithFlags(&evD, cudaEventDisableTiming);
        cudaFuncSetAttribute(gate_kernel, cudaFuncAttributeMaxDynamicSharedMemorySize, GATE_SMEM);
        cudaFuncSetAttribute(head1_kernel, cudaFuncAttributeMaxDynamicSharedMemorySize, H1_SMEM);
        cudaFuncSetAttribute(head2_kernel, cudaFuncAttributeMaxDynamicSharedMemorySize, H2_SMEM);
    }

    const int scan_blocks = (N_NODES + 1023) / 1024;   // 98
    dim3 ggrid(N_TILES, 4);

    cudaEventRecord(evA, 0);   // fork point

    // ---- main stream: weights + x + gate t=0 (gate stays launch #4) ----
    zero_stats<<<1, 256>>>();
    prep_weights<<<256, 64>>>(W_ih, W_hh, b_ih, b_hh, W_rel, b_rel, W_root);
    transpose_x<<<N_NODES / 32, 256>>>(x);
    gate_kernel<<<ggrid, 256, GATE_SMEM>>>(xT16, ah, hbuf, ah + (size_t)N_NODES * 128, 1, 0);

    // ---- S2: CSR build chain, concurrent with the above (disjoint buffers) ----
    cudaStreamWaitEvent(s2, evA, 0);
    zero_deg<<<256, 256, 0, s2>>>();
    detect_kernel<<<1, 256, 0, s2>>>((const unsigned int*)ei);
    prep_head<<<96, 256, 0, s2>>>(W1, W2, W_rel, W_root);
    hist2_kernel<<<512, 256, 0, s2>>>(ei);
    scan1_kernel<<<scan_blocks, 1024, 0, s2>>>();
    scan2_kernel<<<1, 128, 0, s2>>>(scan_blocks);
    scan3_kernel<<<(N_NODES + 255) / 256, 256, 0, s2>>>();
    scatter_kernel<<<512, 256, 0, s2>>>(ei);
    cudaEventRecord(evB, s2);

    // ---- main: join CSR, then the recurrent loop ----
    cudaStreamWaitEvent(0, evB, 0);
    for (int t = 1; t < T_STEPS; t++) {
        __nv_bfloat16* ah_in = ah + (size_t)(t & 1) * N_NODES * 128;
        __nv_bfloat16* ah_out = ah + (size_t)((t + 1) & 1) * N_NODES * 128;
        agg_kernel<<<(N_NODES * 32 + 255) / 256, 256>>>(ah_in);
        gate_kernel<<<ggrid, 256, GATE_SMEM>>>(
            xT16 + (size_t)t * N_NODES * 20, ah_in, hbuf, ah_out,
            0, t == T_STEPS - 1 ? 1 : 0);
    }

    // ---- fork: stats_h (reads hbuf only) concurrent with head1 (writes gnn) ----
    cudaEventRecord(evC, 0);
    cudaStreamWaitEvent(s2, evC, 0);
    stats_h_kernel<<<(N_NODES + 255) / 256, 256, 0, s2>>>(hbuf);
    cudaEventRecord(evD, s2);

    head1_kernel<<<N_TILES, 256, H1_SMEM>>>(ah + (size_t)N_NODES * 128, b_rel);
    cudaStreamWaitEvent(0, evD, 0);
    finalize_stats<<<1, 128>>>(gamma, beta);
    head2_kernel<<<N_TILES, 256, H2_SMEM>>>(hbuf, b1, b2, W_out, b_out, (float*)d_out);
}